// round 7
// baseline (speedup 1.0000x reference)
#include <cuda_runtime.h>
#include <math.h>
#include <stdint.h>

#define NTOK 8192
#define QS 288            // qkv row stride: 256 v | 8 qdot | 8 kdot | pad
#define ES 132            // edge smem row stride (floats)
#define HXS 1280          // hx row stride: 256 scalar ctx | 1024 ew

// ---------------- device scratch ----------------
__device__ float g_qkv[NTOK*QS];
__device__ float g_hx[NTOK*HXS];
__device__ float g_hmid[NTOK*256];
__device__ float g_gate[NTOK];
__device__ float g_proj[NTOK*3];
__device__ float g_center[16*3];
__device__ float g_V[16*9];
__device__ float g_Wcomb[256*QS];
__device__ float g_bcomb[QS];
__device__ float g_wg[8*132];       // [h][c]: lng[c]*weff[c][h], padded
__device__ float g_swg[8];          // sum_c wg[h][c]
__device__ float g_beff2[8];        // b_ve-fold + lnb-fold
__device__ float g_W1[HXS*256];     // folded fc1 weight: [1280, 256]
__device__ float g_b1[256];         // folded fc1 bias

__device__ __forceinline__ float siluf(float x){ return x/(1.f+__expf(-x)); }
__device__ __forceinline__ uint32_t f2tf32(float x){
    uint32_t u; asm("cvt.rna.tf32.f32 %0, %1;" : "=r"(u) : "f"(x)); return u;
}
__device__ __forceinline__ float tf32f(float x){ return __uint_as_float(f2tf32(x)); }

// ---------------- prep: fold effective weights ----------------
__global__ void prep_kernel(const float* __restrict__ W_qkv, const float* __restrict__ b_qkv,
                            const float* __restrict__ w_attn,
                            const float* __restrict__ W_qkv_e, const float* __restrict__ b_qkv_e,
                            const float* __restrict__ w_edge,
                            const float* __restrict__ W_fc1, const float* __restrict__ b_fc1,
                            const float* __restrict__ ln_e_g, const float* __restrict__ ln_e_b)
{
    int gid = blockIdx.x*blockDim.x + threadIdx.x;
    int gstride = gridDim.x*blockDim.x;
    for (int idx = gid; idx < 256*QS; idx += gstride) {
        int c = idx / QS, j = idx - c*QS;
        float w = 0.f;
        if (j < 256) {
            w = W_qkv[c*768 + 512 + j];
        } else if (j < 264) {
            int h = j - 256; float s = 0.f;
            #pragma unroll
            for (int d = 0; d < 32; d++) s += W_qkv[c*768 + h*32 + d]*w_attn[d];
            w = s;
        } else if (j < 272) {
            int h = j - 264; float s = 0.f;
            #pragma unroll
            for (int d = 0; d < 32; d++) s += W_qkv[c*768 + 256 + h*32 + d]*w_attn[d];
            w = s;
        }
        g_Wcomb[idx] = w;
    }
    // W1 [1280, 256]
    for (int idx = gid; idx < HXS*256; idx += gstride) {
        int j = idx >> 8, o = idx & 255;
        float w;
        if (j < 256) {
            w = W_fc1[j*256 + o];
        } else {
            int hc = j - 256, h = hc >> 7, c = hc & 127;
            float s = 0.f;
            #pragma unroll
            for (int jp = 0; jp < 16; jp++)
                s += W_qkv_e[c*256 + 128 + h*16 + jp]*W_fc1[(256 + h*16 + jp)*256 + o];
            w = s;
        }
        g_W1[idx] = w;
    }
    if (blockIdx.x == 0) {
        for (int j = threadIdx.x; j < QS; j += blockDim.x) {
            float bv = 0.f;
            if (j < 256) bv = b_qkv[512 + j];
            else if (j < 264) { int h = j-256; for (int d=0; d<32; d++) bv += b_qkv[h*32+d]*w_attn[d]; }
            else if (j < 272) { int h = j-264; for (int d=0; d<32; d++) bv += b_qkv[256 + h*32+d]*w_attn[d]; }
            g_bcomb[j] = bv;
        }
    }
    if (blockIdx.x == 1) {
        __shared__ float sweff[128*8];
        for (int idx = threadIdx.x; idx < 128*8; idx += blockDim.x) {
            int c = idx >> 3, h = idx & 7; float s = 0.f;
            #pragma unroll
            for (int e = 0; e < 16; e++) s += W_qkv_e[c*256 + h*16 + e]*w_edge[e];
            sweff[idx] = s;
            g_wg[h*132 + c] = ln_e_g[c]*s;
        }
        __syncthreads();
        if (threadIdx.x < 8) {
            int h = threadIdx.x;
            float sw = 0.f, b2 = 0.f;
            for (int c = 0; c < 128; c++) {
                float we = sweff[c*8 + h];
                sw += ln_e_g[c]*we;
                b2 += ln_e_b[c]*we;
            }
            for (int e = 0; e < 16; e++) b2 += b_qkv_e[h*16 + e]*w_edge[e];
            g_swg[h] = sw; g_beff2[h] = b2;
        }
    }
    if (blockIdx.x == 2 && threadIdx.x < 256) {
        int o = threadIdx.x;
        float s = b_fc1[o];
        for (int j = 0; j < 128; j++)
            s += b_qkv_e[128 + j]*W_fc1[(256 + j)*256 + o];
        g_b1[o] = s;
    }
}

// ---------------- per-graph geometry ----------------
__device__ void jacobi3(double a00,double a01,double a02,double a11,double a12,double a22,
                        double V[3][3])
{
    double A[3][3] = {{a00,a01,a02},{a01,a11,a12},{a02,a12,a22}};
    V[0][0]=1; V[0][1]=0; V[0][2]=0;
    V[1][0]=0; V[1][1]=1; V[1][2]=0;
    V[2][0]=0; V[2][1]=0; V[2][2]=1;
    for (int it = 0; it < 60; ++it) {
        int p = 0, q = 1; double mx = fabs(A[0][1]);
        if (fabs(A[0][2]) > mx) { mx = fabs(A[0][2]); p = 0; q = 2; }
        if (fabs(A[1][2]) > mx) { mx = fabs(A[1][2]); p = 1; q = 2; }
        if (mx <= 1e-13*(fabs(A[0][0])+fabs(A[1][1])+fabs(A[2][2]))) break;
        double apq = A[p][q];
        double theta = (A[q][q]-A[p][p])/(2.0*apq);
        double t = 1.0/(fabs(theta)+sqrt(theta*theta+1.0));
        if (theta < 0) t = -t;
        double c = 1.0/sqrt(t*t+1.0), s = t*c;
        for (int k = 0; k < 3; k++) { double akp=A[k][p], akq=A[k][q]; A[k][p]=c*akp-s*akq; A[k][q]=s*akp+c*akq; }
        for (int k = 0; k < 3; k++) { double apk=A[p][k], aqk=A[q][k]; A[p][k]=c*apk-s*aqk; A[q][k]=s*apk+c*aqk; }
        for (int k = 0; k < 3; k++) { double vkp=V[k][p], vkq=V[k][q]; V[k][p]=c*vkp-s*vkq; V[k][q]=s*vkp+c*vkq; }
    }
}

__global__ void geom_kernel(const float* __restrict__ geo)
{
    __shared__ double sred[8][9];
    __shared__ double sCd[3];
    __shared__ float sV[9], sC[3];
    int b = blockIdx.x, tid = threadIdx.x, lane = tid & 31, warp = tid >> 5;
    const float* G = geo + (size_t)b*512*3;

    {
        double s[3] = {0,0,0};
        for (int p = tid; p < 512; p += 256) { s[0] += G[p*3]; s[1] += G[p*3+1]; s[2] += G[p*3+2]; }
        #pragma unroll
        for (int k = 0; k < 3; k++)
            #pragma unroll
            for (int o = 16; o; o >>= 1) s[k] += __shfl_xor_sync(0xffffffffu, s[k], o);
        if (lane == 0) { sred[warp][0]=s[0]; sred[warp][1]=s[1]; sred[warp][2]=s[2]; }
    }
    __syncthreads();
    if (tid == 0) {
        for (int k = 0; k < 3; k++) {
            double t = 0; for (int w = 0; w < 8; w++) t += sred[w][k];
            sCd[k] = t/512.0;
        }
    }
    __syncthreads();
    double c0 = sCd[0], c1 = sCd[1], c2 = sCd[2];

    {
        double m[6] = {0,0,0,0,0,0};
        for (int p = tid; p < 512; p += 256) {
            double dx = G[p*3]-c0, dy = G[p*3+1]-c1, dz = G[p*3+2]-c2;
            m[0] += dx*dx; m[1] += dx*dy; m[2] += dx*dz;
            m[3] += dy*dy; m[4] += dy*dz; m[5] += dz*dz;
        }
        #pragma unroll
        for (int k = 0; k < 6; k++)
            #pragma unroll
            for (int o = 16; o; o >>= 1) m[k] += __shfl_xor_sync(0xffffffffu, m[k], o);
        if (lane == 0) for (int k = 0; k < 6; k++) sred[warp][k] = m[k];
    }
    __syncthreads();
    if (tid == 0) {
        double m[6];
        for (int k = 0; k < 6; k++) { double t=0; for (int w=0; w<8; w++) t += sred[w][k]; m[k]=t; }
        double V[3][3];
        jacobi3(m[0],m[1],m[2],m[3],m[4],m[5], V);
        for (int i = 0; i < 3; i++)
            for (int j = 0; j < 3; j++) { sV[i*3+j] = (float)V[i][j]; g_V[b*9+i*3+j] = (float)V[i][j]; }
        sC[0]=(float)c0; sC[1]=(float)c1; sC[2]=(float)c2;
        g_center[b*3+0]=(float)c0; g_center[b*3+1]=(float)c1; g_center[b*3+2]=(float)c2;
    }
    __syncthreads();

    for (int p = tid; p < 512; p += 256) {
        int t = b*512 + p;
        float dx = G[p*3]-sC[0], dy = G[p*3+1]-sC[1], dz = G[p*3+2]-sC[2];
        for (int d = 0; d < 3; d++)
            g_proj[t*3+d] = dx*sV[0*3+d] + dy*sV[1*3+d] + dz*sV[2*3+d];
    }
}

// ---------------- qkv GEMM: full-K A resident + LN + gate ----------------
__global__ __launch_bounds__(256)
void gemm_qkv(const float* __restrict__ A, const float* __restrict__ Bw,
              const float* __restrict__ bias, float* __restrict__ C,
              const float* __restrict__ Wg, const float* __restrict__ bg,
              const float* __restrict__ lng, const float* __restrict__ lnb)
{
    constexpr int K = 256, N = QS;
    constexpr int SA = 292, BS = 292;
    constexpr int WN = N/4, NT = WN/8, CT = N/32, KT = K/32;
    extern __shared__ float smem[];
    float* sA = smem;
    float* sB = smem + 32*SA;
    const int tid = threadIdx.x, lane = tid & 31, warp = tid >> 5;
    const int wr = warp >> 2, wc = warp & 3;
    const int gid = lane >> 2, tig = lane & 3;
    const int rowBase = blockIdx.x*32;

    for (int i = tid; i < 32*64; i += 256) {
        int r = i >> 6, c4 = i & 63;
        *(float4*)&sA[r*SA + c4*4] = *(const float4*)&A[(size_t)(rowBase + r)*K + c4*4];
    }
    __syncthreads();
    #pragma unroll
    for (int rr = 0; rr < 4; rr++) {
        int row = warp*4 + rr;
        float v[8]; float s = 0.f, s2 = 0.f, gd = 0.f;
        #pragma unroll
        for (int j = 0; j < 8; j++) {
            int c = lane + 32*j;
            float t = sA[row*SA + c];
            v[j] = t; s += t; s2 += t*t; gd += t*Wg[c];
        }
        #pragma unroll
        for (int o = 16; o; o >>= 1) {
            s  += __shfl_xor_sync(0xffffffffu, s,  o);
            s2 += __shfl_xor_sync(0xffffffffu, s2, o);
            gd += __shfl_xor_sync(0xffffffffu, gd, o);
        }
        float mean = s*(1.f/256.f);
        float rstd = rsqrtf(s2*(1.f/256.f) - mean*mean + 1e-5f);
        #pragma unroll
        for (int j = 0; j < 8; j++) {
            int c = lane + 32*j;
            sA[row*SA + c] = tf32f((v[j]-mean)*rstd*lng[c] + lnb[c]);
        }
        if (lane == 0) g_gate[rowBase + row] = 1.f/(1.f + __expf(-(gd + bg[0])));
    }

    float acc[NT][4];
    #pragma unroll
    for (int t = 0; t < NT; t++) {
        int j0 = wc*WN + t*8 + tig*2;
        acc[t][0] = bias[j0];   acc[t][1] = bias[j0+1];
        acc[t][2] = bias[j0];   acc[t][3] = bias[j0+1];
    }

    float4 rB[9];
    #pragma unroll
    for (int jj = 0; jj < 9; jj++) {
        int idx = tid + 256*jj;
        int r = idx/72, c4 = idx - r*72;
        rB[jj] = *(const float4*)&Bw[(size_t)r*N + c4*4];
    }
    for (int kt = 0; kt < KT; ++kt) {
        __syncthreads();
        #pragma unroll
        for (int jj = 0; jj < 9; jj++) {
            int idx = tid + 256*jj;
            int r = idx/72, c4 = idx - r*72;
            float* d = &sB[r*BS + c4*4];
            d[0] = tf32f(rB[jj].x); d[1] = tf32f(rB[jj].y);
            d[2] = tf32f(rB[jj].z); d[3] = tf32f(rB[jj].w);
        }
        __syncthreads();
        if (kt + 1 < KT) {
            #pragma unroll
            for (int jj = 0; jj < 9; jj++) {
                int idx = tid + 256*jj;
                int r = idx/72, c4 = idx - r*72;
                rB[jj] = *(const float4*)&Bw[(size_t)((kt+1)*32 + r)*N + c4*4];
            }
        }
        #pragma unroll
        for (int kk = 0; kk < 4; kk++) {
            int kc = kt*32 + kk*8;
            uint32_t a0 = __float_as_uint(sA[(wr*16 + gid    )*SA + kc + tig    ]);
            uint32_t a1 = __float_as_uint(sA[(wr*16 + gid + 8)*SA + kc + tig    ]);
            uint32_t a2 = __float_as_uint(sA[(wr*16 + gid    )*SA + kc + tig + 4]);
            uint32_t a3 = __float_as_uint(sA[(wr*16 + gid + 8)*SA + kc + tig + 4]);
            #pragma unroll
            for (int t = 0; t < NT; t++) {
                int n0 = wc*WN + t*8;
                uint32_t b0 = __float_as_uint(sB[(kk*8 + tig    )*BS + n0 + gid]);
                uint32_t b1 = __float_as_uint(sB[(kk*8 + tig + 4)*BS + n0 + gid]);
                asm volatile(
                    "mma.sync.aligned.m16n8k8.row.col.f32.tf32.tf32.f32 "
                    "{%0,%1,%2,%3}, {%4,%5,%6,%7}, {%8,%9}, {%0,%1,%2,%3};"
                    : "+f"(acc[t][0]), "+f"(acc[t][1]), "+f"(acc[t][2]), "+f"(acc[t][3])
                    : "r"(a0), "r"(a1), "r"(a2), "r"(a3), "r"(b0), "r"(b1));
            }
        }
    }

    __syncthreads();
    #pragma unroll
    for (int t = 0; t < NT; t++) {
        int n0 = wc*WN + t*8 + tig*2;
        int r0 = wr*16 + gid;
        sA[ r0     *SA + n0    ] = acc[t][0];
        sA[ r0     *SA + n0 + 1] = acc[t][1];
        sA[(r0 + 8)*SA + n0    ] = acc[t][2];
        sA[(r0 + 8)*SA + n0 + 1] = acc[t][3];
    }
    __syncthreads();
    #pragma unroll
    for (int rr = 0; rr < 4; rr++) {
        int row = warp*4 + rr;
        int grow = rowBase + row;
        #pragma unroll
        for (int j = 0; j < CT; j++) {
            int col = lane + 32*j;
            C[(size_t)grow*N + col] = sA[row*SA + col];
        }
    }
}

// ---------------- BM=64 K-tiled tf32 GEMM, 512 threads (16 warps = 4x4) ----------------
// EPI: 1 = gelu+LN, 2 = +residual. N=256.
template<int K, int EPI>
__global__ __launch_bounds__(512)
void gemm_kt64(const float* __restrict__ A, const float* __restrict__ Bw,
               const float* __restrict__ bias, float* __restrict__ C,
               const float* __restrict__ p1, const float* __restrict__ p2)
{
    constexpr int N = 256;
    constexpr int KT = K/32, SA = 36, BS = N + 4;
    constexpr int NT = 8, CT = N/32;    // warp: 16 rows x 64 cols
    extern __shared__ float smem[];
    float* sA = smem;                   // [64][36]
    float* sB = smem + 64*SA;           // [32][260]
    float* sC = smem;                   // staging [64][260]
    const int tid = threadIdx.x, lane = tid & 31, warp = tid >> 5;
    const int wr = warp >> 2, wc = warp & 3;
    const int gid = lane >> 2, tig = lane & 3;
    const int rowBase = blockIdx.x*64;

    float4 rA, rB[4];
    {
        int r = tid >> 3, c4 = tid & 7;
        rA = *(const float4*)&A[(size_t)(rowBase + r)*K + c4*4];
    }
    #pragma unroll
    for (int jj = 0; jj < 4; jj++) {
        int idx = tid + 512*jj;
        int r = idx >> 6, c4 = idx & 63;
        rB[jj] = *(const float4*)&Bw[(size_t)r*N + c4*4];
    }

    float acc[NT][4];
    #pragma unroll
    for (int t = 0; t < NT; t++) {
        int j0 = wc*64 + t*8 + tig*2;
        acc[t][0] = bias[j0];   acc[t][1] = bias[j0+1];
        acc[t][2] = bias[j0];   acc[t][3] = bias[j0+1];
    }

    for (int kt = 0; kt < KT; ++kt) {
        __syncthreads();
        {
            int r = tid >> 3, c4 = tid & 7;
            float* d = &sA[r*SA + c4*4];
            d[0] = tf32f(rA.x); d[1] = tf32f(rA.y); d[2] = tf32f(rA.z); d[3] = tf32f(rA.w);
            #pragma unroll
            for (int jj = 0; jj < 4; jj++) {
                int idx = tid + 512*jj;
                int rr = idx >> 6, cc4 = idx & 63;
                float* db = &sB[rr*BS + cc4*4];
                db[0] = tf32f(rB[jj].x); db[1] = tf32f(rB[jj].y);
                db[2] = tf32f(rB[jj].z); db[3] = tf32f(rB[jj].w);
            }
        }
        __syncthreads();
        if (kt + 1 < KT) {
            int r = tid >> 3, c4 = tid & 7;
            rA = *(const float4*)&A[(size_t)(rowBase + r)*K + (kt+1)*32 + c4*4];
            #pragma unroll
            for (int jj = 0; jj < 4; jj++) {
                int idx = tid + 512*jj;
                int rr = idx >> 6, cc4 = idx & 63;
                rB[jj] = *(const float4*)&Bw[(size_t)((kt+1)*32 + rr)*N + cc4*4];
            }
        }
        #pragma unroll
        for (int kk = 0; kk < 4; kk++) {
            uint32_t a0 = __float_as_uint(sA[(wr*16 + gid    )*SA + kk*8 + tig    ]);
            uint32_t a1 = __float_as_uint(sA[(wr*16 + gid + 8)*SA + kk*8 + tig    ]);
            uint32_t a2 = __float_as_uint(sA[(wr*16 + gid    )*SA + kk*8 + tig + 4]);
            uint32_t a3 = __float_as_uint(sA[(wr*16 + gid + 8)*SA + kk*8 + tig + 4]);
            #pragma unroll
            for (int t = 0; t < NT; t++) {
                int n0 = wc*64 + t*8;
                uint32_t b0 = __float_as_uint(sB[(kk*8 + tig    )*BS + n0 + gid]);
                uint32_t b1 = __float_as_uint(sB[(kk*8 + tig + 4)*BS + n0 + gid]);
                asm volatile(
                    "mma.sync.aligned.m16n8k8.row.col.f32.tf32.tf32.f32 "
                    "{%0,%1,%2,%3}, {%4,%5,%6,%7}, {%8,%9}, {%0,%1,%2,%3};"
                    : "+f"(acc[t][0]), "+f"(acc[t][1]), "+f"(acc[t][2]), "+f"(acc[t][3])
                    : "r"(a0), "r"(a1), "r"(a2), "r"(a3), "r"(b0), "r"(b1));
            }
        }
    }

    __syncthreads();
    #pragma unroll
    for (int t = 0; t < NT; t++) {
        int n0 = wc*64 + t*8 + tig*2;
        int r0 = wr*16 + gid;
        sC[ r0     *BS + n0    ] = acc[t][0];
        sC[ r0     *BS + n0 + 1] = acc[t][1];
        sC[(r0 + 8)*BS + n0    ] = acc[t][2];
        sC[(r0 + 8)*BS + n0 + 1] = acc[t][3];
    }
    __syncthreads();

    // 16 warps x 4 rows
    #pragma unroll
    for (int rr = 0; rr < 4; rr++) {
        int row = warp*4 + rr;
        int grow = rowBase + row;
        if (EPI == 1) {
            float v[CT]; float s = 0.f, s2 = 0.f;
            #pragma unroll
            for (int j = 0; j < CT; j++) {
                float x = sC[row*BS + lane + 32*j];
                x = 0.5f*x*(1.f + erff(x*0.70710678118654752f));
                v[j] = x; s += x; s2 += x*x;
            }
            #pragma unroll
            for (int o = 16; o; o >>= 1) {
                s  += __shfl_xor_sync(0xffffffffu, s,  o);
                s2 += __shfl_xor_sync(0xffffffffu, s2, o);
            }
            float mean = s*(1.f/256.f);
            float rstd = rsqrtf(s2*(1.f/256.f) - mean*mean + 1e-5f);
            #pragma unroll
            for (int j = 0; j < CT; j++) {
                int col = lane + 32*j;
                C[(size_t)grow*256 + col] = (v[j]-mean)*rstd*p1[col] + p2[col];
            }
        } else {
            #pragma unroll
            for (int j = 0; j < CT; j++) {
                int col = lane + 32*j;
                C[(size_t)grow*256 + col] = sC[row*BS + col] + p1[(size_t)grow*256 + col];
            }
        }
    }
}

// ---------------- fused per-token attention: raw edges + LN-fold ----------------
struct AttnGroup {
    float edge[32*ES];    // raw edge rows
    float logit[8*32];
    float attnT[32*8];    // [m][h]
    float arT[32*8];      // [m][h] attn*rstd
    float kd[32*8];
    float mean[32];
    float rstd[32];
    float s1[8];
    float qd[8];
    int   nbr[32];
    int   msk[32];
};
struct AttnSmem {
    float wg[8*132];      // [h][c]: lng*weff
    float swg[8];
    float beff2[8];
    float wfa[8];
    float lng[128];
    float lnb[128];
    AttnGroup grp[4];
};

#define GBAR(id) asm volatile("bar.sync %0, 128;" :: "r"(id) : "memory")

__global__ __launch_bounds__(512, 2)
void attn_kernel(const float* __restrict__ edge_feats,
                 const float* __restrict__ geo_feats,
                 const int*   __restrict__ nbr_idx,
                 const int*   __restrict__ masks,
                 const float* __restrict__ ln_e_g,
                 const float* __restrict__ ln_e_b,
                 const float* __restrict__ W_fa,
                 const float* __restrict__ b_fa,
                 float* __restrict__ out_geo)
{
    extern __shared__ char smraw[];
    AttnSmem& sm = *reinterpret_cast<AttnSmem*>(smraw);
    const int tid = threadIdx.x;

    for (int i = tid; i < 8*132; i += 512) sm.wg[i] = g_wg[i];
    if (tid < 128) { sm.lng[tid] = ln_e_g[tid]; sm.lnb[tid] = ln_e_b[tid]; }
    if (tid >= 128 && tid < 136) {
        int h = tid - 128;
        sm.swg[h] = g_swg[h]; sm.beff2[h] = g_beff2[h]; sm.wfa[h] = W_fa[h];
    }
    const float bfa = b_fa[0];
    __syncthreads();

    const int g     = tid >> 7;
    const int gtid  = tid & 127;
    const int glane = gtid & 31;
    const int gwarp = gtid >> 5;
    const int bid   = 1 + g;
    AttnGroup& G = sm.grp[g];

    for (int tok = 0; tok < 2; ++tok) {
        const int n = blockIdx.x*8 + g*2 + tok;

        // phase 1: loads (raw edges)
        {
            const float4* ep4 = (const float4*)(edge_feats + (size_t)n*4096);
            #pragma unroll
            for (int jj = 0; jj < 8; jj++) {
                int idx = gtid + 128*jj;
                int m = idx >> 5, c4 = idx & 31;
                *(float4*)&G.edge[m*ES + c4*4] = ep4[idx];
            }
            if (gtid < 32) { G.nbr[gtid] = nbr_idx[n*32 + gtid]; G.msk[gtid] = masks[n*32 + gtid]; }
            if (gtid >= 32 && gtid < 40) G.qd[gtid-32] = g_qkv[(size_t)n*QS + 256 + gtid-32];
        }
        GBAR(bid);

        // phase 2: kd gather + row stats (read-only)
        {
            #pragma unroll
            for (int jj = 0; jj < 2; jj++) {
                int item = gtid + 128*jj;
                int m = item >> 3, h = item & 7;
                G.kd[item] = g_qkv[(size_t)G.nbr[m]*QS + 264 + h];
            }
            #pragma unroll
            for (int i = 0; i < 8; i++) {
                int m = gwarp + 4*i;
                float v0 = G.edge[m*ES + glane];
                float v1 = G.edge[m*ES + glane + 32];
                float v2 = G.edge[m*ES + glane + 64];
                float v3 = G.edge[m*ES + glane + 96];
                float s  = v0+v1+v2+v3;
                float s2 = v0*v0+v1*v1+v2*v2+v3*v3;
                #pragma unroll
                for (int o = 16; o; o >>= 1) {
                    s  += __shfl_xor_sync(0xffffffffu, s,  o);
                    s2 += __shfl_xor_sync(0xffffffffu, s2, o);
                }
                float mean = s*(1.f/128.f);
                float rstd = rsqrtf(s2*(1.f/128.f) - mean*mean + 1e-5f);
                if (glane == 0) { G.mean[m] = mean; G.rstd[m] = rstd; }
            }
        }
        GBAR(bid);

        // phase 3: logits on raw edges (LN folded)
        {
            int m0 = gtid >> 3, h = gtid & 7;
            float base = G.qd[h] + sm.beff2[h];
            float d0 = 0.f, d1 = 0.f;
            const float4* e0 = (const float4*)&G.edge[m0*ES];
            const float4* e1 = (const float4*)&G.edge[(m0+16)*ES];
            const float4* wt = (const float4*)&sm.wg[h*132];
            #pragma unroll 8
            for (int c4 = 0; c4 < 32; c4++) {
                float4 w = wt[c4], x = e0[c4], y = e1[c4];
                d0 += x.x*w.x + x.y*w.y + x.z*w.z + x.w*w.w;
                d1 += y.x*w.x + y.y*w.y + y.z*w.z + y.w*w.w;
            }
            float sw = sm.swg[h];
            float a0 = base + G.kd[m0*8 + h]      + G.rstd[m0]   *(d0 - G.mean[m0]   *sw);
            float a1 = base + G.kd[(m0+16)*8 + h] + G.rstd[m0+16]*(d1 - G.mean[m0+16]*sw);
            if (!G.msk[m0])    a0 = -1e9f;
            if (!G.msk[m0+16]) a1 = -1e9f;
            G.logit[h*32 + m0]      = a0;
            G.logit[h*32 + m0 + 16] = a1;
        }
        GBAR(bid);

        // phase 4: softmax + transpose + ar/s1
        {
            #pragma unroll
            for (int i = 0; i < 2; i++) {
                int h = gwarp + 4*i;
                float l = G.logit[h*32 + glane];
                float mx = l;
                #pragma unroll
                for (int o = 16; o; o >>= 1) mx = fmaxf(mx, __shfl_xor_sync(0xffffffffu, mx, o));
                float e = __expf(l - mx);
                float ss = e;
                #pragma unroll
                for (int o = 16; o; o >>= 1) ss += __shfl_xor_sync(0xffffffffu, ss, o);
                float a = e/ss;
                float ar = a*G.rstd[glane];
                float s1p = ar*G.mean[glane];
                #pragma unroll
                for (int o = 16; o; o >>= 1) s1p += __shfl_xor_sync(0xffffffffu, s1p, o);
                G.attnT[glane*8 + h] = a;
                G.arT[glane*8 + h]   = ar;
                if (glane == 0) G.s1[h] = s1p;
            }
        }
        GBAR(bid);

        // phase 5: scalar ctx + ew + geo
        {
            float acc0 = 0.f, acc1 = 0.f;
            int c0 = gtid, c1 = gtid + 128;
            int h0 = c0 >> 5, h1 = c1 >> 5;
            #pragma unroll
            for (int m = 0; m < 32; m++) {
                const float* vrow = &g_qkv[(size_t)G.nbr[m]*QS];
                acc0 += G.attnT[m*8 + h0]*vrow[c0];
                acc1 += G.attnT[m*8 + h1]*vrow[c1];
            }
            g_hx[(size_t)n*HXS + c0] = acc0;
            g_hx[(size_t)n*HXS + c1] = acc1;

            float ewa[8];
            #pragma unroll
            for (int h = 0; h < 8; h++) ewa[h] = 0.f;
            const float4* ar4 = (const float4*)G.arT;
            #pragma unroll
            for (int m = 0; m < 32; m++) {
                float e = G.edge[m*ES + gtid];
                float4 r0 = ar4[m*2], r1 = ar4[m*2 + 1];
                ewa[0] += r0.x*e; ewa[1] += r0.y*e; ewa[2] += r0.z*e; ewa[3] += r0.w*e;
                ewa[4] += r1.x*e; ewa[5] += r1.y*e; ewa[6] += r1.z*e; ewa[7] += r1.w*e;
            }
            float gl = sm.lng[gtid], bl = sm.lnb[gtid];
            #pragma unroll
            for (int h = 0; h < 8; h++)
                g_hx[(size_t)n*HXS + 256 + h*128 + gtid] = gl*(ewa[h] - G.s1[h]) + bl;
        }
        if (gwarp == 3) {
            int m = glane;
            float aw = 0.f;
            #pragma unroll
            for (int h = 0; h < 8; h++) aw += G.attnT[m*8 + h]*sm.wfa[h];
            int nb = G.nbr[m];
            float p0 = aw*g_proj[nb*3 + 0];
            float p1 = aw*g_proj[nb*3 + 1];
            float p2 = aw*g_proj[nb*3 + 2];
            #pragma unroll
            for (int o = 16; o; o >>= 1) {
                p0 += __shfl_xor_sync(0xffffffffu, p0, o);
                p1 += __shfl_xor_sync(0xffffffffu, p1, o);
                p2 += __shfl_xor_sync(0xffffffffu, p2, o);
            }
            if (glane == 0) {
                int b = n >> 9;
                float ps[3] = {p0, p1, p2};
                float sd[3];
                #pragma unroll
                for (int j = 0; j < 3; j++)
                    sd[j] = 0.5f*(siluf(ps[j] + bfa) - siluf(-ps[j] + bfa));
                float gt = g_gate[n];
                #pragma unroll
                for (int i = 0; i < 3; i++) {
                    float gc = g_center[b*3 + i]
                             + sd[0]*g_V[b*9 + i*3 + 0]
                             + sd[1]*g_V[b*9 + i*3 + 1]
                             + sd[2]*g_V[b*9 + i*3 + 2];
                    out_geo[n*3 + i] = gc*gt + geo_feats[n*3 + i]*(1.f - gt);
                }
            }
        }
        GBAR(bid);
    }
}

// ---------------- launcher ----------------
extern "C" void kernel_launch(void* const* d_in, const int* in_sizes, int n_in,
                              void* d_out, int out_size)
{
    const float* token    = (const float*)d_in[0];
    const float* geo      = (const float*)d_in[1];
    const float* edge     = (const float*)d_in[2];
    const int*   nbr      = (const int*)d_in[3];
    const int*   mask     = (const int*)d_in[5];
    const float* ln_qkv_g = (const float*)d_in[6];
    const float* ln_qkv_b = (const float*)d_in[7];
    const float* W_qkv    = (const float*)d_in[8];
    const float* b_qkv    = (const float*)d_in[9];
    const float* ln_e_g   = (const float*)d_in[10];
    const float* ln_e_b   = (const float*)d_in[11];
    const float* W_qkv_e  = (const float*)d_in[12];
    const float* b_qkv_e  = (const float*)d_in[13];
    const float* w_attn   = (const float*)d_in[14];
    const float* w_edge   = (const float*)d_in[15];
    const float* W_gate   = (const float*)d_in[16];
    const float* b_gate   = (const float*)d_in[17];
    const float* W_fc1    = (const float*)d_in[18];
    const float* b_fc1    = (const float*)d_in[19];
    const float* ln_h_g   = (const float*)d_in[20];
    const float* ln_h_b   = (const float*)d_in[21];
    const float* W_fc2    = (const float*)d_in[22];
    const float* b_fc2    = (const float*)d_in[23];
    const float* W_fa     = (const float*)d_in[24];
    const float* b_fa     = (const float*)d_in[25];
    float* out = (float*)d_out;

    void* p;
    cudaGetSymbolAddress(&p, g_qkv);   float* p_qkv   = (float*)p;
    cudaGetSymbolAddress(&p, g_hx);    float* p_hx    = (float*)p;
    cudaGetSymbolAddress(&p, g_hmid);  float* p_hmid  = (float*)p;
    cudaGetSymbolAddress(&p, g_Wcomb); float* p_Wcomb = (float*)p;
    cudaGetSymbolAddress(&p, g_bcomb); float* p_bcomb = (float*)p;
    cudaGetSymbolAddress(&p, g_W1);    float* p_W1    = (float*)p;
    cudaGetSymbolAddress(&p, g_b1);    float* p_b1    = (float*)p;

    prep_kernel<<<64, 256>>>(W_qkv, b_qkv, w_attn, W_qkv_e, b_qkv_e, w_edge,
                             W_fc1, b_fc1, ln_e_g, ln_e_b);
    geom_kernel<<<16, 256>>>(geo);

    {
        constexpr int SM = (32*292 + 32*292)*sizeof(float);
        cudaFuncSetAttribute((const void*)gemm_qkv,
                             cudaFuncAttributeMaxDynamicSharedMemorySize, SM);
        gemm_qkv<<<256, 256, SM>>>(token, p_Wcomb, p_bcomb, p_qkv,
                                   W_gate, b_gate, ln_qkv_g, ln_qkv_b);
    }

    cudaFuncSetAttribute(attn_kernel, cudaFuncAttributeMaxDynamicSharedMemorySize,
                         (int)sizeof(AttnSmem));
    attn_kernel<<<1024, 512, sizeof(AttnSmem)>>>(
        edge, geo, nbr, mask, ln_e_g, ln_e_b, W_fa, b_fa,
        out + (size_t)NTOK*256);

    // fc1 (folded): hx[8192,1280] @ W1[1280,256] -> gelu -> LN -> hmid
    {
        constexpr int SM = 64*260*sizeof(float);
        cudaFuncSetAttribute((const void*)gemm_kt64<HXS, 1>,
                             cudaFuncAttributeMaxDynamicSharedMemorySize, SM);
        gemm_kt64<HXS, 1><<<128, 512, SM>>>(p_hx, p_W1, p_b1, p_hmid, ln_h_g, ln_h_b);
    }

    // fc2: hmid[8192,256] @ W_fc2[256,256] + token -> out
    {
        constexpr int SM = 64*260*sizeof(float);
        cudaFuncSetAttribute((const void*)gemm_kt64<256, 2>,
                             cudaFuncAttributeMaxDynamicSharedMemorySize, SM);
        gemm_kt64<256, 2><<<128, 512, SM>>>(p_hmid, W_fc2, b_fc2, out, token, nullptr);
    }
}

// round 8
// speedup vs baseline: 1.0411x; 1.0411x over previous
#include <cuda_runtime.h>
#include <math.h>
#include <stdint.h>

#define NTOK 8192
#define QS 288            // qkv row stride: 256 v | 8 qdot | 8 kdot | pad
#define ES 132            // edge smem row stride (floats)
#define HXS 1280          // hx row stride: 256 scalar ctx | 1024 ew

// ---------------- device scratch ----------------
__device__ float g_qkv[NTOK*QS];
__device__ float g_hx[NTOK*HXS];
__device__ float g_hmid[NTOK*256];
__device__ float g_gate[NTOK];
__device__ float g_proj[NTOK*3];
__device__ float g_center[16*3];
__device__ float g_V[16*9];
__device__ float g_Wcomb[256*QS];
__device__ float g_bcomb[QS];
__device__ float g_wg[8*132];       // [h][c]: lng[c]*weff[c][h], padded
__device__ float g_swg[8];          // sum_c wg[h][c]
__device__ float g_beff2[8];        // b_ve-fold + lnb-fold
__device__ float g_W1[HXS*256];     // folded fc1 weight: [1280, 256]
__device__ float g_b1[256];         // folded fc1 bias

__device__ __forceinline__ float siluf(float x){ return x/(1.f+__expf(-x)); }

#define CP_ASYNC16(dst, src) \
    asm volatile("cp.async.ca.shared.global [%0], [%1], 16;\n" :: "r"(dst), "l"(src))
#define CP_COMMIT() asm volatile("cp.async.commit_group;\n" ::: "memory")
#define CP_WAIT1()  asm volatile("cp.async.wait_group 1;\n" ::: "memory")

__device__ __forceinline__ uint32_t sptr(const void* p){
    return (uint32_t)__cvta_generic_to_shared(p);
}

// ---------------- prep: fold effective weights ----------------
__global__ void prep_kernel(const float* __restrict__ W_qkv, const float* __restrict__ b_qkv,
                            const float* __restrict__ w_attn,
                            const float* __restrict__ W_qkv_e, const float* __restrict__ b_qkv_e,
                            const float* __restrict__ w_edge,
                            const float* __restrict__ W_fc1, const float* __restrict__ b_fc1,
                            const float* __restrict__ ln_e_g, const float* __restrict__ ln_e_b)
{
    int gid = blockIdx.x*blockDim.x + threadIdx.x;
    int gstride = gridDim.x*blockDim.x;
    for (int idx = gid; idx < 256*QS; idx += gstride) {
        int c = idx / QS, j = idx - c*QS;
        float w = 0.f;
        if (j < 256) {
            w = W_qkv[c*768 + 512 + j];
        } else if (j < 264) {
            int h = j - 256; float s = 0.f;
            #pragma unroll
            for (int d = 0; d < 32; d++) s += W_qkv[c*768 + h*32 + d]*w_attn[d];
            w = s;
        } else if (j < 272) {
            int h = j - 264; float s = 0.f;
            #pragma unroll
            for (int d = 0; d < 32; d++) s += W_qkv[c*768 + 256 + h*32 + d]*w_attn[d];
            w = s;
        }
        g_Wcomb[idx] = w;
    }
    for (int idx = gid; idx < HXS*256; idx += gstride) {
        int j = idx >> 8, o = idx & 255;
        float w;
        if (j < 256) {
            w = W_fc1[j*256 + o];
        } else {
            int hc = j - 256, h = hc >> 7, c = hc & 127;
            float s = 0.f;
            #pragma unroll
            for (int jp = 0; jp < 16; jp++)
                s += W_qkv_e[c*256 + 128 + h*16 + jp]*W_fc1[(256 + h*16 + jp)*256 + o];
            w = s;
        }
        g_W1[idx] = w;
    }
    if (blockIdx.x == 0) {
        for (int j = threadIdx.x; j < QS; j += blockDim.x) {
            float bv = 0.f;
            if (j < 256) bv = b_qkv[512 + j];
            else if (j < 264) { int h = j-256; for (int d=0; d<32; d++) bv += b_qkv[h*32+d]*w_attn[d]; }
            else if (j < 272) { int h = j-264; for (int d=0; d<32; d++) bv += b_qkv[256 + h*32+d]*w_attn[d]; }
            g_bcomb[j] = bv;
        }
    }
    if (blockIdx.x == 1) {
        __shared__ float sweff[128*8];
        for (int idx = threadIdx.x; idx < 128*8; idx += blockDim.x) {
            int c = idx >> 3, h = idx & 7; float s = 0.f;
            #pragma unroll
            for (int e = 0; e < 16; e++) s += W_qkv_e[c*256 + h*16 + e]*w_edge[e];
            sweff[idx] = s;
            g_wg[h*132 + c] = ln_e_g[c]*s;
        }
        __syncthreads();
        if (threadIdx.x < 8) {
            int h = threadIdx.x;
            float sw = 0.f, b2 = 0.f;
            for (int c = 0; c < 128; c++) {
                float we = sweff[c*8 + h];
                sw += ln_e_g[c]*we;
                b2 += ln_e_b[c]*we;
            }
            for (int e = 0; e < 16; e++) b2 += b_qkv_e[h*16 + e]*w_edge[e];
            g_swg[h] = sw; g_beff2[h] = b2;
        }
    }
    if (blockIdx.x == 2 && threadIdx.x < 256) {
        int o = threadIdx.x;
        float s = b_fc1[o];
        for (int j = 0; j < 128; j++)
            s += b_qkv_e[128 + j]*W_fc1[(256 + j)*256 + o];
        g_b1[o] = s;
    }
}

// ---------------- per-graph geometry ----------------
__device__ void jacobi3(double a00,double a01,double a02,double a11,double a12,double a22,
                        double V[3][3])
{
    double A[3][3] = {{a00,a01,a02},{a01,a11,a12},{a02,a12,a22}};
    V[0][0]=1; V[0][1]=0; V[0][2]=0;
    V[1][0]=0; V[1][1]=1; V[1][2]=0;
    V[2][0]=0; V[2][1]=0; V[2][2]=1;
    for (int it = 0; it < 60; ++it) {
        int p = 0, q = 1; double mx = fabs(A[0][1]);
        if (fabs(A[0][2]) > mx) { mx = fabs(A[0][2]); p = 0; q = 2; }
        if (fabs(A[1][2]) > mx) { mx = fabs(A[1][2]); p = 1; q = 2; }
        if (mx <= 1e-13*(fabs(A[0][0])+fabs(A[1][1])+fabs(A[2][2]))) break;
        double apq = A[p][q];
        double theta = (A[q][q]-A[p][p])/(2.0*apq);
        double t = 1.0/(fabs(theta)+sqrt(theta*theta+1.0));
        if (theta < 0) t = -t;
        double c = 1.0/sqrt(t*t+1.0), s = t*c;
        for (int k = 0; k < 3; k++) { double akp=A[k][p], akq=A[k][q]; A[k][p]=c*akp-s*akq; A[k][q]=s*akp+c*akq; }
        for (int k = 0; k < 3; k++) { double apk=A[p][k], aqk=A[q][k]; A[p][k]=c*apk-s*aqk; A[q][k]=s*apk+c*aqk; }
        for (int k = 0; k < 3; k++) { double vkp=V[k][p], vkq=V[k][q]; V[k][p]=c*vkp-s*vkq; V[k][q]=s*vkp+c*vkq; }
    }
}

__global__ void geom_kernel(const float* __restrict__ geo)
{
    __shared__ double sred[8][9];
    __shared__ double sCd[3];
    __shared__ float sV[9], sC[3];
    int b = blockIdx.x, tid = threadIdx.x, lane = tid & 31, warp = tid >> 5;
    const float* G = geo + (size_t)b*512*3;

    {
        double s[3] = {0,0,0};
        for (int p = tid; p < 512; p += 256) { s[0] += G[p*3]; s[1] += G[p*3+1]; s[2] += G[p*3+2]; }
        #pragma unroll
        for (int k = 0; k < 3; k++)
            #pragma unroll
            for (int o = 16; o; o >>= 1) s[k] += __shfl_xor_sync(0xffffffffu, s[k], o);
        if (lane == 0) { sred[warp][0]=s[0]; sred[warp][1]=s[1]; sred[warp][2]=s[2]; }
    }
    __syncthreads();
    if (tid == 0) {
        for (int k = 0; k < 3; k++) {
            double t = 0; for (int w = 0; w < 8; w++) t += sred[w][k];
            sCd[k] = t/512.0;
        }
    }
    __syncthreads();
    double c0 = sCd[0], c1 = sCd[1], c2 = sCd[2];

    {
        double m[6] = {0,0,0,0,0,0};
        for (int p = tid; p < 512; p += 256) {
            double dx = G[p*3]-c0, dy = G[p*3+1]-c1, dz = G[p*3+2]-c2;
            m[0] += dx*dx; m[1] += dx*dy; m[2] += dx*dz;
            m[3] += dy*dy; m[4] += dy*dz; m[5] += dz*dz;
        }
        #pragma unroll
        for (int k = 0; k < 6; k++)
            #pragma unroll
            for (int o = 16; o; o >>= 1) m[k] += __shfl_xor_sync(0xffffffffu, m[k], o);
        if (lane == 0) for (int k = 0; k < 6; k++) sred[warp][k] = m[k];
    }
    __syncthreads();
    if (tid == 0) {
        double m[6];
        for (int k = 0; k < 6; k++) { double t=0; for (int w=0; w<8; w++) t += sred[w][k]; m[k]=t; }
        double V[3][3];
        jacobi3(m[0],m[1],m[2],m[3],m[4],m[5], V);
        for (int i = 0; i < 3; i++)
            for (int j = 0; j < 3; j++) { sV[i*3+j] = (float)V[i][j]; g_V[b*9+i*3+j] = (float)V[i][j]; }
        sC[0]=(float)c0; sC[1]=(float)c1; sC[2]=(float)c2;
        g_center[b*3+0]=(float)c0; g_center[b*3+1]=(float)c1; g_center[b*3+2]=(float)c2;
    }
    __syncthreads();

    for (int p = tid; p < 512; p += 256) {
        int t = b*512 + p;
        float dx = G[p*3]-sC[0], dy = G[p*3+1]-sC[1], dz = G[p*3+2]-sC[2];
        for (int d = 0; d < 3; d++)
            g_proj[t*3+d] = dx*sV[0*3+d] + dy*sV[1*3+d] + dz*sV[2*3+d];
    }
}

// ---------------- qkv GEMM: full-K A resident + LN + gate ----------------
__global__ __launch_bounds__(256)
void gemm_qkv(const float* __restrict__ A, const float* __restrict__ Bw,
              const float* __restrict__ bias, float* __restrict__ C,
              const float* __restrict__ Wg, const float* __restrict__ bg,
              const float* __restrict__ lng, const float* __restrict__ lnb)
{
    constexpr int K = 256, N = QS;
    constexpr int SA = 292, BS = 292;
    constexpr int WN = N/4, NT = WN/8, CT = N/32, KT = K/32;
    extern __shared__ float smem[];
    float* sA = smem;
    float* sB = smem + 32*SA;
    const int tid = threadIdx.x, lane = tid & 31, warp = tid >> 5;
    const int wr = warp >> 2, wc = warp & 3;
    const int gid = lane >> 2, tig = lane & 3;
    const int rowBase = blockIdx.x*32;

    for (int i = tid; i < 32*64; i += 256) {
        int r = i >> 6, c4 = i & 63;
        *(float4*)&sA[r*SA + c4*4] = *(const float4*)&A[(size_t)(rowBase + r)*K + c4*4];
    }
    __syncthreads();
    #pragma unroll
    for (int rr = 0; rr < 4; rr++) {
        int row = warp*4 + rr;
        float v[8]; float s = 0.f, s2 = 0.f, gd = 0.f;
        #pragma unroll
        for (int j = 0; j < 8; j++) {
            int c = lane + 32*j;
            float t = sA[row*SA + c];
            v[j] = t; s += t; s2 += t*t; gd += t*Wg[c];
        }
        #pragma unroll
        for (int o = 16; o; o >>= 1) {
            s  += __shfl_xor_sync(0xffffffffu, s,  o);
            s2 += __shfl_xor_sync(0xffffffffu, s2, o);
            gd += __shfl_xor_sync(0xffffffffu, gd, o);
        }
        float mean = s*(1.f/256.f);
        float rstd = rsqrtf(s2*(1.f/256.f) - mean*mean + 1e-5f);
        #pragma unroll
        for (int j = 0; j < 8; j++) {
            int c = lane + 32*j;
            sA[row*SA + c] = (v[j]-mean)*rstd*lng[c] + lnb[c];
        }
        if (lane == 0) g_gate[rowBase + row] = 1.f/(1.f + __expf(-(gd + bg[0])));
    }

    float acc[NT][4];
    #pragma unroll
    for (int t = 0; t < NT; t++) {
        int j0 = wc*WN + t*8 + tig*2;
        acc[t][0] = bias[j0];   acc[t][1] = bias[j0+1];
        acc[t][2] = bias[j0];   acc[t][3] = bias[j0+1];
    }

    float4 rB[9];
    #pragma unroll
    for (int jj = 0; jj < 9; jj++) {
        int idx = tid + 256*jj;
        int r = idx/72, c4 = idx - r*72;
        rB[jj] = *(const float4*)&Bw[(size_t)r*N + c4*4];
    }
    for (int kt = 0; kt < KT; ++kt) {
        __syncthreads();
        #pragma unroll
        for (int jj = 0; jj < 9; jj++) {
            int idx = tid + 256*jj;
            int r = idx/72, c4 = idx - r*72;
            *(float4*)&sB[r*BS + c4*4] = rB[jj];
        }
        __syncthreads();
        if (kt + 1 < KT) {
            #pragma unroll
            for (int jj = 0; jj < 9; jj++) {
                int idx = tid + 256*jj;
                int r = idx/72, c4 = idx - r*72;
                rB[jj] = *(const float4*)&Bw[(size_t)((kt+1)*32 + r)*N + c4*4];
            }
        }
        #pragma unroll
        for (int kk = 0; kk < 4; kk++) {
            int kc = kt*32 + kk*8;
            uint32_t a0 = __float_as_uint(sA[(wr*16 + gid    )*SA + kc + tig    ]);
            uint32_t a1 = __float_as_uint(sA[(wr*16 + gid + 8)*SA + kc + tig    ]);
            uint32_t a2 = __float_as_uint(sA[(wr*16 + gid    )*SA + kc + tig + 4]);
            uint32_t a3 = __float_as_uint(sA[(wr*16 + gid + 8)*SA + kc + tig + 4]);
            #pragma unroll
            for (int t = 0; t < NT; t++) {
                int n0 = wc*WN + t*8;
                uint32_t b0 = __float_as_uint(sB[(kk*8 + tig    )*BS + n0 + gid]);
                uint32_t b1 = __float_as_uint(sB[(kk*8 + tig + 4)*BS + n0 + gid]);
                asm volatile(
                    "mma.sync.aligned.m16n8k8.row.col.f32.tf32.tf32.f32 "
                    "{%0,%1,%2,%3}, {%4,%5,%6,%7}, {%8,%9}, {%0,%1,%2,%3};"
                    : "+f"(acc[t][0]), "+f"(acc[t][1]), "+f"(acc[t][2]), "+f"(acc[t][3])
                    : "r"(a0), "r"(a1), "r"(a2), "r"(a3), "r"(b0), "r"(b1));
            }
        }
    }

    __syncthreads();
    #pragma unroll
    for (int t = 0; t < NT; t++) {
        int n0 = wc*WN + t*8 + tig*2;
        int r0 = wr*16 + gid;
        sA[ r0     *SA + n0    ] = acc[t][0];
        sA[ r0     *SA + n0 + 1] = acc[t][1];
        sA[(r0 + 8)*SA + n0    ] = acc[t][2];
        sA[(r0 + 8)*SA + n0 + 1] = acc[t][3];
    }
    __syncthreads();
    #pragma unroll
    for (int rr = 0; rr < 4; rr++) {
        int row = warp*4 + rr;
        int grow = rowBase + row;
        #pragma unroll
        for (int j = 0; j < CT; j++) {
            int col = lane + 32*j;
            C[(size_t)grow*N + col] = sA[row*SA + col];
        }
    }
}

// ---------------- BM=64 cp.async 3-stage pipelined tf32 GEMM, 512 threads ----------------
// EPI: 1 = gelu+LN, 2 = +residual. N=256.
template<int K, int EPI>
__global__ __launch_bounds__(512)
void gemm_cp(const float* __restrict__ A, const float* __restrict__ Bw,
             const float* __restrict__ bias, float* __restrict__ C,
             const float* __restrict__ p1, const float* __restrict__ p2)
{
    constexpr int N = 256;
    constexpr int KT = K/32, SA = 36, BS = N + 4;
    constexpr int ASZ = 64*SA, BSZ = 32*BS, STGSZ = ASZ + BSZ;
    constexpr int NT = 8, CT = N/32;
    extern __shared__ float smem[];
    const int tid = threadIdx.x, lane = tid & 31, warp = tid >> 5;
    const int wr = warp >> 2, wc = warp & 3;
    const int gid = lane >> 2, tig = lane & 3;
    const int rowBase = blockIdx.x*64;

    const int ar = tid >> 3, ac4 = tid & 7;

    auto issue = [&](int kt) {
        float* dA = smem + (kt % 3)*STGSZ;
        float* dB = dA + ASZ;
        CP_ASYNC16(sptr(&dA[ar*SA + ac4*4]),
                   &A[(size_t)(rowBase + ar)*K + kt*32 + ac4*4]);
        #pragma unroll
        for (int jj = 0; jj < 4; jj++) {
            int idx = tid + 512*jj;
            int r = idx >> 6, c4 = idx & 63;
            CP_ASYNC16(sptr(&dB[r*BS + c4*4]),
                       &Bw[(size_t)(kt*32 + r)*N + c4*4]);
        }
        CP_COMMIT();
    };

    issue(0);
    issue(1);

    float acc[NT][4];
    #pragma unroll
    for (int t = 0; t < NT; t++) {
        int j0 = wc*64 + t*8 + tig*2;
        acc[t][0] = bias[j0];   acc[t][1] = bias[j0+1];
        acc[t][2] = bias[j0];   acc[t][3] = bias[j0+1];
    }

    for (int kt = 0; kt < KT; ++kt) {
        CP_WAIT1();
        __syncthreads();
        if (kt + 2 < KT) issue(kt + 2);
        const float* sA = smem + (kt % 3)*STGSZ;
        const float* sB = sA + ASZ;
        #pragma unroll
        for (int kk = 0; kk < 4; kk++) {
            uint32_t a0 = __float_as_uint(sA[(wr*16 + gid    )*SA + kk*8 + tig    ]);
            uint32_t a1 = __float_as_uint(sA[(wr*16 + gid + 8)*SA + kk*8 + tig    ]);
            uint32_t a2 = __float_as_uint(sA[(wr*16 + gid    )*SA + kk*8 + tig + 4]);
            uint32_t a3 = __float_as_uint(sA[(wr*16 + gid + 8)*SA + kk*8 + tig + 4]);
            #pragma unroll
            for (int t = 0; t < NT; t++) {
                int n0 = wc*64 + t*8;
                uint32_t b0 = __float_as_uint(sB[(kk*8 + tig    )*BS + n0 + gid]);
                uint32_t b1 = __float_as_uint(sB[(kk*8 + tig + 4)*BS + n0 + gid]);
                asm volatile(
                    "mma.sync.aligned.m16n8k8.row.col.f32.tf32.tf32.f32 "
                    "{%0,%1,%2,%3}, {%4,%5,%6,%7}, {%8,%9}, {%0,%1,%2,%3};"
                    : "+f"(acc[t][0]), "+f"(acc[t][1]), "+f"(acc[t][2]), "+f"(acc[t][3])
                    : "r"(a0), "r"(a1), "r"(a2), "r"(a3), "r"(b0), "r"(b1));
            }
        }
    }

    // stage C [64][BS] over the (now dead) pipeline smem
    float* sC = smem;
    __syncthreads();
    #pragma unroll
    for (int t = 0; t < NT; t++) {
        int n0 = wc*64 + t*8 + tig*2;
        int r0 = wr*16 + gid;
        sC[ r0     *BS + n0    ] = acc[t][0];
        sC[ r0     *BS + n0 + 1] = acc[t][1];
        sC[(r0 + 8)*BS + n0    ] = acc[t][2];
        sC[(r0 + 8)*BS + n0 + 1] = acc[t][3];
    }
    __syncthreads();

    #pragma unroll
    for (int rr = 0; rr < 4; rr++) {
        int row = warp*4 + rr;
        int grow = rowBase + row;
        if (EPI == 1) {
            float v[CT]; float s = 0.f, s2 = 0.f;
            #pragma unroll
            for (int j = 0; j < CT; j++) {
                float x = sC[row*BS + lane + 32*j];
                x = 0.5f*x*(1.f + erff(x*0.70710678118654752f));
                v[j] = x; s += x; s2 += x*x;
            }
            #pragma unroll
            for (int o = 16; o; o >>= 1) {
                s  += __shfl_xor_sync(0xffffffffu, s,  o);
                s2 += __shfl_xor_sync(0xffffffffu, s2, o);
            }
            float mean = s*(1.f/256.f);
            float rstd = rsqrtf(s2*(1.f/256.f) - mean*mean + 1e-5f);
            #pragma unroll
            for (int j = 0; j < CT; j++) {
                int col = lane + 32*j;
                C[(size_t)grow*256 + col] = (v[j]-mean)*rstd*p1[col] + p2[col];
            }
        } else {
            #pragma unroll
            for (int j = 0; j < CT; j++) {
                int col = lane + 32*j;
                C[(size_t)grow*256 + col] = sC[row*BS + col] + p1[(size_t)grow*256 + col];
            }
        }
    }
}

// ---------------- fused per-token attention: 4 groups, 4 barriers/token ----------------
struct AttnGroup {
    float edge[32*ES];    // raw edge rows
    float logit[8*32];
    float attnT[32*8];    // [m][h]
    float arT[32*8];      // [m][h] attn*rstd
    float mean[32];
    float rstd[32];
    float s1[8];
    float qd[8];
    int   nbr[32];
};
struct AttnSmem {
    float wg[8*132];      // [h][c]: lng*weff
    float swg[8];
    float beff2[8];
    float wfa[8];
    float lng[128];
    float lnb[128];
    AttnGroup grp[4];
};

#define GBAR(id) asm volatile("bar.sync %0, 128;" :: "r"(id) : "memory")

__global__ __launch_bounds__(512, 2)
void attn_kernel(const float* __restrict__ edge_feats,
                 const float* __restrict__ geo_feats,
                 const int*   __restrict__ nbr_idx,
                 const int*   __restrict__ masks,
                 const float* __restrict__ ln_e_g,
                 const float* __restrict__ ln_e_b,
                 const float* __restrict__ W_fa,
                 const float* __restrict__ b_fa,
                 float* __restrict__ out_geo)
{
    extern __shared__ char smraw[];
    AttnSmem& sm = *reinterpret_cast<AttnSmem*>(smraw);
    const int tid = threadIdx.x;

    for (int i = tid; i < 8*132; i += 512) sm.wg[i] = g_wg[i];
    if (tid < 128) { sm.lng[tid] = ln_e_g[tid]; sm.lnb[tid] = ln_e_b[tid]; }
    if (tid >= 128 && tid < 136) {
        int h = tid - 128;
        sm.swg[h] = g_swg[h]; sm.beff2[h] = g_beff2[h]; sm.wfa[h] = W_fa[h];
    }
    const float bfa = b_fa[0];
    __syncthreads();

    const int g     = tid >> 7;
    const int gtid  = tid & 127;
    const int glane = gtid & 31;
    const int gwarp = gtid >> 5;
    const int bid   = 1 + g;
    AttnGroup& G = sm.grp[g];

    for (int tok = 0; tok < 2; ++tok) {
        const int n = blockIdx.x*8 + g*2 + tok;

        // phase 1: edge load + fused row stats + nbr/qd
        {
            const float4* ep4 = (const float4*)(edge_feats + (size_t)n*4096);
            #pragma unroll
            for (int jj = 0; jj < 8; jj++) {
                int idx = gtid + 128*jj;
                int m = gwarp + 4*jj;                 // = idx >> 5
                float4 v = ep4[idx];
                *(float4*)&G.edge[m*ES + glane*4] = v;
                float s  = v.x + v.y + v.z + v.w;
                float s2 = v.x*v.x + v.y*v.y + v.z*v.z + v.w*v.w;
                #pragma unroll
                for (int o = 16; o; o >>= 1) {
                    s  += __shfl_xor_sync(0xffffffffu, s,  o);
                    s2 += __shfl_xor_sync(0xffffffffu, s2, o);
                }
                if (glane == 0) {
                    float mean = s*(1.f/128.f);
                    float rstd = rsqrtf(s2*(1.f/128.f) - mean*mean + 1e-5f);
                    G.mean[m] = mean; G.rstd[m] = rstd;
                }
            }
            if (gtid < 32) G.nbr[gtid] = nbr_idx[n*32 + gtid];
            if (gtid >= 32 && gtid < 40) G.qd[gtid-32] = g_qkv[(size_t)n*QS + 256 + gtid-32];
        }
        GBAR(bid);

        // phase 2: logits (kd/msk gathered direct from gmem, latency hidden by dot loop)
        {
            int m0 = gtid >> 3, h = gtid & 7;
            int nb0 = G.nbr[m0], nb1 = G.nbr[m0 + 16];
            float kd0 = g_qkv[(size_t)nb0*QS + 264 + h];
            float kd1 = g_qkv[(size_t)nb1*QS + 264 + h];
            int mk0 = masks[n*32 + m0];
            int mk1 = masks[n*32 + m0 + 16];
            float d0 = 0.f, d1 = 0.f;
            const float4* e0 = (const float4*)&G.edge[m0*ES];
            const float4* e1 = (const float4*)&G.edge[(m0+16)*ES];
            const float4* wt = (const float4*)&sm.wg[h*132];
            #pragma unroll 8
            for (int c4 = 0; c4 < 32; c4++) {
                float4 w = wt[c4], x = e0[c4], y = e1[c4];
                d0 += x.x*w.x + x.y*w.y + x.z*w.z + x.w*w.w;
                d1 += y.x*w.x + y.y*w.y + y.z*w.z + y.w*w.w;
            }
            float base = G.qd[h] + sm.beff2[h];
            float sw = sm.swg[h];
            float a0 = base + kd0 + G.rstd[m0]   *(d0 - G.mean[m0]   *sw);
            float a1 = base + kd1 + G.rstd[m0+16]*(d1 - G.mean[m0+16]*sw);
            if (!mk0) a0 = -1e9f;
            if (!mk1) a1 = -1e9f;
            G.logit[h*32 + m0]      = a0;
            G.logit[h*32 + m0 + 16] = a1;
        }
        GBAR(bid);

        // phase 3: softmax + transpose + ar/s1
        {
            #pragma unroll
            for (int i = 0; i < 2; i++) {
                int h = gwarp + 4*i;
                float l = G.logit[h*32 + glane];
                float mx = l;
                #pragma unroll
                for (int o = 16; o; o >>= 1) mx = fmaxf(mx, __shfl_xor_sync(0xffffffffu, mx, o));
                float e = __expf(l - mx);
                float ss = e;
                #pragma unroll
                for (int o = 16; o; o >>= 1) ss += __shfl_xor_sync(0xffffffffu, ss, o);
                float a = e/ss;
                float ar = a*G.rstd[glane];
                float s1p = ar*G.mean[glane];
                #pragma unroll
                for (int o = 16; o; o >>= 1) s1p += __shfl_xor_sync(0xffffffffu, s1p, o);
                G.attnT[glane*8 + h] = a;
                G.arT[glane*8 + h]   = ar;
                if (glane == 0) G.s1[h] = s1p;
            }
        }
        GBAR(bid);

        // phase 4: scalar ctx + ew + geo
        {
            float acc0 = 0.f, acc1 = 0.f;
            int c0 = gtid, c1 = gtid + 128;
            int h0 = c0 >> 5, h1 = c1 >> 5;
            #pragma unroll
            for (int m = 0; m < 32; m++) {
                const float* vrow = &g_qkv[(size_t)G.nbr[m]*QS];
                acc0 += G.attnT[m*8 + h0]*vrow[c0];
                acc1 += G.attnT[m*8 + h1]*vrow[c1];
            }
            g_hx[(size_t)n*HXS + c0] = acc0;
            g_hx[(size_t)n*HXS + c1] = acc1;

            float ewa[8];
            #pragma unroll
            for (int h = 0; h < 8; h++) ewa[h] = 0.f;
            const float4* ar4 = (const float4*)G.arT;
            #pragma unroll
            for (int m = 0; m < 32; m++) {
                float e = G.edge[m*ES + gtid];
                float4 r0 = ar4[m*2], r1 = ar4[m*2 + 1];
                ewa[0] += r0.x*e; ewa[1] += r0.y*e; ewa[2] += r0.z*e; ewa[3] += r0.w*e;
                ewa[4] += r1.x*e; ewa[5] += r1.y*e; ewa[6] += r1.z*e; ewa[7] += r1.w*e;
            }
            float gl = sm.lng[gtid], bl = sm.lnb[gtid];
            #pragma unroll
            for (int h = 0; h < 8; h++)
                g_hx[(size_t)n*HXS + 256 + h*128 + gtid] = gl*(ewa[h] - G.s1[h]) + bl;
        }
        if (gwarp == 3) {
            int m = glane;
            float aw = 0.f;
            #pragma unroll
            for (int h = 0; h < 8; h++) aw += G.attnT[m*8 + h]*sm.wfa[h];
            int nb = G.nbr[m];
            float p0 = aw*g_proj[nb*3 + 0];
            float p1 = aw*g_proj[nb*3 + 1];
            float p2 = aw*g_proj[nb*3 + 2];
            #pragma unroll
            for (int o = 16; o; o >>= 1) {
                p0 += __shfl_xor_sync(0xffffffffu, p0, o);
                p1 += __shfl_xor_sync(0xffffffffu, p1, o);
                p2 += __shfl_xor_sync(0xffffffffu, p2, o);
            }
            if (glane == 0) {
                int b = n >> 9;
                float ps[3] = {p0, p1, p2};
                float sd[3];
                #pragma unroll
                for (int j = 0; j < 3; j++)
                    sd[j] = 0.5f*(siluf(ps[j] + bfa) - siluf(-ps[j] + bfa));
                float gt = g_gate[n];
                #pragma unroll
                for (int i = 0; i < 3; i++) {
                    float gc = g_center[b*3 + i]
                             + sd[0]*g_V[b*9 + i*3 + 0]
                             + sd[1]*g_V[b*9 + i*3 + 1]
                             + sd[2]*g_V[b*9 + i*3 + 2];
                    out_geo[n*3 + i] = gc*gt + geo_feats[n*3 + i]*(1.f - gt);
                }
            }
        }
        GBAR(bid);
    }
}

// ---------------- launcher ----------------
extern "C" void kernel_launch(void* const* d_in, const int* in_sizes, int n_in,
                              void* d_out, int out_size)
{
    const float* token    = (const float*)d_in[0];
    const float* geo      = (const float*)d_in[1];
    const float* edge     = (const float*)d_in[2];
    const int*   nbr      = (const int*)d_in[3];
    const int*   mask     = (const int*)d_in[5];
    const float* ln_qkv_g = (const float*)d_in[6];
    const float* ln_qkv_b = (const float*)d_in[7];
    const float* W_qkv    = (const float*)d_in[8];
    const float* b_qkv    = (const float*)d_in[9];
    const float* ln_e_g   = (const float*)d_in[10];
    const float* ln_e_b   = (const float*)d_in[11];
    const float* W_qkv_e  = (const float*)d_in[12];
    const float* b_qkv_e  = (const float*)d_in[13];
    const float* w_attn   = (const float*)d_in[14];
    const float* w_edge   = (const float*)d_in[15];
    const float* W_gate   = (const float*)d_in[16];
    const float* b_gate   = (const float*)d_in[17];
    const float* W_fc1    = (const float*)d_in[18];
    const float* b_fc1    = (const float*)d_in[19];
    const float* ln_h_g   = (const float*)d_in[20];
    const float* ln_h_b   = (const float*)d_in[21];
    const float* W_fc2    = (const float*)d_in[22];
    const float* b_fc2    = (const float*)d_in[23];
    const float* W_fa     = (const float*)d_in[24];
    const float* b_fa     = (const float*)d_in[25];
    float* out = (float*)d_out;

    void* p;
    cudaGetSymbolAddress(&p, g_qkv);   float* p_qkv   = (float*)p;
    cudaGetSymbolAddress(&p, g_hx);    float* p_hx    = (float*)p;
    cudaGetSymbolAddress(&p, g_hmid);  float* p_hmid  = (float*)p;
    cudaGetSymbolAddress(&p, g_Wcomb); float* p_Wcomb = (float*)p;
    cudaGetSymbolAddress(&p, g_bcomb); float* p_bcomb = (float*)p;
    cudaGetSymbolAddress(&p, g_W1);    float* p_W1    = (float*)p;
    cudaGetSymbolAddress(&p, g_b1);    float* p_b1    = (float*)p;

    prep_kernel<<<64, 256>>>(W_qkv, b_qkv, w_attn, W_qkv_e, b_qkv_e, w_edge,
                             W_fc1, b_fc1, ln_e_g, ln_e_b);
    geom_kernel<<<16, 256>>>(geo);

    {
        constexpr int SM = (32*292 + 32*292)*sizeof(float);
        cudaFuncSetAttribute((const void*)gemm_qkv,
                             cudaFuncAttributeMaxDynamicSharedMemorySize, SM);
        gemm_qkv<<<256, 256, SM>>>(token, p_Wcomb, p_bcomb, p_qkv,
                                   W_gate, b_gate, ln_qkv_g, ln_qkv_b);
    }

    cudaFuncSetAttribute(attn_kernel, cudaFuncAttributeMaxDynamicSharedMemorySize,
                         (int)sizeof(AttnSmem));
    attn_kernel<<<1024, 512, sizeof(AttnSmem)>>>(
        edge, geo, nbr, mask, ln_e_g, ln_e_b, W_fa, b_fa,
        out + (size_t)NTOK*256);

    // fc1 (folded): hx[8192,1280] @ W1[1280,256] -> gelu -> LN -> hmid
    {
        constexpr int SM = 3*(64*36 + 32*260)*sizeof(float);
        cudaFuncSetAttribute((const void*)gemm_cp<HXS, 1>,
                             cudaFuncAttributeMaxDynamicSharedMemorySize, SM);
        gemm_cp<HXS, 1><<<128, 512, SM>>>(p_hx, p_W1, p_b1, p_hmid, ln_h_g, ln_h_b);
    }

    // fc2: hmid[8192,256] @ W_fc2[256,256] + token -> out
    {
        constexpr int SM = 3*(64*36 + 32*260)*sizeof(float);
        cudaFuncSetAttribute((const void*)gemm_cp<256, 2>,
                             cudaFuncAttributeMaxDynamicSharedMemorySize, SM);
        gemm_cp<256, 2><<<128, 512, SM>>>(p_hmid, W_fc2, b_fc2, out, token, nullptr);
    }
}

// round 9
// speedup vs baseline: 1.0672x; 1.0251x over previous
#include <cuda_runtime.h>
#include <math.h>
#include <stdint.h>

#define NTOK 8192
#define QS 288            // qkv row stride: 256 v | 8 qdot | 8 kdot | pad
#define ES 132            // edge smem row stride (floats)
#define HXS 1280          // hx row stride: 256 scalar ctx | 1024 ew

// ---------------- device scratch ----------------
__device__ float g_lnx[NTOK*256];
__device__ float g_qkv[NTOK*QS];
__device__ float g_hx[NTOK*HXS];
__device__ float g_gate[NTOK];
__device__ float g_proj[NTOK*3];
__device__ float g_center[16*3];
__device__ float g_V[16*9];
__device__ float g_Wcomb[256*QS];
__device__ float g_bcomb[QS];
__device__ float g_wg[8*132];       // [h][c]: lng[c]*weff[c][h], padded
__device__ float g_swg[8];
__device__ float g_beff2[8];
__device__ float g_W1[HXS*256];     // folded fc1 weight: [1280, 256]
__device__ float g_b1[256];         // folded fc1 bias

__device__ __forceinline__ float siluf(float x){ return x/(1.f+__expf(-x)); }

#define CP_ASYNC16(dst, src) \
    asm volatile("cp.async.ca.shared.global [%0], [%1], 16;\n" :: "r"(dst), "l"(src))
#define CP_COMMIT() asm volatile("cp.async.commit_group;\n" ::: "memory")
#define CP_WAIT1()  asm volatile("cp.async.wait_group 1;\n" ::: "memory")
#define CP_WAIT0()  asm volatile("cp.async.wait_group 0;\n" ::: "memory")

__device__ __forceinline__ uint32_t sptr(const void* p){
    return (uint32_t)__cvta_generic_to_shared(p);
}

// ---------------- prep: fold effective weights ----------------
__global__ void prep_kernel(const float* __restrict__ W_qkv, const float* __restrict__ b_qkv,
                            const float* __restrict__ w_attn,
                            const float* __restrict__ W_qkv_e, const float* __restrict__ b_qkv_e,
                            const float* __restrict__ w_edge,
                            const float* __restrict__ W_fc1, const float* __restrict__ b_fc1,
                            const float* __restrict__ ln_e_g, const float* __restrict__ ln_e_b)
{
    int gid = blockIdx.x*blockDim.x + threadIdx.x;
    int gstride = gridDim.x*blockDim.x;
    for (int idx = gid; idx < 256*QS; idx += gstride) {
        int c = idx / QS, j = idx - c*QS;
        float w = 0.f;
        if (j < 256) {
            w = W_qkv[c*768 + 512 + j];
        } else if (j < 264) {
            int h = j - 256; float s = 0.f;
            #pragma unroll
            for (int d = 0; d < 32; d++) s += W_qkv[c*768 + h*32 + d]*w_attn[d];
            w = s;
        } else if (j < 272) {
            int h = j - 264; float s = 0.f;
            #pragma unroll
            for (int d = 0; d < 32; d++) s += W_qkv[c*768 + 256 + h*32 + d]*w_attn[d];
            w = s;
        }
        g_Wcomb[idx] = w;
    }
    for (int idx = gid; idx < HXS*256; idx += gstride) {
        int j = idx >> 8, o = idx & 255;
        float w;
        if (j < 256) {
            w = W_fc1[j*256 + o];
        } else {
            int hc = j - 256, h = hc >> 7, c = hc & 127;
            float s = 0.f;
            #pragma unroll
            for (int jp = 0; jp < 16; jp++)
                s += W_qkv_e[c*256 + 128 + h*16 + jp]*W_fc1[(256 + h*16 + jp)*256 + o];
            w = s;
        }
        g_W1[idx] = w;
    }
    if (blockIdx.x == 0) {
        for (int j = threadIdx.x; j < QS; j += blockDim.x) {
            float bv = 0.f;
            if (j < 256) bv = b_qkv[512 + j];
            else if (j < 264) { int h = j-256; for (int d=0; d<32; d++) bv += b_qkv[h*32+d]*w_attn[d]; }
            else if (j < 272) { int h = j-264; for (int d=0; d<32; d++) bv += b_qkv[256 + h*32+d]*w_attn[d]; }
            g_bcomb[j] = bv;
        }
    }
    if (blockIdx.x == 1) {
        __shared__ float sweff[128*8];
        for (int idx = threadIdx.x; idx < 128*8; idx += blockDim.x) {
            int c = idx >> 3, h = idx & 7; float s = 0.f;
            #pragma unroll
            for (int e = 0; e < 16; e++) s += W_qkv_e[c*256 + h*16 + e]*w_edge[e];
            sweff[idx] = s;
            g_wg[h*132 + c] = ln_e_g[c]*s;
        }
        __syncthreads();
        if (threadIdx.x < 8) {
            int h = threadIdx.x;
            float sw = 0.f, b2 = 0.f;
            for (int c = 0; c < 128; c++) {
                float we = sweff[c*8 + h];
                sw += ln_e_g[c]*we;
                b2 += ln_e_b[c]*we;
            }
            for (int e = 0; e < 16; e++) b2 += b_qkv_e[h*16 + e]*w_edge[e];
            g_swg[h] = sw; g_beff2[h] = b2;
        }
    }
    if (blockIdx.x == 2 && threadIdx.x < 256) {
        int o = threadIdx.x;
        float s = b_fc1[o];
        for (int j = 0; j < 128; j++)
            s += b_qkv_e[128 + j]*W_fc1[(256 + j)*256 + o];
        g_b1[o] = s;
    }
}

// ---------------- per-graph geometry ----------------
__device__ void jacobi3(double a00,double a01,double a02,double a11,double a12,double a22,
                        double V[3][3])
{
    double A[3][3] = {{a00,a01,a02},{a01,a11,a12},{a02,a12,a22}};
    V[0][0]=1; V[0][1]=0; V[0][2]=0;
    V[1][0]=0; V[1][1]=1; V[1][2]=0;
    V[2][0]=0; V[2][1]=0; V[2][2]=1;
    for (int it = 0; it < 60; ++it) {
        int p = 0, q = 1; double mx = fabs(A[0][1]);
        if (fabs(A[0][2]) > mx) { mx = fabs(A[0][2]); p = 0; q = 2; }
        if (fabs(A[1][2]) > mx) { mx = fabs(A[1][2]); p = 1; q = 2; }
        if (mx <= 1e-13*(fabs(A[0][0])+fabs(A[1][1])+fabs(A[2][2]))) break;
        double apq = A[p][q];
        double theta = (A[q][q]-A[p][p])/(2.0*apq);
        double t = 1.0/(fabs(theta)+sqrt(theta*theta+1.0));
        if (theta < 0) t = -t;
        double c = 1.0/sqrt(t*t+1.0), s = t*c;
        for (int k = 0; k < 3; k++) { double akp=A[k][p], akq=A[k][q]; A[k][p]=c*akp-s*akq; A[k][q]=s*akp+c*akq; }
        for (int k = 0; k < 3; k++) { double apk=A[p][k], aqk=A[q][k]; A[p][k]=c*apk-s*aqk; A[q][k]=s*apk+c*aqk; }
        for (int k = 0; k < 3; k++) { double vkp=V[k][p], vkq=V[k][q]; V[k][p]=c*vkp-s*vkq; V[k][q]=s*vkp+c*vkq; }
    }
}

__global__ void geom_kernel(const float* __restrict__ geo)
{
    __shared__ double sred[8][9];
    __shared__ double sCd[3];
    __shared__ float sV[9], sC[3];
    int b = blockIdx.x, tid = threadIdx.x, lane = tid & 31, warp = tid >> 5;
    const float* G = geo + (size_t)b*512*3;

    {
        double s[3] = {0,0,0};
        for (int p = tid; p < 512; p += 256) { s[0] += G[p*3]; s[1] += G[p*3+1]; s[2] += G[p*3+2]; }
        #pragma unroll
        for (int k = 0; k < 3; k++)
            #pragma unroll
            for (int o = 16; o; o >>= 1) s[k] += __shfl_xor_sync(0xffffffffu, s[k], o);
        if (lane == 0) { sred[warp][0]=s[0]; sred[warp][1]=s[1]; sred[warp][2]=s[2]; }
    }
    __syncthreads();
    if (tid == 0) {
        for (int k = 0; k < 3; k++) {
            double t = 0; for (int w = 0; w < 8; w++) t += sred[w][k];
            sCd[k] = t/512.0;
        }
    }
    __syncthreads();
    double c0 = sCd[0], c1 = sCd[1], c2 = sCd[2];

    {
        double m[6] = {0,0,0,0,0,0};
        for (int p = tid; p < 512; p += 256) {
            double dx = G[p*3]-c0, dy = G[p*3+1]-c1, dz = G[p*3+2]-c2;
            m[0] += dx*dx; m[1] += dx*dy; m[2] += dx*dz;
            m[3] += dy*dy; m[4] += dy*dz; m[5] += dz*dz;
        }
        #pragma unroll
        for (int k = 0; k < 6; k++)
            #pragma unroll
            for (int o = 16; o; o >>= 1) m[k] += __shfl_xor_sync(0xffffffffu, m[k], o);
        if (lane == 0) for (int k = 0; k < 6; k++) sred[warp][k] = m[k];
    }
    __syncthreads();
    if (tid == 0) {
        double m[6];
        for (int k = 0; k < 6; k++) { double t=0; for (int w=0; w<8; w++) t += sred[w][k]; m[k]=t; }
        double V[3][3];
        jacobi3(m[0],m[1],m[2],m[3],m[4],m[5], V);
        for (int i = 0; i < 3; i++)
            for (int j = 0; j < 3; j++) { sV[i*3+j] = (float)V[i][j]; g_V[b*9+i*3+j] = (float)V[i][j]; }
        sC[0]=(float)c0; sC[1]=(float)c1; sC[2]=(float)c2;
        g_center[b*3+0]=(float)c0; g_center[b*3+1]=(float)c1; g_center[b*3+2]=(float)c2;
    }
    __syncthreads();

    for (int p = tid; p < 512; p += 256) {
        int t = b*512 + p;
        float dx = G[p*3]-sC[0], dy = G[p*3+1]-sC[1], dz = G[p*3+2]-sC[2];
        for (int d = 0; d < 3; d++)
            g_proj[t*3+d] = dx*sV[0*3+d] + dy*sV[1*3+d] + dz*sV[2*3+d];
    }
}

// ---------------- token LN + gate ----------------
__global__ __launch_bounds__(256)
void ln_gate_kernel(const float* __restrict__ X,
                    const float* __restrict__ gw, const float* __restrict__ gb,
                    const float* __restrict__ Wg, const float* __restrict__ bg)
{
    int lane = threadIdx.x & 31, warp = threadIdx.x >> 5;
    int row = blockIdx.x*8 + warp;
    const float* x = X + (size_t)row*256;
    float v[8]; float s = 0.f, s2 = 0.f, gd = 0.f;
    #pragma unroll
    for (int j = 0; j < 8; j++) {
        int c = lane + 32*j;
        float t = x[c]; v[j] = t; s += t; s2 += t*t; gd += t*Wg[c];
    }
    #pragma unroll
    for (int o = 16; o; o >>= 1) {
        s  += __shfl_xor_sync(0xffffffffu, s,  o);
        s2 += __shfl_xor_sync(0xffffffffu, s2, o);
        gd += __shfl_xor_sync(0xffffffffu, gd, o);
    }
    float mean = s*(1.f/256.f);
    float rstd = rsqrtf(s2*(1.f/256.f) - mean*mean + 1e-5f);
    #pragma unroll
    for (int j = 0; j < 8; j++) {
        int c = lane + 32*j;
        g_lnx[(size_t)row*256 + c] = (v[j]-mean)*rstd*gw[c] + gb[c];
    }
    if (lane == 0) g_gate[row] = 1.f/(1.f + __expf(-(gd + bg[0])));
}

// ---------------- generic BM=64 cp.async 3-stage tf32 GEMM, 512 threads ----------------
// EPI 0: plain store.
template<int K, int N, int EPI>
__global__ __launch_bounds__(512)
void gemm_cp(const float* __restrict__ A, const float* __restrict__ Bw,
             const float* __restrict__ bias, float* __restrict__ C)
{
    constexpr int KT = K/32, SA = 36, BS = N + 4;
    constexpr int ASZ = 64*SA, BSZ = 32*BS, STGSZ = ASZ + BSZ;
    constexpr int WN = N/4, NT = WN/8, CT = N/32;
    extern __shared__ float smem[];
    const int tid = threadIdx.x, lane = tid & 31, warp = tid >> 5;
    const int wr = warp >> 2, wc = warp & 3;
    const int gid = lane >> 2, tig = lane & 3;
    const int rowBase = blockIdx.x*64;
    const int ar = tid >> 3, ac4 = tid & 7;

    auto issue = [&](int kt) {
        float* dA = smem + (kt % 3)*STGSZ;
        float* dB = dA + ASZ;
        CP_ASYNC16(sptr(&dA[ar*SA + ac4*4]),
                   &A[(size_t)(rowBase + ar)*K + kt*32 + ac4*4]);
        for (int idx = tid; idx < 32*(N/4); idx += 512) {
            int r = idx/(N/4), c4 = idx - r*(N/4);
            CP_ASYNC16(sptr(&dB[r*BS + c4*4]),
                       &Bw[(size_t)(kt*32 + r)*N + c4*4]);
        }
        CP_COMMIT();
    };

    issue(0);
    issue(1);

    float acc[NT][4];
    #pragma unroll
    for (int t = 0; t < NT; t++) {
        int j0 = wc*WN + t*8 + tig*2;
        acc[t][0] = bias[j0];   acc[t][1] = bias[j0+1];
        acc[t][2] = bias[j0];   acc[t][3] = bias[j0+1];
    }

    for (int kt = 0; kt < KT; ++kt) {
        if (kt + 1 < KT) CP_WAIT1(); else CP_WAIT0();
        __syncthreads();
        if (kt + 2 < KT) issue(kt + 2);
        const float* sA = smem + (kt % 3)*STGSZ;
        const float* sB = sA + ASZ;
        #pragma unroll
        for (int kk = 0; kk < 4; kk++) {
            uint32_t a0 = __float_as_uint(sA[(wr*16 + gid    )*SA + kk*8 + tig    ]);
            uint32_t a1 = __float_as_uint(sA[(wr*16 + gid + 8)*SA + kk*8 + tig    ]);
            uint32_t a2 = __float_as_uint(sA[(wr*16 + gid    )*SA + kk*8 + tig + 4]);
            uint32_t a3 = __float_as_uint(sA[(wr*16 + gid + 8)*SA + kk*8 + tig + 4]);
            #pragma unroll
            for (int t = 0; t < NT; t++) {
                int n0 = wc*WN + t*8;
                uint32_t b0 = __float_as_uint(sB[(kk*8 + tig    )*BS + n0 + gid]);
                uint32_t b1 = __float_as_uint(sB[(kk*8 + tig + 4)*BS + n0 + gid]);
                asm volatile(
                    "mma.sync.aligned.m16n8k8.row.col.f32.tf32.tf32.f32 "
                    "{%0,%1,%2,%3}, {%4,%5,%6,%7}, {%8,%9}, {%0,%1,%2,%3};"
                    : "+f"(acc[t][0]), "+f"(acc[t][1]), "+f"(acc[t][2]), "+f"(acc[t][3])
                    : "r"(a0), "r"(a1), "r"(a2), "r"(a3), "r"(b0), "r"(b1));
            }
        }
    }

    float* sC = smem;                   // [64][BS], pipeline dead
    __syncthreads();
    #pragma unroll
    for (int t = 0; t < NT; t++) {
        int n0 = wc*WN + t*8 + tig*2;
        int r0 = wr*16 + gid;
        sC[ r0     *BS + n0    ] = acc[t][0];
        sC[ r0     *BS + n0 + 1] = acc[t][1];
        sC[(r0 + 8)*BS + n0    ] = acc[t][2];
        sC[(r0 + 8)*BS + n0 + 1] = acc[t][3];
    }
    __syncthreads();

    #pragma unroll
    for (int rr = 0; rr < 4; rr++) {
        int row = warp*4 + rr;
        int grow = rowBase + row;
        #pragma unroll
        for (int j = 0; j < CT; j++) {
            int col = lane + 32*j;
            C[(size_t)grow*N + col] = sC[row*BS + col];
        }
    }
}

// ---------------- fused fc1(gelu+LN)+fc2(+residual) ----------------
__global__ __launch_bounds__(512)
void gemm_fc12(const float* __restrict__ A,      // g_hx [NTOK, 1280]
               const float* __restrict__ W1,     // [1280, 256]
               const float* __restrict__ b1,
               const float* __restrict__ W2,     // [256, 256]
               const float* __restrict__ b2,
               const float* __restrict__ token,
               const float* __restrict__ lnhg, const float* __restrict__ lnhb,
               float* __restrict__ out)
{
    constexpr int N = 256, K1 = HXS, K2 = 256;
    constexpr int KT1 = K1/32, KT2 = K2/32;
    constexpr int SA = 36, BS = N + 4;
    constexpr int ASZ = 64*SA, BSZ = 32*BS, STG1 = ASZ + BSZ;
    constexpr int SCSZ = 64*BS;                    // 16640 floats
    constexpr int OFF2 = SCSZ;                     // phase-B stage area offset
    constexpr int NT = 8, CT = N/32;
    extern __shared__ float smem[];
    const int tid = threadIdx.x, lane = tid & 31, warp = tid >> 5;
    const int wr = warp >> 2, wc = warp & 3;
    const int gid = lane >> 2, tig = lane & 3;
    const int rowBase = blockIdx.x*64;
    const int ar = tid >> 3, ac4 = tid & 7;

    auto issueA = [&](int kt) {
        float* dA = smem + (kt % 3)*STG1;
        float* dB = dA + ASZ;
        CP_ASYNC16(sptr(&dA[ar*SA + ac4*4]),
                   &A[(size_t)(rowBase + ar)*K1 + kt*32 + ac4*4]);
        #pragma unroll
        for (int jj = 0; jj < 4; jj++) {
            int idx = tid + 512*jj;
            int r = idx >> 6, c4 = idx & 63;
            CP_ASYNC16(sptr(&dB[r*BS + c4*4]),
                       &W1[(size_t)(kt*32 + r)*N + c4*4]);
        }
        CP_COMMIT();
    };
    auto issueB = [&](int kt) {
        float* dB = smem + OFF2 + (kt % 3)*BSZ;
        #pragma unroll
        for (int jj = 0; jj < 4; jj++) {
            int idx = tid + 512*jj;
            int r = idx >> 6, c4 = idx & 63;
            CP_ASYNC16(sptr(&dB[r*BS + c4*4]),
                       &W2[(size_t)(kt*32 + r)*N + c4*4]);
        }
        CP_COMMIT();
    };

    issueA(0);
    issueA(1);

    float acc[NT][4];
    #pragma unroll
    for (int t = 0; t < NT; t++) {
        int j0 = wc*64 + t*8 + tig*2;
        acc[t][0] = b1[j0];   acc[t][1] = b1[j0+1];
        acc[t][2] = b1[j0];   acc[t][3] = b1[j0+1];
    }

    for (int kt = 0; kt < KT1; ++kt) {
        if (kt + 1 < KT1) CP_WAIT1(); else CP_WAIT0();
        __syncthreads();
        if (kt + 2 < KT1) issueA(kt + 2);
        const float* sA = smem + (kt % 3)*STG1;
        const float* sB = sA + ASZ;
        #pragma unroll
        for (int kk = 0; kk < 4; kk++) {
            uint32_t a0 = __float_as_uint(sA[(wr*16 + gid    )*SA + kk*8 + tig    ]);
            uint32_t a1 = __float_as_uint(sA[(wr*16 + gid + 8)*SA + kk*8 + tig    ]);
            uint32_t a2 = __float_as_uint(sA[(wr*16 + gid    )*SA + kk*8 + tig + 4]);
            uint32_t a3 = __float_as_uint(sA[(wr*16 + gid + 8)*SA + kk*8 + tig + 4]);
            #pragma unroll
            for (int t = 0; t < NT; t++) {
                int n0 = wc*64 + t*8;
                uint32_t b0 = __float_as_uint(sB[(kk*8 + tig    )*BS + n0 + gid]);
                uint32_t b1v = __float_as_uint(sB[(kk*8 + tig + 4)*BS + n0 + gid]);
                asm volatile(
                    "mma.sync.aligned.m16n8k8.row.col.f32.tf32.tf32.f32 "
                    "{%0,%1,%2,%3}, {%4,%5,%6,%7}, {%8,%9}, {%0,%1,%2,%3};"
                    : "+f"(acc[t][0]), "+f"(acc[t][1]), "+f"(acc[t][2]), "+f"(acc[t][3])
                    : "r"(a0), "r"(a1), "r"(a2), "r"(a3), "r"(b0), "r"(b1v));
            }
        }
    }

    // all phase-A cp.async retired (WAIT0 at last iter). Start phase-B prefetch now
    // (targets smem[OFF2..), disjoint from sC=[0..SCSZ)).
    __syncthreads();
    issueB(0);
    issueB(1);

    // epilogue 1: stage acc -> sC, gelu+LN in place
    float* sC = smem;                   // [64][BS]
    #pragma unroll
    for (int t = 0; t < NT; t++) {
        int n0 = wc*64 + t*8 + tig*2;
        int r0 = wr*16 + gid;
        sC[ r0     *BS + n0    ] = acc[t][0];
        sC[ r0     *BS + n0 + 1] = acc[t][1];
        sC[(r0 + 8)*BS + n0    ] = acc[t][2];
        sC[(r0 + 8)*BS + n0 + 1] = acc[t][3];
    }
    __syncthreads();
    #pragma unroll
    for (int rr = 0; rr < 4; rr++) {
        int row = warp*4 + rr;
        float v[CT]; float s = 0.f, s2 = 0.f;
        #pragma unroll
        for (int j = 0; j < CT; j++) {
            float x = sC[row*BS + lane + 32*j];
            x = 0.5f*x*(1.f + erff(x*0.70710678118654752f));
            v[j] = x; s += x; s2 += x*x;
        }
        #pragma unroll
        for (int o = 16; o; o >>= 1) {
            s  += __shfl_xor_sync(0xffffffffu, s,  o);
            s2 += __shfl_xor_sync(0xffffffffu, s2, o);
        }
        float mean = s*(1.f/256.f);
        float rstd = rsqrtf(s2*(1.f/256.f) - mean*mean + 1e-5f);
        #pragma unroll
        for (int j = 0; j < CT; j++) {
            int col = lane + 32*j;
            sC[row*BS + col] = (v[j]-mean)*rstd*lnhg[col] + lnhb[col];
        }
    }
    __syncthreads();

    // phase B: hmid(sC) @ W2
    float acc2[NT][4];
    #pragma unroll
    for (int t = 0; t < NT; t++) {
        int j0 = wc*64 + t*8 + tig*2;
        acc2[t][0] = b2[j0];   acc2[t][1] = b2[j0+1];
        acc2[t][2] = b2[j0];   acc2[t][3] = b2[j0+1];
    }
    for (int kt = 0; kt < KT2; ++kt) {
        if (kt + 1 < KT2) CP_WAIT1(); else CP_WAIT0();
        __syncthreads();
        if (kt + 2 < KT2) issueB(kt + 2);
        const float* sB = smem + OFF2 + (kt % 3)*BSZ;
        #pragma unroll
        for (int kk = 0; kk < 4; kk++) {
            int kc = kt*32 + kk*8;
            uint32_t a0 = __float_as_uint(sC[(wr*16 + gid    )*BS + kc + tig    ]);
            uint32_t a1 = __float_as_uint(sC[(wr*16 + gid + 8)*BS + kc + tig    ]);
            uint32_t a2 = __float_as_uint(sC[(wr*16 + gid    )*BS + kc + tig + 4]);
            uint32_t a3 = __float_as_uint(sC[(wr*16 + gid + 8)*BS + kc + tig + 4]);
            #pragma unroll
            for (int t = 0; t < NT; t++) {
                int n0 = wc*64 + t*8;
                uint32_t b0 = __float_as_uint(sB[(kk*8 + tig    )*BS + n0 + gid]);
                uint32_t b1v = __float_as_uint(sB[(kk*8 + tig + 4)*BS + n0 + gid]);
                asm volatile(
                    "mma.sync.aligned.m16n8k8.row.col.f32.tf32.tf32.f32 "
                    "{%0,%1,%2,%3}, {%4,%5,%6,%7}, {%8,%9}, {%0,%1,%2,%3};"
                    : "+f"(acc2[t][0]), "+f"(acc2[t][1]), "+f"(acc2[t][2]), "+f"(acc2[t][3])
                    : "r"(a0), "r"(a1), "r"(a2), "r"(a3), "r"(b0), "r"(b1v));
            }
        }
    }

    // epilogue 2: stage acc2 -> phase-B stage area, + residual, store
    float* sO = smem + OFF2;            // [64][BS]
    __syncthreads();
    #pragma unroll
    for (int t = 0; t < NT; t++) {
        int n0 = wc*64 + t*8 + tig*2;
        int r0 = wr*16 + gid;
        sO[ r0     *BS + n0    ] = acc2[t][0];
        sO[ r0     *BS + n0 + 1] = acc2[t][1];
        sO[(r0 + 8)*BS + n0    ] = acc2[t][2];
        sO[(r0 + 8)*BS + n0 + 1] = acc2[t][3];
    }
    __syncthreads();
    #pragma unroll
    for (int rr = 0; rr < 4; rr++) {
        int row = warp*4 + rr;
        int grow = rowBase + row;
        #pragma unroll
        for (int j = 0; j < CT; j++) {
            int col = lane + 32*j;
            out[(size_t)grow*256 + col] = sO[row*BS + col] + token[(size_t)grow*256 + col];
        }
    }
}

// ---------------- fused per-token attention (unchanged from R8) ----------------
struct AttnGroup {
    float edge[32*ES];
    float logit[8*32];
    float attnT[32*8];
    float arT[32*8];
    float mean[32];
    float rstd[32];
    float s1[8];
    float qd[8];
    int   nbr[32];
};
struct AttnSmem {
    float wg[8*132];
    float swg[8];
    float beff2[8];
    float wfa[8];
    float lng[128];
    float lnb[128];
    AttnGroup grp[4];
};

#define GBAR(id) asm volatile("bar.sync %0, 128;" :: "r"(id) : "memory")

__global__ __launch_bounds__(512, 2)
void attn_kernel(const float* __restrict__ edge_feats,
                 const float* __restrict__ geo_feats,
                 const int*   __restrict__ nbr_idx,
                 const int*   __restrict__ masks,
                 const float* __restrict__ ln_e_g,
                 const float* __restrict__ ln_e_b,
                 const float* __restrict__ W_fa,
                 const float* __restrict__ b_fa,
                 float* __restrict__ out_geo)
{
    extern __shared__ char smraw[];
    AttnSmem& sm = *reinterpret_cast<AttnSmem*>(smraw);
    const int tid = threadIdx.x;

    for (int i = tid; i < 8*132; i += 512) sm.wg[i] = g_wg[i];
    if (tid < 128) { sm.lng[tid] = ln_e_g[tid]; sm.lnb[tid] = ln_e_b[tid]; }
    if (tid >= 128 && tid < 136) {
        int h = tid - 128;
        sm.swg[h] = g_swg[h]; sm.beff2[h] = g_beff2[h]; sm.wfa[h] = W_fa[h];
    }
    const float bfa = b_fa[0];
    __syncthreads();

    const int g     = tid >> 7;
    const int gtid  = tid & 127;
    const int glane = gtid & 31;
    const int gwarp = gtid >> 5;
    const int bid   = 1 + g;
    AttnGroup& G = sm.grp[g];

    for (int tok = 0; tok < 2; ++tok) {
        const int n = blockIdx.x*8 + g*2 + tok;

        {
            const float4* ep4 = (const float4*)(edge_feats + (size_t)n*4096);
            #pragma unroll
            for (int jj = 0; jj < 8; jj++) {
                int idx = gtid + 128*jj;
                int m = gwarp + 4*jj;
                float4 v = ep4[idx];
                *(float4*)&G.edge[m*ES + glane*4] = v;
                float s  = v.x + v.y + v.z + v.w;
                float s2 = v.x*v.x + v.y*v.y + v.z*v.z + v.w*v.w;
                #pragma unroll
                for (int o = 16; o; o >>= 1) {
                    s  += __shfl_xor_sync(0xffffffffu, s,  o);
                    s2 += __shfl_xor_sync(0xffffffffu, s2, o);
                }
                if (glane == 0) {
                    float mean = s*(1.f/128.f);
                    float rstd = rsqrtf(s2*(1.f/128.f) - mean*mean + 1e-5f);
                    G.mean[m] = mean; G.rstd[m] = rstd;
                }
            }
            if (gtid < 32) G.nbr[gtid] = nbr_idx[n*32 + gtid];
            if (gtid >= 32 && gtid < 40) G.qd[gtid-32] = g_qkv[(size_t)n*QS + 256 + gtid-32];
        }
        GBAR(bid);

        {
            int m0 = gtid >> 3, h = gtid & 7;
            int nb0 = G.nbr[m0], nb1 = G.nbr[m0 + 16];
            float kd0 = g_qkv[(size_t)nb0*QS + 264 + h];
            float kd1 = g_qkv[(size_t)nb1*QS + 264 + h];
            int mk0 = masks[n*32 + m0];
            int mk1 = masks[n*32 + m0 + 16];
            float d0 = 0.f, d1 = 0.f;
            const float4* e0 = (const float4*)&G.edge[m0*ES];
            const float4* e1 = (const float4*)&G.edge[(m0+16)*ES];
            const float4* wt = (const float4*)&sm.wg[h*132];
            #pragma unroll 8
            for (int c4 = 0; c4 < 32; c4++) {
                float4 w = wt[c4], x = e0[c4], y = e1[c4];
                d0 += x.x*w.x + x.y*w.y + x.z*w.z + x.w*w.w;
                d1 += y.x*w.x + y.y*w.y + y.z*w.z + y.w*w.w;
            }
            float base = G.qd[h] + sm.beff2[h];
            float sw = sm.swg[h];
            float a0 = base + kd0 + G.rstd[m0]   *(d0 - G.mean[m0]   *sw);
            float a1 = base + kd1 + G.rstd[m0+16]*(d1 - G.mean[m0+16]*sw);
            if (!mk0) a0 = -1e9f;
            if (!mk1) a1 = -1e9f;
            G.logit[h*32 + m0]      = a0;
            G.logit[h*32 + m0 + 16] = a1;
        }
        GBAR(bid);

        {
            #pragma unroll
            for (int i = 0; i < 2; i++) {
                int h = gwarp + 4*i;
                float l = G.logit[h*32 + glane];
                float mx = l;
                #pragma unroll
                for (int o = 16; o; o >>= 1) mx = fmaxf(mx, __shfl_xor_sync(0xffffffffu, mx, o));
                float e = __expf(l - mx);
                float ss = e;
                #pragma unroll
                for (int o = 16; o; o >>= 1) ss += __shfl_xor_sync(0xffffffffu, ss, o);
                float a = e/ss;
                float ar = a*G.rstd[glane];
                float s1p = ar*G.mean[glane];
                #pragma unroll
                for (int o = 16; o; o >>= 1) s1p += __shfl_xor_sync(0xffffffffu, s1p, o);
                G.attnT[glane*8 + h] = a;
                G.arT[glane*8 + h]   = ar;
                if (glane == 0) G.s1[h] = s1p;
            }
        }
        GBAR(bid);

        {
            float acc0 = 0.f, acc1 = 0.f;
            int c0 = gtid, c1 = gtid + 128;
            int h0 = c0 >> 5, h1 = c1 >> 5;
            #pragma unroll
            for (int m = 0; m < 32; m++) {
                const float* vrow = &g_qkv[(size_t)G.nbr[m]*QS];
                acc0 += G.attnT[m*8 + h0]*vrow[c0];
                acc1 += G.attnT[m*8 + h1]*vrow[c1];
            }
            g_hx[(size_t)n*HXS + c0] = acc0;
            g_hx[(size_t)n*HXS + c1] = acc1;

            float ewa[8];
            #pragma unroll
            for (int h = 0; h < 8; h++) ewa[h] = 0.f;
            const float4* ar4 = (const float4*)G.arT;
            #pragma unroll
            for (int m = 0; m < 32; m++) {
                float e = G.edge[m*ES + gtid];
                float4 r0 = ar4[m*2], r1 = ar4[m*2 + 1];
                ewa[0] += r0.x*e; ewa[1] += r0.y*e; ewa[2] += r0.z*e; ewa[3] += r0.w*e;
                ewa[4] += r1.x*e; ewa[5] += r1.y*e; ewa[6] += r1.z*e; ewa[7] += r1.w*e;
            }
            float gl = sm.lng[gtid], bl = sm.lnb[gtid];
            #pragma unroll
            for (int h = 0; h < 8; h++)
                g_hx[(size_t)n*HXS + 256 + h*128 + gtid] = gl*(ewa[h] - G.s1[h]) + bl;
        }
        if (gwarp == 3) {
            int m = glane;
            float aw = 0.f;
            #pragma unroll
            for (int h = 0; h < 8; h++) aw += G.attnT[m*8 + h]*sm.wfa[h];
            int nb = G.nbr[m];
            float p0 = aw*g_proj[nb*3 + 0];
            float p1 = aw*g_proj[nb*3 + 1];
            float p2 = aw*g_proj[nb*3 + 2];
            #pragma unroll
            for (int o = 16; o; o >>= 1) {
                p0 += __shfl_xor_sync(0xffffffffu, p0, o);
                p1 += __shfl_xor_sync(0xffffffffu, p1, o);
                p2 += __shfl_xor_sync(0xffffffffu, p2, o);
            }
            if (glane == 0) {
                int b = n >> 9;
                float ps[3] = {p0, p1, p2};
                float sd[3];
                #pragma unroll
                for (int j = 0; j < 3; j++)
                    sd[j] = 0.5f*(siluf(ps[j] + bfa) - siluf(-ps[j] + bfa));
                float gt = g_gate[n];
                #pragma unroll
                for (int i = 0; i < 3; i++) {
                    float gc = g_center[b*3 + i]
                             + sd[0]*g_V[b*9 + i*3 + 0]
                             + sd[1]*g_V[b*9 + i*3 + 1]
                             + sd[2]*g_V[b*9 + i*3 + 2];
                    out_geo[n*3 + i] = gc*gt + geo_feats[n*3 + i]*(1.f - gt);
                }
            }
        }
        GBAR(bid);
    }
}

// ---------------- launcher ----------------
extern "C" void kernel_launch(void* const* d_in, const int* in_sizes, int n_in,
                              void* d_out, int out_size)
{
    const float* token    = (const float*)d_in[0];
    const float* geo      = (const float*)d_in[1];
    const float* edge     = (const float*)d_in[2];
    const int*   nbr      = (const int*)d_in[3];
    const int*   mask     = (const int*)d_in[5];
    const float* ln_qkv_g = (const float*)d_in[6];
    const float* ln_qkv_b = (const float*)d_in[7];
    const float* W_qkv    = (const float*)d_in[8];
    const float* b_qkv    = (const float*)d_in[9];
    const float* ln_e_g   = (const float*)d_in[10];
    const float* ln_e_b   = (const float*)d_in[11];
    const float* W_qkv_e  = (const float*)d_in[12];
    const float* b_qkv_e  = (const float*)d_in[13];
    const float* w_attn   = (const float*)d_in[14];
    const float* w_edge   = (const float*)d_in[15];
    const float* W_gate   = (const float*)d_in[16];
    const float* b_gate   = (const float*)d_in[17];
    const float* W_fc1    = (const float*)d_in[18];
    const float* b_fc1    = (const float*)d_in[19];
    const float* ln_h_g   = (const float*)d_in[20];
    const float* ln_h_b   = (const float*)d_in[21];
    const float* W_fc2    = (const float*)d_in[22];
    const float* b_fc2    = (const float*)d_in[23];
    const float* W_fa     = (const float*)d_in[24];
    const float* b_fa     = (const float*)d_in[25];
    float* out = (float*)d_out;

    void* p;
    cudaGetSymbolAddress(&p, g_lnx);   float* p_lnx   = (float*)p;
    cudaGetSymbolAddress(&p, g_qkv);   float* p_qkv   = (float*)p;
    cudaGetSymbolAddress(&p, g_hx);    float* p_hx    = (float*)p;
    cudaGetSymbolAddress(&p, g_Wcomb); float* p_Wcomb = (float*)p;
    cudaGetSymbolAddress(&p, g_bcomb); float* p_bcomb = (float*)p;
    cudaGetSymbolAddress(&p, g_W1);    float* p_W1    = (float*)p;
    cudaGetSymbolAddress(&p, g_b1);    float* p_b1    = (float*)p;

    prep_kernel<<<64, 256>>>(W_qkv, b_qkv, w_attn, W_qkv_e, b_qkv_e, w_edge,
                             W_fc1, b_fc1, ln_e_g, ln_e_b);
    geom_kernel<<<16, 256>>>(geo);
    ln_gate_kernel<<<1024, 256>>>(token, ln_qkv_g, ln_qkv_b, W_gate, b_gate);

    // qkv: lnx[8192,256] @ Wcomb[256,288]
    {
        constexpr int SM = 3*(64*36 + 32*292)*sizeof(float);
        cudaFuncSetAttribute((const void*)gemm_cp<256, QS, 0>,
                             cudaFuncAttributeMaxDynamicSharedMemorySize, SM);
        gemm_cp<256, QS, 0><<<128, 512, SM>>>(p_lnx, p_Wcomb, p_bcomb, p_qkv);
    }

    cudaFuncSetAttribute(attn_kernel, cudaFuncAttributeMaxDynamicSharedMemorySize,
                         (int)sizeof(AttnSmem));
    attn_kernel<<<1024, 512, sizeof(AttnSmem)>>>(
        edge, geo, nbr, mask, ln_e_g, ln_e_b, W_fa, b_fa,
        out + (size_t)NTOK*256);

    // fused fc1+fc2
    {
        constexpr int SM = (64*260 + 3*32*260)*sizeof(float);   // 166.4 KB
        cudaFuncSetAttribute((const void*)gemm_fc12,
                             cudaFuncAttributeMaxDynamicSharedMemorySize, SM);
        gemm_fc12<<<128, 512, SM>>>(p_hx, p_W1, p_b1, W_fc2, b_fc2,
                                    token, ln_h_g, ln_h_b, out);
    }
}

// round 10
// speedup vs baseline: 1.1714x; 1.0976x over previous
#include <cuda_runtime.h>
#include <math.h>
#include <stdint.h>

#define NTOK 8192
#define QS 288            // qkv row stride: 256 v | 8 qdot | 8 kdot | pad
#define ES 132            // edge smem row stride (floats)
#define HXS 1280          // hx row stride: 256 scalar ctx | 1024 ew

// ---------------- device scratch ----------------
__device__ float g_qkv[NTOK*QS];
__device__ float g_hx[NTOK*HXS];
__device__ float g_gate[NTOK];
__device__ float g_proj[NTOK*3];
__device__ float g_center[16*3];
__device__ float g_V[16*9];
__device__ float g_Wcomb[256*QS];
__device__ float g_bcomb[QS];
__device__ float g_wg[8*132];       // [h][c]: lng[c]*weff[c][h], padded
__device__ float g_swg[8];
__device__ float g_beff2[8];
__device__ float g_W1[HXS*256];     // folded fc1 weight: [1280, 256]
__device__ float g_b1[256];         // folded fc1 bias

__device__ __forceinline__ float siluf(float x){ return x/(1.f+__expf(-x)); }

#define CP_ASYNC16(dst, src) \
    asm volatile("cp.async.ca.shared.global [%0], [%1], 16;\n" :: "r"(dst), "l"(src))
#define CP_COMMIT() asm volatile("cp.async.commit_group;\n" ::: "memory")
#define CP_WAIT2()  asm volatile("cp.async.wait_group 2;\n" ::: "memory")
#define CP_WAIT1()  asm volatile("cp.async.wait_group 1;\n" ::: "memory")
#define CP_WAIT0()  asm volatile("cp.async.wait_group 0;\n" ::: "memory")

__device__ __forceinline__ uint32_t sptr(const void* p){
    return (uint32_t)__cvta_generic_to_shared(p);
}

// ---------------- prep: fold effective weights ----------------
__global__ void prep_kernel(const float* __restrict__ W_qkv, const float* __restrict__ b_qkv,
                            const float* __restrict__ w_attn,
                            const float* __restrict__ W_qkv_e, const float* __restrict__ b_qkv_e,
                            const float* __restrict__ w_edge,
                            const float* __restrict__ W_fc1, const float* __restrict__ b_fc1,
                            const float* __restrict__ ln_e_g, const float* __restrict__ ln_e_b)
{
    int gid = blockIdx.x*blockDim.x + threadIdx.x;
    int gstride = gridDim.x*blockDim.x;
    for (int idx = gid; idx < 256*QS; idx += gstride) {
        int c = idx / QS, j = idx - c*QS;
        float w = 0.f;
        if (j < 256) {
            w = W_qkv[c*768 + 512 + j];
        } else if (j < 264) {
            int h = j - 256; float s = 0.f;
            #pragma unroll
            for (int d = 0; d < 32; d++) s += W_qkv[c*768 + h*32 + d]*w_attn[d];
            w = s;
        } else if (j < 272) {
            int h = j - 264; float s = 0.f;
            #pragma unroll
            for (int d = 0; d < 32; d++) s += W_qkv[c*768 + 256 + h*32 + d]*w_attn[d];
            w = s;
        }
        g_Wcomb[idx] = w;
    }
    for (int idx = gid; idx < HXS*256; idx += gstride) {
        int j = idx >> 8, o = idx & 255;
        float w;
        if (j < 256) {
            w = W_fc1[j*256 + o];
        } else {
            int hc = j - 256, h = hc >> 7, c = hc & 127;
            float s = 0.f;
            #pragma unroll
            for (int jp = 0; jp < 16; jp++)
                s += W_qkv_e[c*256 + 128 + h*16 + jp]*W_fc1[(256 + h*16 + jp)*256 + o];
            w = s;
        }
        g_W1[idx] = w;
    }
    if (blockIdx.x == 0) {
        for (int j = threadIdx.x; j < QS; j += blockDim.x) {
            float bv = 0.f;
            if (j < 256) bv = b_qkv[512 + j];
            else if (j < 264) { int h = j-256; for (int d=0; d<32; d++) bv += b_qkv[h*32+d]*w_attn[d]; }
            else if (j < 272) { int h = j-264; for (int d=0; d<32; d++) bv += b_qkv[256 + h*32+d]*w_attn[d]; }
            g_bcomb[j] = bv;
        }
    }
    if (blockIdx.x == 1) {
        __shared__ float sweff[128*8];
        for (int idx = threadIdx.x; idx < 128*8; idx += blockDim.x) {
            int c = idx >> 3, h = idx & 7; float s = 0.f;
            #pragma unroll
            for (int e = 0; e < 16; e++) s += W_qkv_e[c*256 + h*16 + e]*w_edge[e];
            sweff[idx] = s;
            g_wg[h*132 + c] = ln_e_g[c]*s;
        }
        __syncthreads();
        if (threadIdx.x < 8) {
            int h = threadIdx.x;
            float sw = 0.f, b2 = 0.f;
            for (int c = 0; c < 128; c++) {
                float we = sweff[c*8 + h];
                sw += ln_e_g[c]*we;
                b2 += ln_e_b[c]*we;
            }
            for (int e = 0; e < 16; e++) b2 += b_qkv_e[h*16 + e]*w_edge[e];
            g_swg[h] = sw; g_beff2[h] = b2;
        }
    }
    if (blockIdx.x == 2 && threadIdx.x < 256) {
        int o = threadIdx.x;
        float s = b_fc1[o];
        for (int j = 0; j < 128; j++)
            s += b_qkv_e[128 + j]*W_fc1[(256 + j)*256 + o];
        g_b1[o] = s;
    }
}

// ---------------- per-graph geometry (fp32 Jacobi) ----------------
__device__ void jacobi3f(float a00,float a01,float a02,float a11,float a12,float a22,
                         float V[3][3])
{
    float A[3][3] = {{a00,a01,a02},{a01,a11,a12},{a02,a12,a22}};
    V[0][0]=1; V[0][1]=0; V[0][2]=0;
    V[1][0]=0; V[1][1]=1; V[1][2]=0;
    V[2][0]=0; V[2][1]=0; V[2][2]=1;
    float tr = fabsf(a00)+fabsf(a11)+fabsf(a22);
    for (int it = 0; it < 40; ++it) {
        int p = 0, q = 1; float mx = fabsf(A[0][1]);
        if (fabsf(A[0][2]) > mx) { mx = fabsf(A[0][2]); p = 0; q = 2; }
        if (fabsf(A[1][2]) > mx) { mx = fabsf(A[1][2]); p = 1; q = 2; }
        if (mx <= 1e-8f*tr) break;
        float apq = A[p][q];
        float theta = (A[q][q]-A[p][p])/(2.0f*apq);
        float t = 1.0f/(fabsf(theta)+sqrtf(theta*theta+1.0f));
        if (theta < 0) t = -t;
        float c = rsqrtf(t*t+1.0f), s = t*c;
        for (int k = 0; k < 3; k++) { float akp=A[k][p], akq=A[k][q]; A[k][p]=c*akp-s*akq; A[k][q]=s*akp+c*akq; }
        for (int k = 0; k < 3; k++) { float apk=A[p][k], aqk=A[q][k]; A[p][k]=c*apk-s*aqk; A[q][k]=s*apk+c*aqk; }
        for (int k = 0; k < 3; k++) { float vkp=V[k][p], vkq=V[k][q]; V[k][p]=c*vkp-s*vkq; V[k][q]=s*vkp+c*vkq; }
    }
}

__global__ void geom_kernel(const float* __restrict__ geo)
{
    __shared__ double sred[8][9];
    __shared__ double sCd[3];
    __shared__ float sV[9], sC[3];
    int b = blockIdx.x, tid = threadIdx.x, lane = tid & 31, warp = tid >> 5;
    const float* G = geo + (size_t)b*512*3;

    {
        double s[3] = {0,0,0};
        for (int p = tid; p < 512; p += 256) { s[0] += G[p*3]; s[1] += G[p*3+1]; s[2] += G[p*3+2]; }
        #pragma unroll
        for (int k = 0; k < 3; k++)
            #pragma unroll
            for (int o = 16; o; o >>= 1) s[k] += __shfl_xor_sync(0xffffffffu, s[k], o);
        if (lane == 0) { sred[warp][0]=s[0]; sred[warp][1]=s[1]; sred[warp][2]=s[2]; }
    }
    __syncthreads();
    if (tid == 0) {
        for (int k = 0; k < 3; k++) {
            double t = 0; for (int w = 0; w < 8; w++) t += sred[w][k];
            sCd[k] = t/512.0;
        }
    }
    __syncthreads();
    double c0 = sCd[0], c1 = sCd[1], c2 = sCd[2];

    {
        double m[6] = {0,0,0,0,0,0};
        for (int p = tid; p < 512; p += 256) {
            double dx = G[p*3]-c0, dy = G[p*3+1]-c1, dz = G[p*3+2]-c2;
            m[0] += dx*dx; m[1] += dx*dy; m[2] += dx*dz;
            m[3] += dy*dy; m[4] += dy*dz; m[5] += dz*dz;
        }
        #pragma unroll
        for (int k = 0; k < 6; k++)
            #pragma unroll
            for (int o = 16; o; o >>= 1) m[k] += __shfl_xor_sync(0xffffffffu, m[k], o);
        if (lane == 0) for (int k = 0; k < 6; k++) sred[warp][k] = m[k];
    }
    __syncthreads();
    if (tid == 0) {
        double m[6];
        for (int k = 0; k < 6; k++) { double t=0; for (int w=0; w<8; w++) t += sred[w][k]; m[k]=t; }
        float V[3][3];
        jacobi3f((float)m[0],(float)m[1],(float)m[2],(float)m[3],(float)m[4],(float)m[5], V);
        for (int i = 0; i < 3; i++)
            for (int j = 0; j < 3; j++) { sV[i*3+j] = V[i][j]; g_V[b*9+i*3+j] = V[i][j]; }
        sC[0]=(float)c0; sC[1]=(float)c1; sC[2]=(float)c2;
        g_center[b*3+0]=(float)c0; g_center[b*3+1]=(float)c1; g_center[b*3+2]=(float)c2;
    }
    __syncthreads();

    for (int p = tid; p < 512; p += 256) {
        int t = b*512 + p;
        float dx = G[p*3]-sC[0], dy = G[p*3+1]-sC[1], dz = G[p*3+2]-sC[2];
        for (int d = 0; d < 3; d++)
            g_proj[t*3+d] = dx*sV[0*3+d] + dy*sV[1*3+d] + dz*sV[2*3+d];
    }
}

// ---------------- qkv GEMM: BM=64, A resident + fused LN/gate, B 3-stage cp.async ----------------
__global__ __launch_bounds__(512)
void gemm_qkv_f(const float* __restrict__ X,      // raw token embs [NTOK,256]
                const float* __restrict__ Bw,     // Wcomb [256, 288]
                const float* __restrict__ bias,
                const float* __restrict__ Wg, const float* __restrict__ bg,
                const float* __restrict__ lng, const float* __restrict__ lnb,
                float* __restrict__ C)
{
    constexpr int K = 256, N = QS;
    constexpr int AS = 260, BS = 292;
    constexpr int ASZ = 64*AS, BSZ = 32*BS;
    constexpr int KT = K/32, WN = N/4, NT = WN/8, CT = N/32;
    extern __shared__ float smem[];
    float* sA = smem;                 // [64][260] resident
    float* sBst = smem + ASZ;         // 3 stages of [32][292]
    const int tid = threadIdx.x, lane = tid & 31, warp = tid >> 5;
    const int wr = warp >> 2, wc = warp & 3;
    const int gid = lane >> 2, tig = lane & 3;
    const int rowBase = blockIdx.x*64;

    auto issueB = [&](int kt) {
        float* dB = sBst + (kt % 3)*BSZ;
        #pragma unroll
        for (int jj = 0; jj < 5; jj++) {
            int idx = tid + 512*jj;
            if (idx < 32*72) {
                int r = idx/72, c4 = idx - r*72;
                CP_ASYNC16(sptr(&dB[r*BS + c4*4]),
                           &Bw[(size_t)(kt*32 + r)*N + c4*4]);
            }
        }
        CP_COMMIT();
    };

    // A load (group 0), then B stage 0/1 (groups 1/2)
    {
        #pragma unroll
        for (int jj = 0; jj < 8; jj++) {
            int idx = tid + 512*jj;          // 4096 float4
            int r = idx >> 6, c4 = idx & 63;
            CP_ASYNC16(sptr(&sA[r*AS + c4*4]),
                       &X[(size_t)(rowBase + r)*K + c4*4]);
        }
        CP_COMMIT();
    }
    issueB(0);
    issueB(1);

    // wait for A (2 groups may remain pending)
    CP_WAIT2();
    __syncthreads();

    // LN + gate on resident A: 16 warps x 4 rows
    #pragma unroll
    for (int rr = 0; rr < 4; rr++) {
        int row = warp*4 + rr;
        float v[8]; float s = 0.f, s2 = 0.f, gd = 0.f;
        #pragma unroll
        for (int j = 0; j < 8; j++) {
            int c = lane + 32*j;
            float t = sA[row*AS + c];
            v[j] = t; s += t; s2 += t*t; gd += t*Wg[c];
        }
        #pragma unroll
        for (int o = 16; o; o >>= 1) {
            s  += __shfl_xor_sync(0xffffffffu, s,  o);
            s2 += __shfl_xor_sync(0xffffffffu, s2, o);
            gd += __shfl_xor_sync(0xffffffffu, gd, o);
        }
        float mean = s*(1.f/256.f);
        float rstd = rsqrtf(s2*(1.f/256.f) - mean*mean + 1e-5f);
        #pragma unroll
        for (int j = 0; j < 8; j++) {
            int c = lane + 32*j;
            sA[row*AS + c] = (v[j]-mean)*rstd*lng[c] + lnb[c];
        }
        if (lane == 0) g_gate[rowBase + row] = 1.f/(1.f + __expf(-(gd + bg[0])));
    }
    __syncthreads();

    float acc[NT][4];
    #pragma unroll
    for (int t = 0; t < NT; t++) {
        int j0 = wc*WN + t*8 + tig*2;
        acc[t][0] = bias[j0];   acc[t][1] = bias[j0+1];
        acc[t][2] = bias[j0];   acc[t][3] = bias[j0+1];
    }

    for (int kt = 0; kt < KT; ++kt) {
        if (kt + 1 < KT) CP_WAIT1(); else CP_WAIT0();
        __syncthreads();
        if (kt + 2 < KT) issueB(kt + 2);
        const float* sB = sBst + (kt % 3)*BSZ;
        #pragma unroll
        for (int kk = 0; kk < 4; kk++) {
            int kc = kt*32 + kk*8;
            uint32_t a0 = __float_as_uint(sA[(wr*16 + gid    )*AS + kc + tig    ]);
            uint32_t a1 = __float_as_uint(sA[(wr*16 + gid + 8)*AS + kc + tig    ]);
            uint32_t a2 = __float_as_uint(sA[(wr*16 + gid    )*AS + kc + tig + 4]);
            uint32_t a3 = __float_as_uint(sA[(wr*16 + gid + 8)*AS + kc + tig + 4]);
            #pragma unroll
            for (int t = 0; t < NT; t++) {
                int n0 = wc*WN + t*8;
                uint32_t b0 = __float_as_uint(sB[(kk*8 + tig    )*BS + n0 + gid]);
                uint32_t b1 = __float_as_uint(sB[(kk*8 + tig + 4)*BS + n0 + gid]);
                asm volatile(
                    "mma.sync.aligned.m16n8k8.row.col.f32.tf32.tf32.f32 "
                    "{%0,%1,%2,%3}, {%4,%5,%6,%7}, {%8,%9}, {%0,%1,%2,%3};"
                    : "+f"(acc[t][0]), "+f"(acc[t][1]), "+f"(acc[t][2]), "+f"(acc[t][3])
                    : "r"(a0), "r"(a1), "r"(a2), "r"(a3), "r"(b0), "r"(b1));
            }
        }
    }

    // stage C through B-stage region [64][292] (pipeline dead)
    float* sC = sBst;
    __syncthreads();
    #pragma unroll
    for (int t = 0; t < NT; t++) {
        int n0 = wc*WN + t*8 + tig*2;
        int r0 = wr*16 + gid;
        sC[ r0     *BS + n0    ] = acc[t][0];
        sC[ r0     *BS + n0 + 1] = acc[t][1];
        sC[(r0 + 8)*BS + n0    ] = acc[t][2];
        sC[(r0 + 8)*BS + n0 + 1] = acc[t][3];
    }
    __syncthreads();
    #pragma unroll
    for (int rr = 0; rr < 4; rr++) {
        int row = warp*4 + rr;
        int grow = rowBase + row;
        #pragma unroll
        for (int j = 0; j < CT; j++) {
            int col = lane + 32*j;
            C[(size_t)grow*N + col] = sC[row*BS + col];
        }
    }
}

// ---------------- fused fc1(gelu+LN)+fc2(+residual) ----------------
__global__ __launch_bounds__(512)
void gemm_fc12(const float* __restrict__ A,      // g_hx [NTOK, 1280]
               const float* __restrict__ W1,     // [1280, 256]
               const float* __restrict__ b1,
               const float* __restrict__ W2,     // [256, 256]
               const float* __restrict__ b2,
               const float* __restrict__ token,
               const float* __restrict__ lnhg, const float* __restrict__ lnhb,
               float* __restrict__ out)
{
    constexpr int N = 256, K1 = HXS, K2 = 256;
    constexpr int KT1 = K1/32, KT2 = K2/32;
    constexpr int SA = 36, BS = N + 4;
    constexpr int ASZ = 64*SA, BSZ = 32*BS, STG1 = ASZ + BSZ;
    constexpr int SCSZ = 64*BS;
    constexpr int OFF2 = SCSZ;
    constexpr int NT = 8, CT = N/32;
    extern __shared__ float smem[];
    const int tid = threadIdx.x, lane = tid & 31, warp = tid >> 5;
    const int wr = warp >> 2, wc = warp & 3;
    const int gid = lane >> 2, tig = lane & 3;
    const int rowBase = blockIdx.x*64;
    const int ar = tid >> 3, ac4 = tid & 7;

    auto issueA = [&](int kt) {
        float* dA = smem + (kt % 3)*STG1;
        float* dB = dA + ASZ;
        CP_ASYNC16(sptr(&dA[ar*SA + ac4*4]),
                   &A[(size_t)(rowBase + ar)*K1 + kt*32 + ac4*4]);
        #pragma unroll
        for (int jj = 0; jj < 4; jj++) {
            int idx = tid + 512*jj;
            int r = idx >> 6, c4 = idx & 63;
            CP_ASYNC16(sptr(&dB[r*BS + c4*4]),
                       &W1[(size_t)(kt*32 + r)*N + c4*4]);
        }
        CP_COMMIT();
    };
    auto issueB = [&](int kt) {
        float* dB = smem + OFF2 + (kt % 3)*BSZ;
        #pragma unroll
        for (int jj = 0; jj < 4; jj++) {
            int idx = tid + 512*jj;
            int r = idx >> 6, c4 = idx & 63;
            CP_ASYNC16(sptr(&dB[r*BS + c4*4]),
                       &W2[(size_t)(kt*32 + r)*N + c4*4]);
        }
        CP_COMMIT();
    };

    issueA(0);
    issueA(1);

    float acc[NT][4];
    #pragma unroll
    for (int t = 0; t < NT; t++) {
        int j0 = wc*64 + t*8 + tig*2;
        acc[t][0] = b1[j0];   acc[t][1] = b1[j0+1];
        acc[t][2] = b1[j0];   acc[t][3] = b1[j0+1];
    }

    for (int kt = 0; kt < KT1; ++kt) {
        if (kt + 1 < KT1) CP_WAIT1(); else CP_WAIT0();
        __syncthreads();
        if (kt + 2 < KT1) issueA(kt + 2);
        const float* sA = smem + (kt % 3)*STG1;
        const float* sB = sA + ASZ;
        #pragma unroll
        for (int kk = 0; kk < 4; kk++) {
            uint32_t a0 = __float_as_uint(sA[(wr*16 + gid    )*SA + kk*8 + tig    ]);
            uint32_t a1 = __float_as_uint(sA[(wr*16 + gid + 8)*SA + kk*8 + tig    ]);
            uint32_t a2 = __float_as_uint(sA[(wr*16 + gid    )*SA + kk*8 + tig + 4]);
            uint32_t a3 = __float_as_uint(sA[(wr*16 + gid + 8)*SA + kk*8 + tig + 4]);
            #pragma unroll
            for (int t = 0; t < NT; t++) {
                int n0 = wc*64 + t*8;
                uint32_t b0 = __float_as_uint(sB[(kk*8 + tig    )*BS + n0 + gid]);
                uint32_t b1v = __float_as_uint(sB[(kk*8 + tig + 4)*BS + n0 + gid]);
                asm volatile(
                    "mma.sync.aligned.m16n8k8.row.col.f32.tf32.tf32.f32 "
                    "{%0,%1,%2,%3}, {%4,%5,%6,%7}, {%8,%9}, {%0,%1,%2,%3};"
                    : "+f"(acc[t][0]), "+f"(acc[t][1]), "+f"(acc[t][2]), "+f"(acc[t][3])
                    : "r"(a0), "r"(a1), "r"(a2), "r"(a3), "r"(b0), "r"(b1v));
            }
        }
    }

    __syncthreads();
    issueB(0);
    issueB(1);

    float* sC = smem;
    #pragma unroll
    for (int t = 0; t < NT; t++) {
        int n0 = wc*64 + t*8 + tig*2;
        int r0 = wr*16 + gid;
        sC[ r0     *BS + n0    ] = acc[t][0];
        sC[ r0     *BS + n0 + 1] = acc[t][1];
        sC[(r0 + 8)*BS + n0    ] = acc[t][2];
        sC[(r0 + 8)*BS + n0 + 1] = acc[t][3];
    }
    __syncthreads();
    #pragma unroll
    for (int rr = 0; rr < 4; rr++) {
        int row = warp*4 + rr;
        float v[CT]; float s = 0.f, s2 = 0.f;
        #pragma unroll
        for (int j = 0; j < CT; j++) {
            float x = sC[row*BS + lane + 32*j];
            x = 0.5f*x*(1.f + erff(x*0.70710678118654752f));
            v[j] = x; s += x; s2 += x*x;
        }
        #pragma unroll
        for (int o = 16; o; o >>= 1) {
            s  += __shfl_xor_sync(0xffffffffu, s,  o);
            s2 += __shfl_xor_sync(0xffffffffu, s2, o);
        }
        float mean = s*(1.f/256.f);
        float rstd = rsqrtf(s2*(1.f/256.f) - mean*mean + 1e-5f);
        #pragma unroll
        for (int j = 0; j < CT; j++) {
            int col = lane + 32*j;
            sC[row*BS + col] = (v[j]-mean)*rstd*lnhg[col] + lnhb[col];
        }
    }
    __syncthreads();

    float acc2[NT][4];
    #pragma unroll
    for (int t = 0; t < NT; t++) {
        int j0 = wc*64 + t*8 + tig*2;
        acc2[t][0] = b2[j0];   acc2[t][1] = b2[j0+1];
        acc2[t][2] = b2[j0];   acc2[t][3] = b2[j0+1];
    }
    for (int kt = 0; kt < KT2; ++kt) {
        if (kt + 1 < KT2) CP_WAIT1(); else CP_WAIT0();
        __syncthreads();
        if (kt + 2 < KT2) issueB(kt + 2);
        const float* sB = smem + OFF2 + (kt % 3)*BSZ;
        #pragma unroll
        for (int kk = 0; kk < 4; kk++) {
            int kc = kt*32 + kk*8;
            uint32_t a0 = __float_as_uint(sC[(wr*16 + gid    )*BS + kc + tig    ]);
            uint32_t a1 = __float_as_uint(sC[(wr*16 + gid + 8)*BS + kc + tig    ]);
            uint32_t a2 = __float_as_uint(sC[(wr*16 + gid    )*BS + kc + tig + 4]);
            uint32_t a3 = __float_as_uint(sC[(wr*16 + gid + 8)*BS + kc + tig + 4]);
            #pragma unroll
            for (int t = 0; t < NT; t++) {
                int n0 = wc*64 + t*8;
                uint32_t b0 = __float_as_uint(sB[(kk*8 + tig    )*BS + n0 + gid]);
                uint32_t b1v = __float_as_uint(sB[(kk*8 + tig + 4)*BS + n0 + gid]);
                asm volatile(
                    "mma.sync.aligned.m16n8k8.row.col.f32.tf32.tf32.f32 "
                    "{%0,%1,%2,%3}, {%4,%5,%6,%7}, {%8,%9}, {%0,%1,%2,%3};"
                    : "+f"(acc2[t][0]), "+f"(acc2[t][1]), "+f"(acc2[t][2]), "+f"(acc2[t][3])
                    : "r"(a0), "r"(a1), "r"(a2), "r"(a3), "r"(b0), "r"(b1v));
            }
        }
    }

    float* sO = smem + OFF2;
    __syncthreads();
    #pragma unroll
    for (int t = 0; t < NT; t++) {
        int n0 = wc*64 + t*8 + tig*2;
        int r0 = wr*16 + gid;
        sO[ r0     *BS + n0    ] = acc2[t][0];
        sO[ r0     *BS + n0 + 1] = acc2[t][1];
        sO[(r0 + 8)*BS + n0    ] = acc2[t][2];
        sO[(r0 + 8)*BS + n0 + 1] = acc2[t][3];
    }
    __syncthreads();
    #pragma unroll
    for (int rr = 0; rr < 4; rr++) {
        int row = warp*4 + rr;
        int grow = rowBase + row;
        #pragma unroll
        for (int j = 0; j < CT; j++) {
            int col = lane + 32*j;
            out[(size_t)grow*256 + col] = sO[row*BS + col] + token[(size_t)grow*256 + col];
        }
    }
}

// ---------------- fused per-token attention (unchanged from R8/R9) ----------------
struct AttnGroup {
    float edge[32*ES];
    float logit[8*32];
    float attnT[32*8];
    float arT[32*8];
    float mean[32];
    float rstd[32];
    float s1[8];
    float qd[8];
    int   nbr[32];
};
struct AttnSmem {
    float wg[8*132];
    float swg[8];
    float beff2[8];
    float wfa[8];
    float lng[128];
    float lnb[128];
    AttnGroup grp[4];
};

#define GBAR(id) asm volatile("bar.sync %0, 128;" :: "r"(id) : "memory")

__global__ __launch_bounds__(512, 2)
void attn_kernel(const float* __restrict__ edge_feats,
                 const float* __restrict__ geo_feats,
                 const int*   __restrict__ nbr_idx,
                 const int*   __restrict__ masks,
                 const float* __restrict__ ln_e_g,
                 const float* __restrict__ ln_e_b,
                 const float* __restrict__ W_fa,
                 const float* __restrict__ b_fa,
                 float* __restrict__ out_geo)
{
    extern __shared__ char smraw[];
    AttnSmem& sm = *reinterpret_cast<AttnSmem*>(smraw);
    const int tid = threadIdx.x;

    for (int i = tid; i < 8*132; i += 512) sm.wg[i] = g_wg[i];
    if (tid < 128) { sm.lng[tid] = ln_e_g[tid]; sm.lnb[tid] = ln_e_b[tid]; }
    if (tid >= 128 && tid < 136) {
        int h = tid - 128;
        sm.swg[h] = g_swg[h]; sm.beff2[h] = g_beff2[h]; sm.wfa[h] = W_fa[h];
    }
    const float bfa = b_fa[0];
    __syncthreads();

    const int g     = tid >> 7;
    const int gtid  = tid & 127;
    const int glane = gtid & 31;
    const int gwarp = gtid >> 5;
    const int bid   = 1 + g;
    AttnGroup& G = sm.grp[g];

    for (int tok = 0; tok < 2; ++tok) {
        const int n = blockIdx.x*8 + g*2 + tok;

        {
            const float4* ep4 = (const float4*)(edge_feats + (size_t)n*4096);
            #pragma unroll
            for (int jj = 0; jj < 8; jj++) {
                int idx = gtid + 128*jj;
                int m = gwarp + 4*jj;
                float4 v = ep4[idx];
                *(float4*)&G.edge[m*ES + glane*4] = v;
                float s  = v.x + v.y + v.z + v.w;
                float s2 = v.x*v.x + v.y*v.y + v.z*v.z + v.w*v.w;
                #pragma unroll
                for (int o = 16; o; o >>= 1) {
                    s  += __shfl_xor_sync(0xffffffffu, s,  o);
                    s2 += __shfl_xor_sync(0xffffffffu, s2, o);
                }
                if (glane == 0) {
                    float mean = s*(1.f/128.f);
                    float rstd = rsqrtf(s2*(1.f/128.f) - mean*mean + 1e-5f);
                    G.mean[m] = mean; G.rstd[m] = rstd;
                }
            }
            if (gtid < 32) G.nbr[gtid] = nbr_idx[n*32 + gtid];
            if (gtid >= 32 && gtid < 40) G.qd[gtid-32] = g_qkv[(size_t)n*QS + 256 + gtid-32];
        }
        GBAR(bid);

        {
            int m0 = gtid >> 3, h = gtid & 7;
            int nb0 = G.nbr[m0], nb1 = G.nbr[m0 + 16];
            float kd0 = g_qkv[(size_t)nb0*QS + 264 + h];
            float kd1 = g_qkv[(size_t)nb1*QS + 264 + h];
            int mk0 = masks[n*32 + m0];
            int mk1 = masks[n*32 + m0 + 16];
            float d0 = 0.f, d1 = 0.f;
            const float4* e0 = (const float4*)&G.edge[m0*ES];
            const float4* e1 = (const float4*)&G.edge[(m0+16)*ES];
            const float4* wt = (const float4*)&sm.wg[h*132];
            #pragma unroll 8
            for (int c4 = 0; c4 < 32; c4++) {
                float4 w = wt[c4], x = e0[c4], y = e1[c4];
                d0 += x.x*w.x + x.y*w.y + x.z*w.z + x.w*w.w;
                d1 += y.x*w.x + y.y*w.y + y.z*w.z + y.w*w.w;
            }
            float base = G.qd[h] + sm.beff2[h];
            float sw = sm.swg[h];
            float a0 = base + kd0 + G.rstd[m0]   *(d0 - G.mean[m0]   *sw);
            float a1 = base + kd1 + G.rstd[m0+16]*(d1 - G.mean[m0+16]*sw);
            if (!mk0) a0 = -1e9f;
            if (!mk1) a1 = -1e9f;
            G.logit[h*32 + m0]      = a0;
            G.logit[h*32 + m0 + 16] = a1;
        }
        GBAR(bid);

        {
            #pragma unroll
            for (int i = 0; i < 2; i++) {
                int h = gwarp + 4*i;
                float l = G.logit[h*32 + glane];
                float mx = l;
                #pragma unroll
                for (int o = 16; o; o >>= 1) mx = fmaxf(mx, __shfl_xor_sync(0xffffffffu, mx, o));
                float e = __expf(l - mx);
                float ss = e;
                #pragma unroll
                for (int o = 16; o; o >>= 1) ss += __shfl_xor_sync(0xffffffffu, ss, o);
                float a = e/ss;
                float ar = a*G.rstd[glane];
                float s1p = ar*G.mean[glane];
                #pragma unroll
                for (int o = 16; o; o >>= 1) s1p += __shfl_xor_sync(0xffffffffu, s1p, o);
                G.attnT[glane*8 + h] = a;
                G.arT[glane*8 + h]   = ar;
                if (glane == 0) G.s1[h] = s1p;
            }
        }
        GBAR(bid);

        {
            float acc0 = 0.f, acc1 = 0.f;
            int c0 = gtid, c1 = gtid + 128;
            int h0 = c0 >> 5, h1 = c1 >> 5;
            #pragma unroll
            for (int m = 0; m < 32; m++) {
                const float* vrow = &g_qkv[(size_t)G.nbr[m]*QS];
                acc0 += G.attnT[m*8 + h0]*vrow[c0];
                acc1 += G.attnT[m*8 + h1]*vrow[c1];
            }
            g_hx[(size_t)n*HXS + c0] = acc0;
            g_hx[(size_t)n*HXS + c1] = acc1;

            float ewa[8];
            #pragma unroll
            for (int h = 0; h < 8; h++) ewa[h] = 0.f;
            const float4* ar4 = (const float4*)G.arT;
            #pragma unroll
            for (int m = 0; m < 32; m++) {
                float e = G.edge[m*ES + gtid];
                float4 r0 = ar4[m*2], r1 = ar4[m*2 + 1];
                ewa[0] += r0.x*e; ewa[1] += r0.y*e; ewa[2] += r0.z*e; ewa[3] += r0.w*e;
                ewa[4] += r1.x*e; ewa[5] += r1.y*e; ewa[6] += r1.z*e; ewa[7] += r1.w*e;
            }
            float gl = sm.lng[gtid], bl = sm.lnb[gtid];
            #pragma unroll
            for (int h = 0; h < 8; h++)
                g_hx[(size_t)n*HXS + 256 + h*128 + gtid] = gl*(ewa[h] - G.s1[h]) + bl;
        }
        if (gwarp == 3) {
            int m = glane;
            float aw = 0.f;
            #pragma unroll
            for (int h = 0; h < 8; h++) aw += G.attnT[m*8 + h]*sm.wfa[h];
            int nb = G.nbr[m];
            float p0 = aw*g_proj[nb*3 + 0];
            float p1 = aw*g_proj[nb*3 + 1];
            float p2 = aw*g_proj[nb*3 + 2];
            #pragma unroll
            for (int o = 16; o; o >>= 1) {
                p0 += __shfl_xor_sync(0xffffffffu, p0, o);
                p1 += __shfl_xor_sync(0xffffffffu, p1, o);
                p2 += __shfl_xor_sync(0xffffffffu, p2, o);
            }
            if (glane == 0) {
                int b = n >> 9;
                float ps[3] = {p0, p1, p2};
                float sd[3];
                #pragma unroll
                for (int j = 0; j < 3; j++)
                    sd[j] = 0.5f*(siluf(ps[j] + bfa) - siluf(-ps[j] + bfa));
                float gt = g_gate[n];
                #pragma unroll
                for (int i = 0; i < 3; i++) {
                    float gc = g_center[b*3 + i]
                             + sd[0]*g_V[b*9 + i*3 + 0]
                             + sd[1]*g_V[b*9 + i*3 + 1]
                             + sd[2]*g_V[b*9 + i*3 + 2];
                    out_geo[n*3 + i] = gc*gt + geo_feats[n*3 + i]*(1.f - gt);
                }
            }
        }
        GBAR(bid);
    }
}

// ---------------- launcher ----------------
extern "C" void kernel_launch(void* const* d_in, const int* in_sizes, int n_in,
                              void* d_out, int out_size)
{
    const float* token    = (const float*)d_in[0];
    const float* geo      = (const float*)d_in[1];
    const float* edge     = (const float*)d_in[2];
    const int*   nbr      = (const int*)d_in[3];
    const int*   mask     = (const int*)d_in[5];
    const float* ln_qkv_g = (const float*)d_in[6];
    const float* ln_qkv_b = (const float*)d_in[7];
    const float* W_qkv    = (const float*)d_in[8];
    const float* b_qkv    = (const float*)d_in[9];
    const float* ln_e_g   = (const float*)d_in[10];
    const float* ln_e_b   = (const float*)d_in[11];
    const float* W_qkv_e  = (const float*)d_in[12];
    const float* b_qkv_e  = (const float*)d_in[13];
    const float* w_attn   = (const float*)d_in[14];
    const float* w_edge   = (const float*)d_in[15];
    const float* W_gate   = (const float*)d_in[16];
    const float* b_gate   = (const float*)d_in[17];
    const float* W_fc1    = (const float*)d_in[18];
    const float* b_fc1    = (const float*)d_in[19];
    const float* ln_h_g   = (const float*)d_in[20];
    const float* ln_h_b   = (const float*)d_in[21];
    const float* W_fc2    = (const float*)d_in[22];
    const float* b_fc2    = (const float*)d_in[23];
    const float* W_fa     = (const float*)d_in[24];
    const float* b_fa     = (const float*)d_in[25];
    float* out = (float*)d_out;

    void* p;
    cudaGetSymbolAddress(&p, g_qkv);   float* p_qkv   = (float*)p;
    cudaGetSymbolAddress(&p, g_hx);    float* p_hx    = (float*)p;
    cudaGetSymbolAddress(&p, g_Wcomb); float* p_Wcomb = (float*)p;
    cudaGetSymbolAddress(&p, g_bcomb); float* p_bcomb = (float*)p;
    cudaGetSymbolAddress(&p, g_W1);    float* p_W1    = (float*)p;
    cudaGetSymbolAddress(&p, g_b1);    float* p_b1    = (float*)p;

    prep_kernel<<<64, 256>>>(W_qkv, b_qkv, w_attn, W_qkv_e, b_qkv_e, w_edge,
                             W_fc1, b_fc1, ln_e_g, ln_e_b);
    geom_kernel<<<16, 256>>>(geo);

    // qkv: token -> LN(+gate) -> @ Wcomb[256,288], all in one kernel
    {
        constexpr int SM = (64*260 + 3*32*292)*sizeof(float);   // ~178.7 KB
        cudaFuncSetAttribute((const void*)gemm_qkv_f,
                             cudaFuncAttributeMaxDynamicSharedMemorySize, SM);
        gemm_qkv_f<<<128, 512, SM>>>(token, p_Wcomb, p_bcomb,
                                     W_gate, b_gate, ln_qkv_g, ln_qkv_b, p_qkv);
    }

    cudaFuncSetAttribute(attn_kernel, cudaFuncAttributeMaxDynamicSharedMemorySize,
                         (int)sizeof(AttnSmem));
    attn_kernel<<<1024, 512, sizeof(AttnSmem)>>>(
        edge, geo, nbr, mask, ln_e_g, ln_e_b, W_fa, b_fa,
        out + (size_t)NTOK*256);

    // fused fc1+fc2
    {
        constexpr int SM = (64*260 + 3*32*260)*sizeof(float);   // 166.4 KB
        cudaFuncSetAttribute((const void*)gemm_fc12,
                             cudaFuncAttributeMaxDynamicSharedMemorySize, SM);
        gemm_fc12<<<128, 512, SM>>>(p_hx, p_W1, p_b1, W_fc2, b_fc2,
                                    token, ln_h_g, ln_h_b, out);
    }
}

// round 11
// speedup vs baseline: 1.2044x; 1.0282x over previous
#include <cuda_runtime.h>
#include <math.h>
#include <stdint.h>

#define NTOK 8192
#define QS 288            // qkv row stride: 256 v | 8 qdot | 8 kdot | pad
#define ES 132            // edge smem row stride (floats)
#define HXS 1280          // hx row stride: 256 scalar ctx | 1024 ew

// ---------------- device scratch ----------------
__device__ float g_qkv[NTOK*QS];
__device__ float g_hx[NTOK*HXS];
__device__ float g_gate[NTOK];
__device__ float g_proj[NTOK*3];
__device__ float g_center[16*3];
__device__ float g_V[16*9];
__device__ float g_Wcomb[256*QS];
__device__ float g_bcomb[QS];
__device__ float g_wg[8*132];       // [h][c]: lng[c]*weff[c][h], padded
__device__ float g_swg[8];
__device__ float g_beff2[8];
__device__ float g_W1[HXS*256];     // folded fc1 weight: [1280, 256]
__device__ float g_b1[256];         // folded fc1 bias

__device__ __forceinline__ float siluf(float x){ return x/(1.f+__expf(-x)); }
__device__ __forceinline__ uint32_t f2tf32(float x){
    uint32_t u; asm("cvt.rna.tf32.f32 %0, %1;" : "=r"(u) : "f"(x)); return u;
}

#define CP_ASYNC16(dst, src) \
    asm volatile("cp.async.ca.shared.global [%0], [%1], 16;\n" :: "r"(dst), "l"(src))
#define CP_COMMIT() asm volatile("cp.async.commit_group;\n" ::: "memory")
#define CP_WAIT2()  asm volatile("cp.async.wait_group 2;\n" ::: "memory")
#define CP_WAIT1()  asm volatile("cp.async.wait_group 1;\n" ::: "memory")
#define CP_WAIT0()  asm volatile("cp.async.wait_group 0;\n" ::: "memory")

__device__ __forceinline__ uint32_t sptr(const void* p){
    return (uint32_t)__cvta_generic_to_shared(p);
}

// ---------------- prep: fold effective weights ----------------
__global__ void prep_kernel(const float* __restrict__ W_qkv, const float* __restrict__ b_qkv,
                            const float* __restrict__ w_attn,
                            const float* __restrict__ W_qkv_e, const float* __restrict__ b_qkv_e,
                            const float* __restrict__ w_edge,
                            const float* __restrict__ W_fc1, const float* __restrict__ b_fc1,
                            const float* __restrict__ ln_e_g, const float* __restrict__ ln_e_b)
{
    int gid = blockIdx.x*blockDim.x + threadIdx.x;
    int gstride = gridDim.x*blockDim.x;
    for (int idx = gid; idx < 256*QS; idx += gstride) {
        int c = idx / QS, j = idx - c*QS;
        float w = 0.f;
        if (j < 256) {
            w = W_qkv[c*768 + 512 + j];
        } else if (j < 264) {
            int h = j - 256; float s = 0.f;
            #pragma unroll
            for (int d = 0; d < 32; d++) s += W_qkv[c*768 + h*32 + d]*w_attn[d];
            w = s;
        } else if (j < 272) {
            int h = j - 264; float s = 0.f;
            #pragma unroll
            for (int d = 0; d < 32; d++) s += W_qkv[c*768 + 256 + h*32 + d]*w_attn[d];
            w = s;
        }
        g_Wcomb[idx] = w;
    }
    for (int idx = gid; idx < HXS*256; idx += gstride) {
        int j = idx >> 8, o = idx & 255;
        float w;
        if (j < 256) {
            w = W_fc1[j*256 + o];
        } else {
            int hc = j - 256, h = hc >> 7, c = hc & 127;
            float s = 0.f;
            #pragma unroll
            for (int jp = 0; jp < 16; jp++)
                s += W_qkv_e[c*256 + 128 + h*16 + jp]*W_fc1[(256 + h*16 + jp)*256 + o];
            w = s;
        }
        g_W1[idx] = w;
    }
    if (blockIdx.x == 0) {
        for (int j = threadIdx.x; j < QS; j += blockDim.x) {
            float bv = 0.f;
            if (j < 256) bv = b_qkv[512 + j];
            else if (j < 264) { int h = j-256; for (int d=0; d<32; d++) bv += b_qkv[h*32+d]*w_attn[d]; }
            else if (j < 272) { int h = j-264; for (int d=0; d<32; d++) bv += b_qkv[256 + h*32+d]*w_attn[d]; }
            g_bcomb[j] = bv;
        }
    }
    if (blockIdx.x == 1) {
        __shared__ float sweff[128*8];
        for (int idx = threadIdx.x; idx < 128*8; idx += blockDim.x) {
            int c = idx >> 3, h = idx & 7; float s = 0.f;
            #pragma unroll
            for (int e = 0; e < 16; e++) s += W_qkv_e[c*256 + h*16 + e]*w_edge[e];
            sweff[idx] = s;
            g_wg[h*132 + c] = ln_e_g[c]*s;
        }
        __syncthreads();
        if (threadIdx.x < 8) {
            int h = threadIdx.x;
            float sw = 0.f, b2 = 0.f;
            for (int c = 0; c < 128; c++) {
                float we = sweff[c*8 + h];
                sw += ln_e_g[c]*we;
                b2 += ln_e_b[c]*we;
            }
            for (int e = 0; e < 16; e++) b2 += b_qkv_e[h*16 + e]*w_edge[e];
            g_swg[h] = sw; g_beff2[h] = b2;
        }
    }
    if (blockIdx.x == 2 && threadIdx.x < 256) {
        int o = threadIdx.x;
        float s = b_fc1[o];
        for (int j = 0; j < 128; j++)
            s += b_qkv_e[128 + j]*W_fc1[(256 + j)*256 + o];
        g_b1[o] = s;
    }
}

// ---------------- per-graph geometry (fp32 Jacobi) ----------------
__device__ void jacobi3f(float a00,float a01,float a02,float a11,float a12,float a22,
                         float V[3][3])
{
    float A[3][3] = {{a00,a01,a02},{a01,a11,a12},{a02,a12,a22}};
    V[0][0]=1; V[0][1]=0; V[0][2]=0;
    V[1][0]=0; V[1][1]=1; V[1][2]=0;
    V[2][0]=0; V[2][1]=0; V[2][2]=1;
    float tr = fabsf(a00)+fabsf(a11)+fabsf(a22);
    for (int it = 0; it < 40; ++it) {
        int p = 0, q = 1; float mx = fabsf(A[0][1]);
        if (fabsf(A[0][2]) > mx) { mx = fabsf(A[0][2]); p = 0; q = 2; }
        if (fabsf(A[1][2]) > mx) { mx = fabsf(A[1][2]); p = 1; q = 2; }
        if (mx <= 1e-8f*tr) break;
        float apq = A[p][q];
        float theta = (A[q][q]-A[p][p])/(2.0f*apq);
        float t = 1.0f/(fabsf(theta)+sqrtf(theta*theta+1.0f));
        if (theta < 0) t = -t;
        float c = rsqrtf(t*t+1.0f), s = t*c;
        for (int k = 0; k < 3; k++) { float akp=A[k][p], akq=A[k][q]; A[k][p]=c*akp-s*akq; A[k][q]=s*akp+c*akq; }
        for (int k = 0; k < 3; k++) { float apk=A[p][k], aqk=A[q][k]; A[p][k]=c*apk-s*aqk; A[q][k]=s*apk+c*aqk; }
        for (int k = 0; k < 3; k++) { float vkp=V[k][p], vkq=V[k][q]; V[k][p]=c*vkp-s*vkq; V[k][q]=s*vkp+c*vkq; }
    }
}

__global__ void geom_kernel(const float* __restrict__ geo)
{
    __shared__ double sred[8][9];
    __shared__ double sCd[3];
    __shared__ float sV[9], sC[3];
    int b = blockIdx.x, tid = threadIdx.x, lane = tid & 31, warp = tid >> 5;
    const float* G = geo + (size_t)b*512*3;

    {
        double s[3] = {0,0,0};
        for (int p = tid; p < 512; p += 256) { s[0] += G[p*3]; s[1] += G[p*3+1]; s[2] += G[p*3+2]; }
        #pragma unroll
        for (int k = 0; k < 3; k++)
            #pragma unroll
            for (int o = 16; o; o >>= 1) s[k] += __shfl_xor_sync(0xffffffffu, s[k], o);
        if (lane == 0) { sred[warp][0]=s[0]; sred[warp][1]=s[1]; sred[warp][2]=s[2]; }
    }
    __syncthreads();
    if (tid == 0) {
        for (int k = 0; k < 3; k++) {
            double t = 0; for (int w = 0; w < 8; w++) t += sred[w][k];
            sCd[k] = t/512.0;
        }
    }
    __syncthreads();
    double c0 = sCd[0], c1 = sCd[1], c2 = sCd[2];

    {
        double m[6] = {0,0,0,0,0,0};
        for (int p = tid; p < 512; p += 256) {
            double dx = G[p*3]-c0, dy = G[p*3+1]-c1, dz = G[p*3+2]-c2;
            m[0] += dx*dx; m[1] += dx*dy; m[2] += dx*dz;
            m[3] += dy*dy; m[4] += dy*dz; m[5] += dz*dz;
        }
        #pragma unroll
        for (int k = 0; k < 6; k++)
            #pragma unroll
            for (int o = 16; o; o >>= 1) m[k] += __shfl_xor_sync(0xffffffffu, m[k], o);
        if (lane == 0) for (int k = 0; k < 6; k++) sred[warp][k] = m[k];
    }
    __syncthreads();
    if (tid == 0) {
        double m[6];
        for (int k = 0; k < 6; k++) { double t=0; for (int w=0; w<8; w++) t += sred[w][k]; m[k]=t; }
        float V[3][3];
        jacobi3f((float)m[0],(float)m[1],(float)m[2],(float)m[3],(float)m[4],(float)m[5], V);
        for (int i = 0; i < 3; i++)
            for (int j = 0; j < 3; j++) { sV[i*3+j] = V[i][j]; g_V[b*9+i*3+j] = V[i][j]; }
        sC[0]=(float)c0; sC[1]=(float)c1; sC[2]=(float)c2;
        g_center[b*3+0]=(float)c0; g_center[b*3+1]=(float)c1; g_center[b*3+2]=(float)c2;
    }
    __syncthreads();

    for (int p = tid; p < 512; p += 256) {
        int t = b*512 + p;
        float dx = G[p*3]-sC[0], dy = G[p*3+1]-sC[1], dz = G[p*3+2]-sC[2];
        for (int d = 0; d < 3; d++)
            g_proj[t*3+d] = dx*sV[0*3+d] + dy*sV[1*3+d] + dz*sV[2*3+d];
    }
}

// ---------------- qkv GEMM: BM=64, A resident + fused LN/gate, B 3-stage cp.async ----------------
__global__ __launch_bounds__(512)
void gemm_qkv_f(const float* __restrict__ X,
                const float* __restrict__ Bw,
                const float* __restrict__ bias,
                const float* __restrict__ Wg, const float* __restrict__ bg,
                const float* __restrict__ lng, const float* __restrict__ lnb,
                float* __restrict__ C)
{
    constexpr int K = 256, N = QS;
    constexpr int AS = 260, BS = 292;
    constexpr int ASZ = 64*AS, BSZ = 32*BS;
    constexpr int KT = K/32, WN = N/4, NT = WN/8, CT = N/32;
    extern __shared__ float smem[];
    float* sA = smem;
    float* sBst = smem + ASZ;
    const int tid = threadIdx.x, lane = tid & 31, warp = tid >> 5;
    const int wr = warp >> 2, wc = warp & 3;
    const int gid = lane >> 2, tig = lane & 3;
    const int rowBase = blockIdx.x*64;

    auto issueB = [&](int kt) {
        float* dB = sBst + (kt % 3)*BSZ;
        #pragma unroll
        for (int jj = 0; jj < 5; jj++) {
            int idx = tid + 512*jj;
            if (idx < 32*72) {
                int r = idx/72, c4 = idx - r*72;
                CP_ASYNC16(sptr(&dB[r*BS + c4*4]),
                           &Bw[(size_t)(kt*32 + r)*N + c4*4]);
            }
        }
        CP_COMMIT();
    };

    {
        #pragma unroll
        for (int jj = 0; jj < 8; jj++) {
            int idx = tid + 512*jj;
            int r = idx >> 6, c4 = idx & 63;
            CP_ASYNC16(sptr(&sA[r*AS + c4*4]),
                       &X[(size_t)(rowBase + r)*K + c4*4]);
        }
        CP_COMMIT();
    }
    issueB(0);
    issueB(1);

    CP_WAIT2();
    __syncthreads();

    #pragma unroll
    for (int rr = 0; rr < 4; rr++) {
        int row = warp*4 + rr;
        float v[8]; float s = 0.f, s2 = 0.f, gd = 0.f;
        #pragma unroll
        for (int j = 0; j < 8; j++) {
            int c = lane + 32*j;
            float t = sA[row*AS + c];
            v[j] = t; s += t; s2 += t*t; gd += t*Wg[c];
        }
        #pragma unroll
        for (int o = 16; o; o >>= 1) {
            s  += __shfl_xor_sync(0xffffffffu, s,  o);
            s2 += __shfl_xor_sync(0xffffffffu, s2, o);
            gd += __shfl_xor_sync(0xffffffffu, gd, o);
        }
        float mean = s*(1.f/256.f);
        float rstd = rsqrtf(s2*(1.f/256.f) - mean*mean + 1e-5f);
        #pragma unroll
        for (int j = 0; j < 8; j++) {
            int c = lane + 32*j;
            sA[row*AS + c] = (v[j]-mean)*rstd*lng[c] + lnb[c];
        }
        if (lane == 0) g_gate[rowBase + row] = 1.f/(1.f + __expf(-(gd + bg[0])));
    }
    __syncthreads();

    float acc[NT][4];
    #pragma unroll
    for (int t = 0; t < NT; t++) {
        int j0 = wc*WN + t*8 + tig*2;
        acc[t][0] = bias[j0];   acc[t][1] = bias[j0+1];
        acc[t][2] = bias[j0];   acc[t][3] = bias[j0+1];
    }

    for (int kt = 0; kt < KT; ++kt) {
        if (kt + 1 < KT) CP_WAIT1(); else CP_WAIT0();
        __syncthreads();
        if (kt + 2 < KT) issueB(kt + 2);
        const float* sB = sBst + (kt % 3)*BSZ;
        #pragma unroll
        for (int kk = 0; kk < 4; kk++) {
            int kc = kt*32 + kk*8;
            uint32_t a0 = __float_as_uint(sA[(wr*16 + gid    )*AS + kc + tig    ]);
            uint32_t a1 = __float_as_uint(sA[(wr*16 + gid + 8)*AS + kc + tig    ]);
            uint32_t a2 = __float_as_uint(sA[(wr*16 + gid    )*AS + kc + tig + 4]);
            uint32_t a3 = __float_as_uint(sA[(wr*16 + gid + 8)*AS + kc + tig + 4]);
            #pragma unroll
            for (int t = 0; t < NT; t++) {
                int n0 = wc*WN + t*8;
                uint32_t b0 = __float_as_uint(sB[(kk*8 + tig    )*BS + n0 + gid]);
                uint32_t b1 = __float_as_uint(sB[(kk*8 + tig + 4)*BS + n0 + gid]);
                asm volatile(
                    "mma.sync.aligned.m16n8k8.row.col.f32.tf32.tf32.f32 "
                    "{%0,%1,%2,%3}, {%4,%5,%6,%7}, {%8,%9}, {%0,%1,%2,%3};"
                    : "+f"(acc[t][0]), "+f"(acc[t][1]), "+f"(acc[t][2]), "+f"(acc[t][3])
                    : "r"(a0), "r"(a1), "r"(a2), "r"(a3), "r"(b0), "r"(b1));
            }
        }
    }

    float* sC = sBst;
    __syncthreads();
    #pragma unroll
    for (int t = 0; t < NT; t++) {
        int n0 = wc*WN + t*8 + tig*2;
        int r0 = wr*16 + gid;
        sC[ r0     *BS + n0    ] = acc[t][0];
        sC[ r0     *BS + n0 + 1] = acc[t][1];
        sC[(r0 + 8)*BS + n0    ] = acc[t][2];
        sC[(r0 + 8)*BS + n0 + 1] = acc[t][3];
    }
    __syncthreads();
    #pragma unroll
    for (int rr = 0; rr < 4; rr++) {
        int row = warp*4 + rr;
        int grow = rowBase + row;
        #pragma unroll
        for (int j = 0; j < CT; j++) {
            int col = lane + 32*j;
            C[(size_t)grow*N + col] = sC[row*BS + col];
        }
    }
}

// ---------------- fused fc1(gelu+LN)+fc2(+residual) ----------------
__global__ __launch_bounds__(512)
void gemm_fc12(const float* __restrict__ A,
               const float* __restrict__ W1,
               const float* __restrict__ b1,
               const float* __restrict__ W2,
               const float* __restrict__ b2,
               const float* __restrict__ token,
               const float* __restrict__ lnhg, const float* __restrict__ lnhb,
               float* __restrict__ out)
{
    constexpr int N = 256, K1 = HXS, K2 = 256;
    constexpr int KT1 = K1/32, KT2 = K2/32;
    constexpr int SA = 36, BS = N + 4;
    constexpr int ASZ = 64*SA, BSZ = 32*BS, STG1 = ASZ + BSZ;
    constexpr int SCSZ = 64*BS;
    constexpr int OFF2 = SCSZ;
    constexpr int NT = 8, CT = N/32;
    extern __shared__ float smem[];
    const int tid = threadIdx.x, lane = tid & 31, warp = tid >> 5;
    const int wr = warp >> 2, wc = warp & 3;
    const int gid = lane >> 2, tig = lane & 3;
    const int rowBase = blockIdx.x*64;
    const int ar = tid >> 3, ac4 = tid & 7;

    auto issueA = [&](int kt) {
        float* dA = smem + (kt % 3)*STG1;
        float* dB = dA + ASZ;
        CP_ASYNC16(sptr(&dA[ar*SA + ac4*4]),
                   &A[(size_t)(rowBase + ar)*K1 + kt*32 + ac4*4]);
        #pragma unroll
        for (int jj = 0; jj < 4; jj++) {
            int idx = tid + 512*jj;
            int r = idx >> 6, c4 = idx & 63;
            CP_ASYNC16(sptr(&dB[r*BS + c4*4]),
                       &W1[(size_t)(kt*32 + r)*N + c4*4]);
        }
        CP_COMMIT();
    };
    auto issueB = [&](int kt) {
        float* dB = smem + OFF2 + (kt % 3)*BSZ;
        #pragma unroll
        for (int jj = 0; jj < 4; jj++) {
            int idx = tid + 512*jj;
            int r = idx >> 6, c4 = idx & 63;
            CP_ASYNC16(sptr(&dB[r*BS + c4*4]),
                       &W2[(size_t)(kt*32 + r)*N + c4*4]);
        }
        CP_COMMIT();
    };

    issueA(0);
    issueA(1);

    float acc[NT][4];
    #pragma unroll
    for (int t = 0; t < NT; t++) {
        int j0 = wc*64 + t*8 + tig*2;
        acc[t][0] = b1[j0];   acc[t][1] = b1[j0+1];
        acc[t][2] = b1[j0];   acc[t][3] = b1[j0+1];
    }

    for (int kt = 0; kt < KT1; ++kt) {
        if (kt + 1 < KT1) CP_WAIT1(); else CP_WAIT0();
        __syncthreads();
        if (kt + 2 < KT1) issueA(kt + 2);
        const float* sA = smem + (kt % 3)*STG1;
        const float* sB = sA + ASZ;
        #pragma unroll
        for (int kk = 0; kk < 4; kk++) {
            uint32_t a0 = __float_as_uint(sA[(wr*16 + gid    )*SA + kk*8 + tig    ]);
            uint32_t a1 = __float_as_uint(sA[(wr*16 + gid + 8)*SA + kk*8 + tig    ]);
            uint32_t a2 = __float_as_uint(sA[(wr*16 + gid    )*SA + kk*8 + tig + 4]);
            uint32_t a3 = __float_as_uint(sA[(wr*16 + gid + 8)*SA + kk*8 + tig + 4]);
            #pragma unroll
            for (int t = 0; t < NT; t++) {
                int n0 = wc*64 + t*8;
                uint32_t b0 = __float_as_uint(sB[(kk*8 + tig    )*BS + n0 + gid]);
                uint32_t b1v = __float_as_uint(sB[(kk*8 + tig + 4)*BS + n0 + gid]);
                asm volatile(
                    "mma.sync.aligned.m16n8k8.row.col.f32.tf32.tf32.f32 "
                    "{%0,%1,%2,%3}, {%4,%5,%6,%7}, {%8,%9}, {%0,%1,%2,%3};"
                    : "+f"(acc[t][0]), "+f"(acc[t][1]), "+f"(acc[t][2]), "+f"(acc[t][3])
                    : "r"(a0), "r"(a1), "r"(a2), "r"(a3), "r"(b0), "r"(b1v));
            }
        }
    }

    __syncthreads();
    issueB(0);
    issueB(1);

    float* sC = smem;
    #pragma unroll
    for (int t = 0; t < NT; t++) {
        int n0 = wc*64 + t*8 + tig*2;
        int r0 = wr*16 + gid;
        sC[ r0     *BS + n0    ] = acc[t][0];
        sC[ r0     *BS + n0 + 1] = acc[t][1];
        sC[(r0 + 8)*BS + n0    ] = acc[t][2];
        sC[(r0 + 8)*BS + n0 + 1] = acc[t][3];
    }
    __syncthreads();
    #pragma unroll
    for (int rr = 0; rr < 4; rr++) {
        int row = warp*4 + rr;
        float v[CT]; float s = 0.f, s2 = 0.f;
        #pragma unroll
        for (int j = 0; j < CT; j++) {
            float x = sC[row*BS + lane + 32*j];
            x = 0.5f*x*(1.f + erff(x*0.70710678118654752f));
            v[j] = x; s += x; s2 += x*x;
        }
        #pragma unroll
        for (int o = 16; o; o >>= 1) {
            s  += __shfl_xor_sync(0xffffffffu, s,  o);
            s2 += __shfl_xor_sync(0xffffffffu, s2, o);
        }
        float mean = s*(1.f/256.f);
        float rstd = rsqrtf(s2*(1.f/256.f) - mean*mean + 1e-5f);
        #pragma unroll
        for (int j = 0; j < CT; j++) {
            int col = lane + 32*j;
            sC[row*BS + col] = (v[j]-mean)*rstd*lnhg[col] + lnhb[col];
        }
    }
    __syncthreads();

    float acc2[NT][4];
    #pragma unroll
    for (int t = 0; t < NT; t++) {
        int j0 = wc*64 + t*8 + tig*2;
        acc2[t][0] = b2[j0];   acc2[t][1] = b2[j0+1];
        acc2[t][2] = b2[j0];   acc2[t][3] = b2[j0+1];
    }
    for (int kt = 0; kt < KT2; ++kt) {
        if (kt + 1 < KT2) CP_WAIT1(); else CP_WAIT0();
        __syncthreads();
        if (kt + 2 < KT2) issueB(kt + 2);
        const float* sB = smem + OFF2 + (kt % 3)*BSZ;
        #pragma unroll
        for (int kk = 0; kk < 4; kk++) {
            int kc = kt*32 + kk*8;
            uint32_t a0 = __float_as_uint(sC[(wr*16 + gid    )*BS + kc + tig    ]);
            uint32_t a1 = __float_as_uint(sC[(wr*16 + gid + 8)*BS + kc + tig    ]);
            uint32_t a2 = __float_as_uint(sC[(wr*16 + gid    )*BS + kc + tig + 4]);
            uint32_t a3 = __float_as_uint(sC[(wr*16 + gid + 8)*BS + kc + tig + 4]);
            #pragma unroll
            for (int t = 0; t < NT; t++) {
                int n0 = wc*64 + t*8;
                uint32_t b0 = __float_as_uint(sB[(kk*8 + tig    )*BS + n0 + gid]);
                uint32_t b1v = __float_as_uint(sB[(kk*8 + tig + 4)*BS + n0 + gid]);
                asm volatile(
                    "mma.sync.aligned.m16n8k8.row.col.f32.tf32.tf32.f32 "
                    "{%0,%1,%2,%3}, {%4,%5,%6,%7}, {%8,%9}, {%0,%1,%2,%3};"
                    : "+f"(acc2[t][0]), "+f"(acc2[t][1]), "+f"(acc2[t][2]), "+f"(acc2[t][3])
                    : "r"(a0), "r"(a1), "r"(a2), "r"(a3), "r"(b0), "r"(b1v));
            }
        }
    }

    float* sO = smem + OFF2;
    __syncthreads();
    #pragma unroll
    for (int t = 0; t < NT; t++) {
        int n0 = wc*64 + t*8 + tig*2;
        int r0 = wr*16 + gid;
        sO[ r0     *BS + n0    ] = acc2[t][0];
        sO[ r0     *BS + n0 + 1] = acc2[t][1];
        sO[(r0 + 8)*BS + n0    ] = acc2[t][2];
        sO[(r0 + 8)*BS + n0 + 1] = acc2[t][3];
    }
    __syncthreads();
    #pragma unroll
    for (int rr = 0; rr < 4; rr++) {
        int row = warp*4 + rr;
        int grow = rowBase + row;
        #pragma unroll
        for (int j = 0; j < CT; j++) {
            int col = lane + 32*j;
            out[(size_t)grow*256 + col] = sO[row*BS + col] + token[(size_t)grow*256 + col];
        }
    }
}

// ---------------- fused per-token attention: ew via tensor cores ----------------
struct AttnGroup {
    float edge[32*ES];
    float logit[8*32];
    float attnT[32*8];    // [m][h]
    float arH[8*36];      // [h][m] attn*rstd, tf32-rounded, stride 36
    float mean[32];
    float rstd[32];
    float s1[8];
    float qd[8];
    int   nbr[32];
};
struct AttnSmem {
    float wg[8*132];
    float swg[8];
    float beff2[8];
    float wfa[8];
    float lng[128];
    float lnb[128];
    AttnGroup grp[4];
};

#define GBAR(id) asm volatile("bar.sync %0, 128;" :: "r"(id) : "memory")

__global__ __launch_bounds__(512, 2)
void attn_kernel(const float* __restrict__ edge_feats,
                 const float* __restrict__ geo_feats,
                 const int*   __restrict__ nbr_idx,
                 const int*   __restrict__ masks,
                 const float* __restrict__ ln_e_g,
                 const float* __restrict__ ln_e_b,
                 const float* __restrict__ W_fa,
                 const float* __restrict__ b_fa,
                 float* __restrict__ out_geo)
{
    extern __shared__ char smraw[];
    AttnSmem& sm = *reinterpret_cast<AttnSmem*>(smraw);
    const int tid = threadIdx.x;

    for (int i = tid; i < 8*132; i += 512) sm.wg[i] = g_wg[i];
    if (tid < 128) { sm.lng[tid] = ln_e_g[tid]; sm.lnb[tid] = ln_e_b[tid]; }
    if (tid >= 128 && tid < 136) {
        int h = tid - 128;
        sm.swg[h] = g_swg[h]; sm.beff2[h] = g_beff2[h]; sm.wfa[h] = W_fa[h];
    }
    const float bfa = b_fa[0];
    __syncthreads();

    const int g     = tid >> 7;
    const int gtid  = tid & 127;
    const int glane = gtid & 31;
    const int gwarp = gtid >> 5;
    const int agid  = glane >> 2;    // mma group id (row)
    const int atig  = glane & 3;     // mma thread-in-group
    const int bid   = 1 + g;
    AttnGroup& G = sm.grp[g];

    for (int tok = 0; tok < 2; ++tok) {
        const int n = blockIdx.x*8 + g*2 + tok;

        // phase 1: edge load + fused row stats + nbr/qd
        {
            const float4* ep4 = (const float4*)(edge_feats + (size_t)n*4096);
            #pragma unroll
            for (int jj = 0; jj < 8; jj++) {
                int idx = gtid + 128*jj;
                int m = gwarp + 4*jj;
                float4 v = ep4[idx];
                *(float4*)&G.edge[m*ES + glane*4] = v;
                float s  = v.x + v.y + v.z + v.w;
                float s2 = v.x*v.x + v.y*v.y + v.z*v.z + v.w*v.w;
                #pragma unroll
                for (int o = 16; o; o >>= 1) {
                    s  += __shfl_xor_sync(0xffffffffu, s,  o);
                    s2 += __shfl_xor_sync(0xffffffffu, s2, o);
                }
                if (glane == 0) {
                    float mean = s*(1.f/128.f);
                    float rstd = rsqrtf(s2*(1.f/128.f) - mean*mean + 1e-5f);
                    G.mean[m] = mean; G.rstd[m] = rstd;
                }
            }
            if (gtid < 32) G.nbr[gtid] = nbr_idx[n*32 + gtid];
            if (gtid >= 32 && gtid < 40) G.qd[gtid-32] = g_qkv[(size_t)n*QS + 256 + gtid-32];
        }
        GBAR(bid);

        // phase 2: logits (LN folded; kd/msk direct from gmem)
        {
            int m0 = gtid >> 3, h = gtid & 7;
            int nb0 = G.nbr[m0], nb1 = G.nbr[m0 + 16];
            float kd0 = g_qkv[(size_t)nb0*QS + 264 + h];
            float kd1 = g_qkv[(size_t)nb1*QS + 264 + h];
            int mk0 = masks[n*32 + m0];
            int mk1 = masks[n*32 + m0 + 16];
            float d0 = 0.f, d1 = 0.f;
            const float4* e0 = (const float4*)&G.edge[m0*ES];
            const float4* e1 = (const float4*)&G.edge[(m0+16)*ES];
            const float4* wt = (const float4*)&sm.wg[h*132];
            #pragma unroll 8
            for (int c4 = 0; c4 < 32; c4++) {
                float4 w = wt[c4], x = e0[c4], y = e1[c4];
                d0 += x.x*w.x + x.y*w.y + x.z*w.z + x.w*w.w;
                d1 += y.x*w.x + y.y*w.y + y.z*w.z + y.w*w.w;
            }
            float base = G.qd[h] + sm.beff2[h];
            float sw = sm.swg[h];
            float a0 = base + kd0 + G.rstd[m0]   *(d0 - G.mean[m0]   *sw);
            float a1 = base + kd1 + G.rstd[m0+16]*(d1 - G.mean[m0+16]*sw);
            if (!mk0) a0 = -1e9f;
            if (!mk1) a1 = -1e9f;
            G.logit[h*32 + m0]      = a0;
            G.logit[h*32 + m0 + 16] = a1;
        }
        GBAR(bid);

        // phase 3: softmax + attnT/arH/s1
        {
            #pragma unroll
            for (int i = 0; i < 2; i++) {
                int h = gwarp + 4*i;
                float l = G.logit[h*32 + glane];
                float mx = l;
                #pragma unroll
                for (int o = 16; o; o >>= 1) mx = fmaxf(mx, __shfl_xor_sync(0xffffffffu, mx, o));
                float e = __expf(l - mx);
                float ss = e;
                #pragma unroll
                for (int o = 16; o; o >>= 1) ss += __shfl_xor_sync(0xffffffffu, ss, o);
                float a = e/ss;
                float arr = __uint_as_float(f2tf32(a*G.rstd[glane]));
                float s1p = arr*G.mean[glane];
                #pragma unroll
                for (int o = 16; o; o >>= 1) s1p += __shfl_xor_sync(0xffffffffu, s1p, o);
                G.attnT[glane*8 + h] = a;
                G.arH[h*36 + glane]  = arr;
                if (glane == 0) G.s1[h] = s1p;
            }
        }
        GBAR(bid);

        // phase 4a: scalar ctx (float2 gather)
        {
            int c = 2*gtid;
            int h = c >> 5;
            float ax = 0.f, ay = 0.f;
            #pragma unroll
            for (int m = 0; m < 32; m++) {
                const float* vrow = &g_qkv[(size_t)G.nbr[m]*QS];
                float2 v = *(const float2*)&vrow[c];
                float a = G.attnT[m*8 + h];
                ax += a*v.x; ay += a*v.y;
            }
            *(float2*)&g_hx[(size_t)n*HXS + c] = make_float2(ax, ay);
        }
        // phase 4b: ew via mma.sync (warp covers 32 cols)
        {
            float d[4][2];
            float z0 = 0.f, z1 = 0.f;
            #pragma unroll
            for (int t = 0; t < 4; t++) { d[t][0] = 0.f; d[t][1] = 0.f; }
            #pragma unroll
            for (int kt = 0; kt < 4; kt++) {
                uint32_t a0 = __float_as_uint(G.arH[agid*36 + kt*8 + atig]);
                uint32_t a2 = __float_as_uint(G.arH[agid*36 + kt*8 + 4 + atig]);
                #pragma unroll
                for (int t = 0; t < 4; t++) {
                    int n0 = gwarp*32 + t*8;
                    uint32_t b0 = f2tf32(G.edge[(kt*8 + atig    )*ES + n0 + agid]);
                    uint32_t b1 = f2tf32(G.edge[(kt*8 + atig + 4)*ES + n0 + agid]);
                    asm volatile(
                        "mma.sync.aligned.m16n8k8.row.col.f32.tf32.tf32.f32 "
                        "{%0,%1,%2,%3}, {%4,%5,%6,%7}, {%8,%9}, {%0,%1,%2,%3};"
                        : "+f"(d[t][0]), "+f"(d[t][1]), "+f"(z0), "+f"(z1)
                        : "r"(a0), "r"(0u), "r"(a2), "r"(0u), "r"(b0), "r"(b1));
                }
            }
            float s1h = G.s1[agid];
            #pragma unroll
            for (int t = 0; t < 4; t++) {
                int c0 = gwarp*32 + t*8 + 2*atig;
                float e0 = sm.lng[c0    ]*(d[t][0] - s1h) + sm.lnb[c0    ];
                float e1 = sm.lng[c0 + 1]*(d[t][1] - s1h) + sm.lnb[c0 + 1];
                *(float2*)&g_hx[(size_t)n*HXS + 256 + agid*128 + c0] = make_float2(e0, e1);
            }
        }
        // geo output (warp 3)
        if (gwarp == 3) {
            int m = glane;
            float aw = 0.f;
            #pragma unroll
            for (int h = 0; h < 8; h++) aw += G.attnT[m*8 + h]*sm.wfa[h];
            int nb = G.nbr[m];
            float p0 = aw*g_proj[nb*3 + 0];
            float p1 = aw*g_proj[nb*3 + 1];
            float p2 = aw*g_proj[nb*3 + 2];
            #pragma unroll
            for (int o = 16; o; o >>= 1) {
                p0 += __shfl_xor_sync(0xffffffffu, p0, o);
                p1 += __shfl_xor_sync(0xffffffffu, p1, o);
                p2 += __shfl_xor_sync(0xffffffffu, p2, o);
            }
            if (glane == 0) {
                int b = n >> 9;
                float ps[3] = {p0, p1, p2};
                float sd[3];
                #pragma unroll
                for (int j = 0; j < 3; j++)
                    sd[j] = 0.5f*(siluf(ps[j] + bfa) - siluf(-ps[j] + bfa));
                float gt = g_gate[n];
                #pragma unroll
                for (int i = 0; i < 3; i++) {
                    float gc = g_center[b*3 + i]
                             + sd[0]*g_V[b*9 + i*3 + 0]
                             + sd[1]*g_V[b*9 + i*3 + 1]
                             + sd[2]*g_V[b*9 + i*3 + 2];
                    out_geo[n*3 + i] = gc*gt + geo_feats[n*3 + i]*(1.f - gt);
                }
            }
        }
        GBAR(bid);
    }
}

// ---------------- launcher ----------------
extern "C" void kernel_launch(void* const* d_in, const int* in_sizes, int n_in,
                              void* d_out, int out_size)
{
    const float* token    = (const float*)d_in[0];
    const float* geo      = (const float*)d_in[1];
    const float* edge     = (const float*)d_in[2];
    const int*   nbr      = (const int*)d_in[3];
    const int*   mask     = (const int*)d_in[5];
    const float* ln_qkv_g = (const float*)d_in[6];
    const float* ln_qkv_b = (const float*)d_in[7];
    const float* W_qkv    = (const float*)d_in[8];
    const float* b_qkv    = (const float*)d_in[9];
    const float* ln_e_g   = (const float*)d_in[10];
    const float* ln_e_b   = (const float*)d_in[11];
    const float* W_qkv_e  = (const float*)d_in[12];
    const float* b_qkv_e  = (const float*)d_in[13];
    const float* w_attn   = (const float*)d_in[14];
    const float* w_edge   = (const float*)d_in[15];
    const float* W_gate   = (const float*)d_in[16];
    const float* b_gate   = (const float*)d_in[17];
    const float* W_fc1    = (const float*)d_in[18];
    const float* b_fc1    = (const float*)d_in[19];
    const float* ln_h_g   = (const float*)d_in[20];
    const float* ln_h_b   = (const float*)d_in[21];
    const float* W_fc2    = (const float*)d_in[22];
    const float* b_fc2    = (const float*)d_in[23];
    const float* W_fa     = (const float*)d_in[24];
    const float* b_fa     = (const float*)d_in[25];
    float* out = (float*)d_out;

    void* p;
    cudaGetSymbolAddress(&p, g_qkv);   float* p_qkv   = (float*)p;
    cudaGetSymbolAddress(&p, g_hx);    float* p_hx    = (float*)p;
    cudaGetSymbolAddress(&p, g_Wcomb); float* p_Wcomb = (float*)p;
    cudaGetSymbolAddress(&p, g_bcomb); float* p_bcomb = (float*)p;
    cudaGetSymbolAddress(&p, g_W1);    float* p_W1    = (float*)p;
    cudaGetSymbolAddress(&p, g_b1);    float* p_b1    = (float*)p;

    prep_kernel<<<64, 256>>>(W_qkv, b_qkv, w_attn, W_qkv_e, b_qkv_e, w_edge,
                             W_fc1, b_fc1, ln_e_g, ln_e_b);
    geom_kernel<<<16, 256>>>(geo);

    {
        constexpr int SM = (64*260 + 3*32*292)*sizeof(float);
        cudaFuncSetAttribute((const void*)gemm_qkv_f,
                             cudaFuncAttributeMaxDynamicSharedMemorySize, SM);
        gemm_qkv_f<<<128, 512, SM>>>(token, p_Wcomb, p_bcomb,
                                     W_gate, b_gate, ln_qkv_g, ln_qkv_b, p_qkv);
    }

    cudaFuncSetAttribute(attn_kernel, cudaFuncAttributeMaxDynamicSharedMemorySize,
                         (int)sizeof(AttnSmem));
    attn_kernel<<<1024, 512, sizeof(AttnSmem)>>>(
        edge, geo, nbr, mask, ln_e_g, ln_e_b, W_fa, b_fa,
        out + (size_t)NTOK*256);

    {
        constexpr int SM = (64*260 + 3*32*260)*sizeof(float);
        cudaFuncSetAttribute((const void*)gemm_fc12,
                             cudaFuncAttributeMaxDynamicSharedMemorySize, SM);
        gemm_fc12<<<128, 512, SM>>>(p_hx, p_W1, p_b1, W_fc2, b_fc2,
                                    token, ln_h_g, ln_h_b, out);
    }
}

// round 12
// speedup vs baseline: 1.3140x; 1.0910x over previous
#include <cuda_runtime.h>
#include <math.h>
#include <stdint.h>

#define NTOK 8192
#define QS 288            // qkv row stride: 256 v | 8 qdot | 8 kdot | pad
#define ES 132            // edge smem row stride (floats)
#define HXS 1280          // hx row stride: 256 scalar ctx | 1024 ew
#define LPS 9             // logitP row stride

// ---------------- device scratch ----------------
__device__ float g_qkv[NTOK*QS];
__device__ float g_hx[NTOK*HXS];
__device__ float g_gate[NTOK];
__device__ float g_proj[NTOK*3];
__device__ float g_center[16*3];
__device__ float g_V[16*9];
__device__ float g_Wcomb[256*QS];
__device__ float g_bcomb[QS];
__device__ float g_wgT[128*8];      // [c][h]: tf32(lng[c]*weff[c][h])
__device__ float g_swg[8];
__device__ float g_beff2[8];
__device__ float g_W1[HXS*256];     // folded fc1 weight: [1280, 256]
__device__ float g_b1[256];         // folded fc1 bias

__device__ __forceinline__ float siluf(float x){ return x/(1.f+__expf(-x)); }
__device__ __forceinline__ uint32_t f2tf32(float x){
    uint32_t u; asm("cvt.rna.tf32.f32 %0, %1;" : "=r"(u) : "f"(x)); return u;
}
__device__ __forceinline__ float tf32f(float x){ return __uint_as_float(f2tf32(x)); }

#define CP_ASYNC16(dst, src) \
    asm volatile("cp.async.ca.shared.global [%0], [%1], 16;\n" :: "r"(dst), "l"(src))
#define CP_COMMIT() asm volatile("cp.async.commit_group;\n" ::: "memory")
#define CP_WAIT2()  asm volatile("cp.async.wait_group 2;\n" ::: "memory")
#define CP_WAIT1()  asm volatile("cp.async.wait_group 1;\n" ::: "memory")
#define CP_WAIT0()  asm volatile("cp.async.wait_group 0;\n" ::: "memory")

__device__ __forceinline__ uint32_t sptr(const void* p){
    return (uint32_t)__cvta_generic_to_shared(p);
}

// ---------------- prep: fold effective weights ----------------
__global__ void prep_kernel(const float* __restrict__ W_qkv, const float* __restrict__ b_qkv,
                            const float* __restrict__ w_attn,
                            const float* __restrict__ W_qkv_e, const float* __restrict__ b_qkv_e,
                            const float* __restrict__ w_edge,
                            const float* __restrict__ W_fc1, const float* __restrict__ b_fc1,
                            const float* __restrict__ ln_e_g, const float* __restrict__ ln_e_b)
{
    int gid = blockIdx.x*blockDim.x + threadIdx.x;
    int gstride = gridDim.x*blockDim.x;
    for (int idx = gid; idx < 256*QS; idx += gstride) {
        int c = idx / QS, j = idx - c*QS;
        float w = 0.f;
        if (j < 256) {
            w = W_qkv[c*768 + 512 + j];
        } else if (j < 264) {
            int h = j - 256; float s = 0.f;
            #pragma unroll
            for (int d = 0; d < 32; d++) s += W_qkv[c*768 + h*32 + d]*w_attn[d];
            w = s;
        } else if (j < 272) {
            int h = j - 264; float s = 0.f;
            #pragma unroll
            for (int d = 0; d < 32; d++) s += W_qkv[c*768 + 256 + h*32 + d]*w_attn[d];
            w = s;
        }
        g_Wcomb[idx] = w;
    }
    for (int idx = gid; idx < HXS*256; idx += gstride) {
        int j = idx >> 8, o = idx & 255;
        float w;
        if (j < 256) {
            w = W_fc1[j*256 + o];
        } else {
            int hc = j - 256, h = hc >> 7, c = hc & 127;
            float s = 0.f;
            #pragma unroll
            for (int jp = 0; jp < 16; jp++)
                s += W_qkv_e[c*256 + 128 + h*16 + jp]*W_fc1[(256 + h*16 + jp)*256 + o];
            w = s;
        }
        g_W1[idx] = w;
    }
    if (blockIdx.x == 0) {
        for (int j = threadIdx.x; j < QS; j += blockDim.x) {
            float bv = 0.f;
            if (j < 256) bv = b_qkv[512 + j];
            else if (j < 264) { int h = j-256; for (int d=0; d<32; d++) bv += b_qkv[h*32+d]*w_attn[d]; }
            else if (j < 272) { int h = j-264; for (int d=0; d<32; d++) bv += b_qkv[256 + h*32+d]*w_attn[d]; }
            g_bcomb[j] = bv;
        }
    }
    if (blockIdx.x == 1) {
        __shared__ float swgt[128*8];
        __shared__ float sweff[128*8];
        for (int idx = threadIdx.x; idx < 128*8; idx += blockDim.x) {
            int c = idx >> 3, h = idx & 7; float s = 0.f;
            #pragma unroll
            for (int e = 0; e < 16; e++) s += W_qkv_e[c*256 + h*16 + e]*w_edge[e];
            sweff[idx] = s;
            float wt = tf32f(ln_e_g[c]*s);
            swgt[c*8 + h] = wt;
            g_wgT[c*8 + h] = wt;
        }
        __syncthreads();
        if (threadIdx.x < 8) {
            int h = threadIdx.x;
            float sw = 0.f, b2 = 0.f;
            for (int c = 0; c < 128; c++) {
                sw += swgt[c*8 + h];
                b2 += ln_e_b[c]*sweff[c*8 + h];
            }
            for (int e = 0; e < 16; e++) b2 += b_qkv_e[h*16 + e]*w_edge[e];
            g_swg[h] = sw; g_beff2[h] = b2;
        }
    }
    if (blockIdx.x == 2 && threadIdx.x < 256) {
        int o = threadIdx.x;
        float s = b_fc1[o];
        for (int j = 0; j < 128; j++)
            s += b_qkv_e[128 + j]*W_fc1[(256 + j)*256 + o];
        g_b1[o] = s;
    }
}

// ---------------- per-graph geometry (fp32 Jacobi) ----------------
__device__ void jacobi3f(float a00,float a01,float a02,float a11,float a12,float a22,
                         float V[3][3])
{
    float A[3][3] = {{a00,a01,a02},{a01,a11,a12},{a02,a12,a22}};
    V[0][0]=1; V[0][1]=0; V[0][2]=0;
    V[1][0]=0; V[1][1]=1; V[1][2]=0;
    V[2][0]=0; V[2][1]=0; V[2][2]=1;
    float tr = fabsf(a00)+fabsf(a11)+fabsf(a22);
    for (int it = 0; it < 40; ++it) {
        int p = 0, q = 1; float mx = fabsf(A[0][1]);
        if (fabsf(A[0][2]) > mx) { mx = fabsf(A[0][2]); p = 0; q = 2; }
        if (fabsf(A[1][2]) > mx) { mx = fabsf(A[1][2]); p = 1; q = 2; }
        if (mx <= 1e-8f*tr) break;
        float apq = A[p][q];
        float theta = (A[q][q]-A[p][p])/(2.0f*apq);
        float t = 1.0f/(fabsf(theta)+sqrtf(theta*theta+1.0f));
        if (theta < 0) t = -t;
        float c = rsqrtf(t*t+1.0f), s = t*c;
        for (int k = 0; k < 3; k++) { float akp=A[k][p], akq=A[k][q]; A[k][p]=c*akp-s*akq; A[k][q]=s*akp+c*akq; }
        for (int k = 0; k < 3; k++) { float apk=A[p][k], aqk=A[q][k]; A[p][k]=c*apk-s*aqk; A[q][k]=s*apk+c*aqk; }
        for (int k = 0; k < 3; k++) { float vkp=V[k][p], vkq=V[k][q]; V[k][p]=c*vkp-s*vkq; V[k][q]=s*vkp+c*vkq; }
    }
}

__global__ void geom_kernel(const float* __restrict__ geo)
{
    __shared__ double sred[8][9];
    __shared__ double sCd[3];
    __shared__ float sV[9], sC[3];
    int b = blockIdx.x, tid = threadIdx.x, lane = tid & 31, warp = tid >> 5;
    const float* G = geo + (size_t)b*512*3;

    {
        double s[3] = {0,0,0};
        for (int p = tid; p < 512; p += 256) { s[0] += G[p*3]; s[1] += G[p*3+1]; s[2] += G[p*3+2]; }
        #pragma unroll
        for (int k = 0; k < 3; k++)
            #pragma unroll
            for (int o = 16; o; o >>= 1) s[k] += __shfl_xor_sync(0xffffffffu, s[k], o);
        if (lane == 0) { sred[warp][0]=s[0]; sred[warp][1]=s[1]; sred[warp][2]=s[2]; }
    }
    __syncthreads();
    if (tid == 0) {
        for (int k = 0; k < 3; k++) {
            double t = 0; for (int w = 0; w < 8; w++) t += sred[w][k];
            sCd[k] = t/512.0;
        }
    }
    __syncthreads();
    double c0 = sCd[0], c1 = sCd[1], c2 = sCd[2];

    {
        double m[6] = {0,0,0,0,0,0};
        for (int p = tid; p < 512; p += 256) {
            double dx = G[p*3]-c0, dy = G[p*3+1]-c1, dz = G[p*3+2]-c2;
            m[0] += dx*dx; m[1] += dx*dy; m[2] += dx*dz;
            m[3] += dy*dy; m[4] += dy*dz; m[5] += dz*dz;
        }
        #pragma unroll
        for (int k = 0; k < 6; k++)
            #pragma unroll
            for (int o = 16; o; o >>= 1) m[k] += __shfl_xor_sync(0xffffffffu, m[k], o);
        if (lane == 0) for (int k = 0; k < 6; k++) sred[warp][k] = m[k];
    }
    __syncthreads();
    if (tid == 0) {
        double m[6];
        for (int k = 0; k < 6; k++) { double t=0; for (int w=0; w<8; w++) t += sred[w][k]; m[k]=t; }
        float V[3][3];
        jacobi3f((float)m[0],(float)m[1],(float)m[2],(float)m[3],(float)m[4],(float)m[5], V);
        for (int i = 0; i < 3; i++)
            for (int j = 0; j < 3; j++) { sV[i*3+j] = V[i][j]; g_V[b*9+i*3+j] = V[i][j]; }
        sC[0]=(float)c0; sC[1]=(float)c1; sC[2]=(float)c2;
        g_center[b*3+0]=(float)c0; g_center[b*3+1]=(float)c1; g_center[b*3+2]=(float)c2;
    }
    __syncthreads();

    for (int p = tid; p < 512; p += 256) {
        int t = b*512 + p;
        float dx = G[p*3]-sC[0], dy = G[p*3+1]-sC[1], dz = G[p*3+2]-sC[2];
        for (int d = 0; d < 3; d++)
            g_proj[t*3+d] = dx*sV[0*3+d] + dy*sV[1*3+d] + dz*sV[2*3+d];
    }
}

// ---------------- qkv GEMM: BM=64, A resident + fused LN/gate, B 3-stage cp.async ----------------
__global__ __launch_bounds__(512)
void gemm_qkv_f(const float* __restrict__ X,
                const float* __restrict__ Bw,
                const float* __restrict__ bias,
                const float* __restrict__ Wg, const float* __restrict__ bg,
                const float* __restrict__ lng, const float* __restrict__ lnb,
                float* __restrict__ C)
{
    constexpr int K = 256, N = QS;
    constexpr int AS = 260, BS = 292;
    constexpr int ASZ = 64*AS, BSZ = 32*BS;
    constexpr int KT = K/32, WN = N/4, NT = WN/8, CT = N/32;
    extern __shared__ float smem[];
    float* sA = smem;
    float* sBst = smem + ASZ;
    const int tid = threadIdx.x, lane = tid & 31, warp = tid >> 5;
    const int wr = warp >> 2, wc = warp & 3;
    const int gid = lane >> 2, tig = lane & 3;
    const int rowBase = blockIdx.x*64;

    auto issueB = [&](int kt) {
        float* dB = sBst + (kt % 3)*BSZ;
        #pragma unroll
        for (int jj = 0; jj < 5; jj++) {
            int idx = tid + 512*jj;
            if (idx < 32*72) {
                int r = idx/72, c4 = idx - r*72;
                CP_ASYNC16(sptr(&dB[r*BS + c4*4]),
                           &Bw[(size_t)(kt*32 + r)*N + c4*4]);
            }
        }
        CP_COMMIT();
    };

    {
        #pragma unroll
        for (int jj = 0; jj < 8; jj++) {
            int idx = tid + 512*jj;
            int r = idx >> 6, c4 = idx & 63;
            CP_ASYNC16(sptr(&sA[r*AS + c4*4]),
                       &X[(size_t)(rowBase + r)*K + c4*4]);
        }
        CP_COMMIT();
    }
    issueB(0);
    issueB(1);

    CP_WAIT2();
    __syncthreads();

    #pragma unroll
    for (int rr = 0; rr < 4; rr++) {
        int row = warp*4 + rr;
        float v[8]; float s = 0.f, s2 = 0.f, gd = 0.f;
        #pragma unroll
        for (int j = 0; j < 8; j++) {
            int c = lane + 32*j;
            float t = sA[row*AS + c];
            v[j] = t; s += t; s2 += t*t; gd += t*Wg[c];
        }
        #pragma unroll
        for (int o = 16; o; o >>= 1) {
            s  += __shfl_xor_sync(0xffffffffu, s,  o);
            s2 += __shfl_xor_sync(0xffffffffu, s2, o);
            gd += __shfl_xor_sync(0xffffffffu, gd, o);
        }
        float mean = s*(1.f/256.f);
        float rstd = rsqrtf(s2*(1.f/256.f) - mean*mean + 1e-5f);
        #pragma unroll
        for (int j = 0; j < 8; j++) {
            int c = lane + 32*j;
            sA[row*AS + c] = (v[j]-mean)*rstd*lng[c] + lnb[c];
        }
        if (lane == 0) g_gate[rowBase + row] = 1.f/(1.f + __expf(-(gd + bg[0])));
    }
    __syncthreads();

    float acc[NT][4];
    #pragma unroll
    for (int t = 0; t < NT; t++) {
        int j0 = wc*WN + t*8 + tig*2;
        acc[t][0] = bias[j0];   acc[t][1] = bias[j0+1];
        acc[t][2] = bias[j0];   acc[t][3] = bias[j0+1];
    }

    for (int kt = 0; kt < KT; ++kt) {
        if (kt + 1 < KT) CP_WAIT1(); else CP_WAIT0();
        __syncthreads();
        if (kt + 2 < KT) issueB(kt + 2);
        const float* sB = sBst + (kt % 3)*BSZ;
        #pragma unroll
        for (int kk = 0; kk < 4; kk++) {
            int kc = kt*32 + kk*8;
            uint32_t a0 = __float_as_uint(sA[(wr*16 + gid    )*AS + kc + tig    ]);
            uint32_t a1 = __float_as_uint(sA[(wr*16 + gid + 8)*AS + kc + tig    ]);
            uint32_t a2 = __float_as_uint(sA[(wr*16 + gid    )*AS + kc + tig + 4]);
            uint32_t a3 = __float_as_uint(sA[(wr*16 + gid + 8)*AS + kc + tig + 4]);
            #pragma unroll
            for (int t = 0; t < NT; t++) {
                int n0 = wc*WN + t*8;
                uint32_t b0 = __float_as_uint(sB[(kk*8 + tig    )*BS + n0 + gid]);
                uint32_t b1 = __float_as_uint(sB[(kk*8 + tig + 4)*BS + n0 + gid]);
                asm volatile(
                    "mma.sync.aligned.m16n8k8.row.col.f32.tf32.tf32.f32 "
                    "{%0,%1,%2,%3}, {%4,%5,%6,%7}, {%8,%9}, {%0,%1,%2,%3};"
                    : "+f"(acc[t][0]), "+f"(acc[t][1]), "+f"(acc[t][2]), "+f"(acc[t][3])
                    : "r"(a0), "r"(a1), "r"(a2), "r"(a3), "r"(b0), "r"(b1));
            }
        }
    }

    float* sC = sBst;
    __syncthreads();
    #pragma unroll
    for (int t = 0; t < NT; t++) {
        int n0 = wc*WN + t*8 + tig*2;
        int r0 = wr*16 + gid;
        sC[ r0     *BS + n0    ] = acc[t][0];
        sC[ r0     *BS + n0 + 1] = acc[t][1];
        sC[(r0 + 8)*BS + n0    ] = acc[t][2];
        sC[(r0 + 8)*BS + n0 + 1] = acc[t][3];
    }
    __syncthreads();
    #pragma unroll
    for (int rr = 0; rr < 4; rr++) {
        int row = warp*4 + rr;
        int grow = rowBase + row;
        #pragma unroll
        for (int j = 0; j < CT; j++) {
            int col = lane + 32*j;
            C[(size_t)grow*N + col] = sC[row*BS + col];
        }
    }
}

// ---------------- fused fc1(gelu+LN)+fc2(+residual) ----------------
__global__ __launch_bounds__(512)
void gemm_fc12(const float* __restrict__ A,
               const float* __restrict__ W1,
               const float* __restrict__ b1,
               const float* __restrict__ W2,
               const float* __restrict__ b2,
               const float* __restrict__ token,
               const float* __restrict__ lnhg, const float* __restrict__ lnhb,
               float* __restrict__ out)
{
    constexpr int N = 256, K1 = HXS, K2 = 256;
    constexpr int KT1 = K1/32, KT2 = K2/32;
    constexpr int SA = 36, BS = N + 4;
    constexpr int ASZ = 64*SA, BSZ = 32*BS, STG1 = ASZ + BSZ;
    constexpr int SCSZ = 64*BS;
    constexpr int OFF2 = SCSZ;
    constexpr int NT = 8, CT = N/32;
    extern __shared__ float smem[];
    const int tid = threadIdx.x, lane = tid & 31, warp = tid >> 5;
    const int wr = warp >> 2, wc = warp & 3;
    const int gid = lane >> 2, tig = lane & 3;
    const int rowBase = blockIdx.x*64;
    const int ar = tid >> 3, ac4 = tid & 7;

    auto issueA = [&](int kt) {
        float* dA = smem + (kt % 3)*STG1;
        float* dB = dA + ASZ;
        CP_ASYNC16(sptr(&dA[ar*SA + ac4*4]),
                   &A[(size_t)(rowBase + ar)*K1 + kt*32 + ac4*4]);
        #pragma unroll
        for (int jj = 0; jj < 4; jj++) {
            int idx = tid + 512*jj;
            int r = idx >> 6, c4 = idx & 63;
            CP_ASYNC16(sptr(&dB[r*BS + c4*4]),
                       &W1[(size_t)(kt*32 + r)*N + c4*4]);
        }
        CP_COMMIT();
    };
    auto issueB = [&](int kt) {
        float* dB = smem + OFF2 + (kt % 3)*BSZ;
        #pragma unroll
        for (int jj = 0; jj < 4; jj++) {
            int idx = tid + 512*jj;
            int r = idx >> 6, c4 = idx & 63;
            CP_ASYNC16(sptr(&dB[r*BS + c4*4]),
                       &W2[(size_t)(kt*32 + r)*N + c4*4]);
        }
        CP_COMMIT();
    };

    issueA(0);
    issueA(1);

    float acc[NT][4];
    #pragma unroll
    for (int t = 0; t < NT; t++) {
        int j0 = wc*64 + t*8 + tig*2;
        acc[t][0] = b1[j0];   acc[t][1] = b1[j0+1];
        acc[t][2] = b1[j0];   acc[t][3] = b1[j0+1];
    }

    for (int kt = 0; kt < KT1; ++kt) {
        if (kt + 1 < KT1) CP_WAIT1(); else CP_WAIT0();
        __syncthreads();
        if (kt + 2 < KT1) issueA(kt + 2);
        const float* sA = smem + (kt % 3)*STG1;
        const float* sB = sA + ASZ;
        #pragma unroll
        for (int kk = 0; kk < 4; kk++) {
            uint32_t a0 = __float_as_uint(sA[(wr*16 + gid    )*SA + kk*8 + tig    ]);
            uint32_t a1 = __float_as_uint(sA[(wr*16 + gid + 8)*SA + kk*8 + tig    ]);
            uint32_t a2 = __float_as_uint(sA[(wr*16 + gid    )*SA + kk*8 + tig + 4]);
            uint32_t a3 = __float_as_uint(sA[(wr*16 + gid + 8)*SA + kk*8 + tig + 4]);
            #pragma unroll
            for (int t = 0; t < NT; t++) {
                int n0 = wc*64 + t*8;
                uint32_t b0 = __float_as_uint(sB[(kk*8 + tig    )*BS + n0 + gid]);
                uint32_t b1v = __float_as_uint(sB[(kk*8 + tig + 4)*BS + n0 + gid]);
                asm volatile(
                    "mma.sync.aligned.m16n8k8.row.col.f32.tf32.tf32.f32 "
                    "{%0,%1,%2,%3}, {%4,%5,%6,%7}, {%8,%9}, {%0,%1,%2,%3};"
                    : "+f"(acc[t][0]), "+f"(acc[t][1]), "+f"(acc[t][2]), "+f"(acc[t][3])
                    : "r"(a0), "r"(a1), "r"(a2), "r"(a3), "r"(b0), "r"(b1v));
            }
        }
    }

    __syncthreads();
    issueB(0);
    issueB(1);

    float* sC = smem;
    #pragma unroll
    for (int t = 0; t < NT; t++) {
        int n0 = wc*64 + t*8 + tig*2;
        int r0 = wr*16 + gid;
        sC[ r0     *BS + n0    ] = acc[t][0];
        sC[ r0     *BS + n0 + 1] = acc[t][1];
        sC[(r0 + 8)*BS + n0    ] = acc[t][2];
        sC[(r0 + 8)*BS + n0 + 1] = acc[t][3];
    }
    __syncthreads();
    #pragma unroll
    for (int rr = 0; rr < 4; rr++) {
        int row = warp*4 + rr;
        float v[CT]; float s = 0.f, s2 = 0.f;
        #pragma unroll
        for (int j = 0; j < CT; j++) {
            float x = sC[row*BS + lane + 32*j];
            x = 0.5f*x*(1.f + erff(x*0.70710678118654752f));
            v[j] = x; s += x; s2 += x*x;
        }
        #pragma unroll
        for (int o = 16; o; o >>= 1) {
            s  += __shfl_xor_sync(0xffffffffu, s,  o);
            s2 += __shfl_xor_sync(0xffffffffu, s2, o);
        }
        float mean = s*(1.f/256.f);
        float rstd = rsqrtf(s2*(1.f/256.f) - mean*mean + 1e-5f);
        #pragma unroll
        for (int j = 0; j < CT; j++) {
            int col = lane + 32*j;
            sC[row*BS + col] = (v[j]-mean)*rstd*lnhg[col] + lnhb[col];
        }
    }
    __syncthreads();

    float acc2[NT][4];
    #pragma unroll
    for (int t = 0; t < NT; t++) {
        int j0 = wc*64 + t*8 + tig*2;
        acc2[t][0] = b2[j0];   acc2[t][1] = b2[j0+1];
        acc2[t][2] = b2[j0];   acc2[t][3] = b2[j0+1];
    }
    for (int kt = 0; kt < KT2; ++kt) {
        if (kt + 1 < KT2) CP_WAIT1(); else CP_WAIT0();
        __syncthreads();
        if (kt + 2 < KT2) issueB(kt + 2);
        const float* sB = smem + OFF2 + (kt % 3)*BSZ;
        #pragma unroll
        for (int kk = 0; kk < 4; kk++) {
            int kc = kt*32 + kk*8;
            uint32_t a0 = __float_as_uint(sC[(wr*16 + gid    )*BS + kc + tig    ]);
            uint32_t a1 = __float_as_uint(sC[(wr*16 + gid + 8)*BS + kc + tig    ]);
            uint32_t a2 = __float_as_uint(sC[(wr*16 + gid    )*BS + kc + tig + 4]);
            uint32_t a3 = __float_as_uint(sC[(wr*16 + gid + 8)*BS + kc + tig + 4]);
            #pragma unroll
            for (int t = 0; t < NT; t++) {
                int n0 = wc*64 + t*8;
                uint32_t b0 = __float_as_uint(sB[(kk*8 + tig    )*BS + n0 + gid]);
                uint32_t b1v = __float_as_uint(sB[(kk*8 + tig + 4)*BS + n0 + gid]);
                asm volatile(
                    "mma.sync.aligned.m16n8k8.row.col.f32.tf32.tf32.f32 "
                    "{%0,%1,%2,%3}, {%4,%5,%6,%7}, {%8,%9}, {%0,%1,%2,%3};"
                    : "+f"(acc2[t][0]), "+f"(acc2[t][1]), "+f"(acc2[t][2]), "+f"(acc2[t][3])
                    : "r"(a0), "r"(a1), "r"(a2), "r"(a3), "r"(b0), "r"(b1v));
            }
        }
    }

    float* sO = smem + OFF2;
    __syncthreads();
    #pragma unroll
    for (int t = 0; t < NT; t++) {
        int n0 = wc*64 + t*8 + tig*2;
        int r0 = wr*16 + gid;
        sO[ r0     *BS + n0    ] = acc2[t][0];
        sO[ r0     *BS + n0 + 1] = acc2[t][1];
        sO[(r0 + 8)*BS + n0    ] = acc2[t][2];
        sO[(r0 + 8)*BS + n0 + 1] = acc2[t][3];
    }
    __syncthreads();
    #pragma unroll
    for (int rr = 0; rr < 4; rr++) {
        int row = warp*4 + rr;
        int grow = rowBase + row;
        #pragma unroll
        for (int j = 0; j < CT; j++) {
            int col = lane + 32*j;
            out[(size_t)grow*256 + col] = sO[row*BS + col] + token[(size_t)grow*256 + col];
        }
    }
}

// ---------------- fused per-token attention: logits AND ew via tensor cores ----------------
struct AttnGroup {
    float edge[32*ES];    // tf32-rounded edge rows
    float logitP[2*32*LPS];
    float attnT[32*8];    // [m][h]
    float arH[8*36];      // [h][m] attn*rstd, tf32-rounded
    float mean[32];
    float rstd[32];
    float s1[8];
    float qd[8];
    int   nbr[32];
};
struct AttnSmem {
    float wgT[128*8];     // [c][h] tf32
    float swg[8];
    float beff2[8];
    float wfa[8];
    float lng[128];
    float lnb[128];
    AttnGroup grp[4];
};

#define GBAR(id) asm volatile("bar.sync %0, 128;" :: "r"(id) : "memory")

__global__ __launch_bounds__(512, 2)
void attn_kernel(const float* __restrict__ edge_feats,
                 const float* __restrict__ geo_feats,
                 const int*   __restrict__ nbr_idx,
                 const int*   __restrict__ masks,
                 const float* __restrict__ ln_e_g,
                 const float* __restrict__ ln_e_b,
                 const float* __restrict__ W_fa,
                 const float* __restrict__ b_fa,
                 float* __restrict__ out_geo)
{
    extern __shared__ char smraw[];
    AttnSmem& sm = *reinterpret_cast<AttnSmem*>(smraw);
    const int tid = threadIdx.x;

    for (int i = tid; i < 128*8; i += 512) sm.wgT[i] = g_wgT[i];
    if (tid < 128) { sm.lng[tid] = ln_e_g[tid]; sm.lnb[tid] = ln_e_b[tid]; }
    if (tid >= 128 && tid < 136) {
        int h = tid - 128;
        sm.swg[h] = g_swg[h]; sm.beff2[h] = g_beff2[h]; sm.wfa[h] = W_fa[h];
    }
    const float bfa = b_fa[0];
    __syncthreads();

    const int g     = tid >> 7;
    const int gtid  = tid & 127;
    const int glane = gtid & 31;
    const int gwarp = gtid >> 5;
    const int agid  = glane >> 2;
    const int atig  = glane & 3;
    const int bid   = 1 + g;
    AttnGroup& G = sm.grp[g];

    for (int tok = 0; tok < 2; ++tok) {
        const int n = blockIdx.x*8 + g*2 + tok;

        // phase 1: edge load (tf32-rounded) + row stats + nbr/qd
        {
            const float4* ep4 = (const float4*)(edge_feats + (size_t)n*4096);
            #pragma unroll
            for (int jj = 0; jj < 8; jj++) {
                int idx = gtid + 128*jj;
                int m = gwarp + 4*jj;
                float4 v = ep4[idx];
                v.x = tf32f(v.x); v.y = tf32f(v.y); v.z = tf32f(v.z); v.w = tf32f(v.w);
                *(float4*)&G.edge[m*ES + glane*4] = v;
                float s  = v.x + v.y + v.z + v.w;
                float s2 = v.x*v.x + v.y*v.y + v.z*v.z + v.w*v.w;
                #pragma unroll
                for (int o = 16; o; o >>= 1) {
                    s  += __shfl_xor_sync(0xffffffffu, s,  o);
                    s2 += __shfl_xor_sync(0xffffffffu, s2, o);
                }
                if (glane == 0) {
                    float mean = s*(1.f/128.f);
                    float rstd = rsqrtf(s2*(1.f/128.f) - mean*mean + 1e-5f);
                    G.mean[m] = mean; G.rstd[m] = rstd;
                }
            }
            if (gtid < 32) G.nbr[gtid] = nbr_idx[n*32 + gtid];
            if (gtid >= 32 && gtid < 40) G.qd[gtid-32] = g_qkv[(size_t)n*QS + 256 + gtid-32];
        }
        GBAR(bid);

        // phase 2: logit dots via mma — warp = (m-half, k-half)
        {
            const int m0  = (gwarp & 1)*16;
            const int kc0 = (gwarp >> 1)*64;
            float d0 = 0.f, d1 = 0.f, d2 = 0.f, d3 = 0.f;
            #pragma unroll
            for (int kk = 0; kk < 8; kk++) {
                int kc = kc0 + kk*8;
                uint32_t a0 = __float_as_uint(G.edge[(m0 + agid    )*ES + kc + atig    ]);
                uint32_t a1 = __float_as_uint(G.edge[(m0 + agid + 8)*ES + kc + atig    ]);
                uint32_t a2 = __float_as_uint(G.edge[(m0 + agid    )*ES + kc + atig + 4]);
                uint32_t a3 = __float_as_uint(G.edge[(m0 + agid + 8)*ES + kc + atig + 4]);
                uint32_t b0 = __float_as_uint(sm.wgT[(kc + atig    )*8 + agid]);
                uint32_t b1 = __float_as_uint(sm.wgT[(kc + atig + 4)*8 + agid]);
                asm volatile(
                    "mma.sync.aligned.m16n8k8.row.col.f32.tf32.tf32.f32 "
                    "{%0,%1,%2,%3}, {%4,%5,%6,%7}, {%8,%9}, {%0,%1,%2,%3};"
                    : "+f"(d0), "+f"(d1), "+f"(d2), "+f"(d3)
                    : "r"(a0), "r"(a1), "r"(a2), "r"(a3), "r"(b0), "r"(b1));
            }
            float* lp = &G.logitP[(gwarp >> 1)*32*LPS];
            lp[(m0 + agid    )*LPS + 2*atig    ] = d0;
            lp[(m0 + agid    )*LPS + 2*atig + 1] = d1;
            lp[(m0 + agid + 8)*LPS + 2*atig    ] = d2;
            lp[(m0 + agid + 8)*LPS + 2*atig + 1] = d3;
        }
        GBAR(bid);

        // phase 3: logits assembly + softmax + attnT/arH/s1 (warp: 2 heads)
        {
            int m = glane;
            float rst = G.rstd[m], mn = G.mean[m];
            int nb = G.nbr[m];
            int mk = masks[n*32 + m];
            #pragma unroll
            for (int i = 0; i < 2; i++) {
                int h = gwarp + 4*i;
                float dot = G.logitP[m*LPS + h] + G.logitP[32*LPS + m*LPS + h];
                float kd = g_qkv[(size_t)nb*QS + 264 + h];
                float l = G.qd[h] + sm.beff2[h] + kd + rst*(dot - mn*sm.swg[h]);
                if (!mk) l = -1e9f;
                float mx = l;
                #pragma unroll
                for (int o = 16; o; o >>= 1) mx = fmaxf(mx, __shfl_xor_sync(0xffffffffu, mx, o));
                float e = __expf(l - mx);
                float ss = e;
                #pragma unroll
                for (int o = 16; o; o >>= 1) ss += __shfl_xor_sync(0xffffffffu, ss, o);
                float a = e/ss;
                float arr = __uint_as_float(f2tf32(a*rst));
                float s1p = arr*mn;
                #pragma unroll
                for (int o = 16; o; o >>= 1) s1p += __shfl_xor_sync(0xffffffffu, s1p, o);
                G.attnT[m*8 + h] = a;
                G.arH[h*36 + m]  = arr;
                if (glane == 0) G.s1[h] = s1p;
            }
        }
        GBAR(bid);

        // phase 4a: scalar ctx (float2 gather)
        {
            int c = 2*gtid;
            int h = c >> 5;
            float ax = 0.f, ay = 0.f;
            #pragma unroll
            for (int m = 0; m < 32; m++) {
                const float* vrow = &g_qkv[(size_t)G.nbr[m]*QS];
                float2 v = *(const float2*)&vrow[c];
                float a = G.attnT[m*8 + h];
                ax += a*v.x; ay += a*v.y;
            }
            *(float2*)&g_hx[(size_t)n*HXS + c] = make_float2(ax, ay);
        }
        // phase 4b: ew via mma.sync (warp covers 32 cols)
        {
            float d[4][2];
            float z0 = 0.f, z1 = 0.f;
            #pragma unroll
            for (int t = 0; t < 4; t++) { d[t][0] = 0.f; d[t][1] = 0.f; }
            #pragma unroll
            for (int kt = 0; kt < 4; kt++) {
                uint32_t a0 = __float_as_uint(G.arH[agid*36 + kt*8 + atig]);
                uint32_t a2 = __float_as_uint(G.arH[agid*36 + kt*8 + 4 + atig]);
                #pragma unroll
                for (int t = 0; t < 4; t++) {
                    int n0 = gwarp*32 + t*8;
                    uint32_t b0 = __float_as_uint(G.edge[(kt*8 + atig    )*ES + n0 + agid]);
                    uint32_t b1 = __float_as_uint(G.edge[(kt*8 + atig + 4)*ES + n0 + agid]);
                    asm volatile(
                        "mma.sync.aligned.m16n8k8.row.col.f32.tf32.tf32.f32 "
                        "{%0,%1,%2,%3}, {%4,%5,%6,%7}, {%8,%9}, {%0,%1,%2,%3};"
                        : "+f"(d[t][0]), "+f"(d[t][1]), "+f"(z0), "+f"(z1)
                        : "r"(a0), "r"(0u), "r"(a2), "r"(0u), "r"(b0), "r"(b1));
                }
            }
            float s1h = G.s1[agid];
            #pragma unroll
            for (int t = 0; t < 4; t++) {
                int c0 = gwarp*32 + t*8 + 2*atig;
                float e0 = sm.lng[c0    ]*(d[t][0] - s1h) + sm.lnb[c0    ];
                float e1 = sm.lng[c0 + 1]*(d[t][1] - s1h) + sm.lnb[c0 + 1];
                *(float2*)&g_hx[(size_t)n*HXS + 256 + agid*128 + c0] = make_float2(e0, e1);
            }
        }
        // geo output (warp 3)
        if (gwarp == 3) {
            int m = glane;
            float aw = 0.f;
            #pragma unroll
            for (int h = 0; h < 8; h++) aw += G.attnT[m*8 + h]*sm.wfa[h];
            int nb = G.nbr[m];
            float p0 = aw*g_proj[nb*3 + 0];
            float p1 = aw*g_proj[nb*3 + 1];
            float p2 = aw*g_proj[nb*3 + 2];
            #pragma unroll
            for (int o = 16; o; o >>= 1) {
                p0 += __shfl_xor_sync(0xffffffffu, p0, o);
                p1 += __shfl_xor_sync(0xffffffffu, p1, o);
                p2 += __shfl_xor_sync(0xffffffffu, p2, o);
            }
            if (glane == 0) {
                int b = n >> 9;
                float ps[3] = {p0, p1, p2};
                float sd[3];
                #pragma unroll
                for (int j = 0; j < 3; j++)
                    sd[j] = 0.5f*(siluf(ps[j] + bfa) - siluf(-ps[j] + bfa));
                float gt = g_gate[n];
                #pragma unroll
                for (int i = 0; i < 3; i++) {
                    float gc = g_center[b*3 + i]
                             + sd[0]*g_V[b*9 + i*3 + 0]
                             + sd[1]*g_V[b*9 + i*3 + 1]
                             + sd[2]*g_V[b*9 + i*3 + 2];
                    out_geo[n*3 + i] = gc*gt + geo_feats[n*3 + i]*(1.f - gt);
                }
            }
        }
        GBAR(bid);
    }
}

// ---------------- launcher ----------------
extern "C" void kernel_launch(void* const* d_in, const int* in_sizes, int n_in,
                              void* d_out, int out_size)
{
    const float* token    = (const float*)d_in[0];
    const float* geo      = (const float*)d_in[1];
    const float* edge     = (const float*)d_in[2];
    const int*   nbr      = (const int*)d_in[3];
    const int*   mask     = (const int*)d_in[5];
    const float* ln_qkv_g = (const float*)d_in[6];
    const float* ln_qkv_b = (const float*)d_in[7];
    const float* W_qkv    = (const float*)d_in[8];
    const float* b_qkv    = (const float*)d_in[9];
    const float* ln_e_g   = (const float*)d_in[10];
    const float* ln_e_b   = (const float*)d_in[11];
    const float* W_qkv_e  = (const float*)d_in[12];
    const float* b_qkv_e  = (const float*)d_in[13];
    const float* w_attn   = (const float*)d_in[14];
    const float* w_edge   = (const float*)d_in[15];
    const float* W_gate   = (const float*)d_in[16];
    const float* b_gate   = (const float*)d_in[17];
    const float* W_fc1    = (const float*)d_in[18];
    const float* b_fc1    = (const float*)d_in[19];
    const float* ln_h_g   = (const float*)d_in[20];
    const float* ln_h_b   = (const float*)d_in[21];
    const float* W_fc2    = (const float*)d_in[22];
    const float* b_fc2    = (const float*)d_in[23];
    const float* W_fa     = (const float*)d_in[24];
    const float* b_fa     = (const float*)d_in[25];
    float* out = (float*)d_out;

    void* p;
    cudaGetSymbolAddress(&p, g_qkv);   float* p_qkv   = (float*)p;
    cudaGetSymbolAddress(&p, g_hx);    float* p_hx    = (float*)p;
    cudaGetSymbolAddress(&p, g_Wcomb); float* p_Wcomb = (float*)p;
    cudaGetSymbolAddress(&p, g_bcomb); float* p_bcomb = (float*)p;
    cudaGetSymbolAddress(&p, g_W1);    float* p_W1    = (float*)p;
    cudaGetSymbolAddress(&p, g_b1);    float* p_b1    = (float*)p;

    prep_kernel<<<64, 256>>>(W_qkv, b_qkv, w_attn, W_qkv_e, b_qkv_e, w_edge,
                             W_fc1, b_fc1, ln_e_g, ln_e_b);
    geom_kernel<<<16, 256>>>(geo);

    {
        constexpr int SM = (64*260 + 3*32*292)*sizeof(float);
        cudaFuncSetAttribute((const void*)gemm_qkv_f,
                             cudaFuncAttributeMaxDynamicSharedMemorySize, SM);
        gemm_qkv_f<<<128, 512, SM>>>(token, p_Wcomb, p_bcomb,
                                     W_gate, b_gate, ln_qkv_g, ln_qkv_b, p_qkv);
    }

    cudaFuncSetAttribute(attn_kernel, cudaFuncAttributeMaxDynamicSharedMemorySize,
                         (int)sizeof(AttnSmem));
    attn_kernel<<<1024, 512, sizeof(AttnSmem)>>>(
        edge, geo, nbr, mask, ln_e_g, ln_e_b, W_fa, b_fa,
        out + (size_t)NTOK*256);

    {
        constexpr int SM = (64*260 + 3*32*260)*sizeof(float);
        cudaFuncSetAttribute((const void*)gemm_fc12,
                             cudaFuncAttributeMaxDynamicSharedMemorySize, SM);
        gemm_fc12<<<128, 512, SM>>>(p_hx, p_W1, p_b1, W_fc2, b_fc2,
                                    token, ln_h_g, ln_h_b, out);
    }
}

// round 13
// speedup vs baseline: 1.4418x; 1.0972x over previous
#include <cuda_runtime.h>
#include <math.h>
#include <stdint.h>

#define NTOK 8192
#define QS 288            // qkv row stride: 256 v | 8 qdot | 8 kdot | pad
#define ES 132            // edge smem row stride (floats)
#define HXS 1280          // hx row stride: 256 scalar ctx | 1024 ew
#define LPS 9             // logitP row stride

// ---------------- device scratch ----------------
__device__ float g_qkv[NTOK*QS];
__device__ float g_hx[NTOK*HXS];
__device__ float g_gate[NTOK];
__device__ float g_proj[NTOK*3];
__device__ float g_center[16*3];
__device__ float g_V[16*9];
__device__ float g_Wcomb[256*QS];
__device__ float g_bcomb[QS];
__device__ float g_wgT[128*8];      // [c][h]: tf32(lng[c]*weff[c][h])
__device__ float g_swg[8];
__device__ float g_beff2[8];
__device__ float g_W1[HXS*256];     // folded fc1 weight: [1280, 256]
__device__ float g_b1[256];         // folded fc1 bias

__device__ __forceinline__ float siluf(float x){ return x/(1.f+__expf(-x)); }
__device__ __forceinline__ uint32_t f2tf32(float x){
    uint32_t u; asm("cvt.rna.tf32.f32 %0, %1;" : "=r"(u) : "f"(x)); return u;
}
__device__ __forceinline__ float tf32f(float x){ return __uint_as_float(f2tf32(x)); }

#define CP_ASYNC16(dst, src) \
    asm volatile("cp.async.ca.shared.global [%0], [%1], 16;\n" :: "r"(dst), "l"(src))
#define CP_COMMIT() asm volatile("cp.async.commit_group;\n" ::: "memory")
#define CP_WAIT2()  asm volatile("cp.async.wait_group 2;\n" ::: "memory")
#define CP_WAIT1()  asm volatile("cp.async.wait_group 1;\n" ::: "memory")
#define CP_WAIT0()  asm volatile("cp.async.wait_group 0;\n" ::: "memory")

__device__ __forceinline__ uint32_t sptr(const void* p){
    return (uint32_t)__cvta_generic_to_shared(p);
}

// ---------------- fp32 Jacobi ----------------
__device__ void jacobi3f(float a00,float a01,float a02,float a11,float a12,float a22,
                         float V[3][3])
{
    float A[3][3] = {{a00,a01,a02},{a01,a11,a12},{a02,a12,a22}};
    V[0][0]=1; V[0][1]=0; V[0][2]=0;
    V[1][0]=0; V[1][1]=1; V[1][2]=0;
    V[2][0]=0; V[2][1]=0; V[2][2]=1;
    float tr = fabsf(a00)+fabsf(a11)+fabsf(a22);
    for (int it = 0; it < 40; ++it) {
        int p = 0, q = 1; float mx = fabsf(A[0][1]);
        if (fabsf(A[0][2]) > mx) { mx = fabsf(A[0][2]); p = 0; q = 2; }
        if (fabsf(A[1][2]) > mx) { mx = fabsf(A[1][2]); p = 1; q = 2; }
        if (mx <= 1e-8f*tr) break;
        float apq = A[p][q];
        float theta = (A[q][q]-A[p][p])/(2.0f*apq);
        float t = 1.0f/(fabsf(theta)+sqrtf(theta*theta+1.0f));
        if (theta < 0) t = -t;
        float c = rsqrtf(t*t+1.0f), s = t*c;
        for (int k = 0; k < 3; k++) { float akp=A[k][p], akq=A[k][q]; A[k][p]=c*akp-s*akq; A[k][q]=s*akp+c*akq; }
        for (int k = 0; k < 3; k++) { float apk=A[p][k], aqk=A[q][k]; A[p][k]=c*apk-s*aqk; A[q][k]=s*apk+c*aqk; }
        for (int k = 0; k < 3; k++) { float vkp=V[k][p], vkq=V[k][q]; V[k][p]=c*vkp-s*vkq; V[k][q]=s*vkp+c*vkq; }
    }
}

// ---------------- merged prep (blocks 0..63) + geometry (blocks 64..79) ----------------
__global__ void prep_geom_kernel(const float* __restrict__ W_qkv, const float* __restrict__ b_qkv,
                                 const float* __restrict__ w_attn,
                                 const float* __restrict__ W_qkv_e, const float* __restrict__ b_qkv_e,
                                 const float* __restrict__ w_edge,
                                 const float* __restrict__ W_fc1, const float* __restrict__ b_fc1,
                                 const float* __restrict__ ln_e_g, const float* __restrict__ ln_e_b,
                                 const float* __restrict__ geo)
{
    if (blockIdx.x >= 64) {
        // ---- geometry block ----
        __shared__ double sred[8][9];
        __shared__ double sCd[3];
        __shared__ float sV[9], sC[3];
        int b = blockIdx.x - 64, tid = threadIdx.x, lane = tid & 31, warp = tid >> 5;
        const float* G = geo + (size_t)b*512*3;

        {
            double s[3] = {0,0,0};
            for (int p = tid; p < 512; p += 256) { s[0] += G[p*3]; s[1] += G[p*3+1]; s[2] += G[p*3+2]; }
            #pragma unroll
            for (int k = 0; k < 3; k++)
                #pragma unroll
                for (int o = 16; o; o >>= 1) s[k] += __shfl_xor_sync(0xffffffffu, s[k], o);
            if (lane == 0) { sred[warp][0]=s[0]; sred[warp][1]=s[1]; sred[warp][2]=s[2]; }
        }
        __syncthreads();
        if (tid == 0) {
            for (int k = 0; k < 3; k++) {
                double t = 0; for (int w = 0; w < 8; w++) t += sred[w][k];
                sCd[k] = t/512.0;
            }
        }
        __syncthreads();
        double c0 = sCd[0], c1 = sCd[1], c2 = sCd[2];

        {
            double m[6] = {0,0,0,0,0,0};
            for (int p = tid; p < 512; p += 256) {
                double dx = G[p*3]-c0, dy = G[p*3+1]-c1, dz = G[p*3+2]-c2;
                m[0] += dx*dx; m[1] += dx*dy; m[2] += dx*dz;
                m[3] += dy*dy; m[4] += dy*dz; m[5] += dz*dz;
            }
            #pragma unroll
            for (int k = 0; k < 6; k++)
                #pragma unroll
                for (int o = 16; o; o >>= 1) m[k] += __shfl_xor_sync(0xffffffffu, m[k], o);
            if (lane == 0) for (int k = 0; k < 6; k++) sred[warp][k] = m[k];
        }
        __syncthreads();
        if (tid == 0) {
            double m[6];
            for (int k = 0; k < 6; k++) { double t=0; for (int w=0; w<8; w++) t += sred[w][k]; m[k]=t; }
            float V[3][3];
            jacobi3f((float)m[0],(float)m[1],(float)m[2],(float)m[3],(float)m[4],(float)m[5], V);
            for (int i = 0; i < 3; i++)
                for (int j = 0; j < 3; j++) { sV[i*3+j] = V[i][j]; g_V[b*9+i*3+j] = V[i][j]; }
            sC[0]=(float)c0; sC[1]=(float)c1; sC[2]=(float)c2;
            g_center[b*3+0]=(float)c0; g_center[b*3+1]=(float)c1; g_center[b*3+2]=(float)c2;
        }
        __syncthreads();

        for (int p = tid; p < 512; p += 256) {
            int t = b*512 + p;
            float dx = G[p*3]-sC[0], dy = G[p*3+1]-sC[1], dz = G[p*3+2]-sC[2];
            for (int d = 0; d < 3; d++)
                g_proj[t*3+d] = dx*sV[0*3+d] + dy*sV[1*3+d] + dz*sV[2*3+d];
        }
        return;
    }

    // ---- prep blocks ----
    int gid = blockIdx.x*blockDim.x + threadIdx.x;
    int gstride = 64*blockDim.x;
    for (int idx = gid; idx < 256*QS; idx += gstride) {
        int c = idx / QS, j = idx - c*QS;
        float w = 0.f;
        if (j < 256) {
            w = W_qkv[c*768 + 512 + j];
        } else if (j < 264) {
            int h = j - 256; float s = 0.f;
            #pragma unroll
            for (int d = 0; d < 32; d++) s += W_qkv[c*768 + h*32 + d]*w_attn[d];
            w = s;
        } else if (j < 272) {
            int h = j - 264; float s = 0.f;
            #pragma unroll
            for (int d = 0; d < 32; d++) s += W_qkv[c*768 + 256 + h*32 + d]*w_attn[d];
            w = s;
        }
        g_Wcomb[idx] = w;
    }
    for (int idx = gid; idx < HXS*256; idx += gstride) {
        int j = idx >> 8, o = idx & 255;
        float w;
        if (j < 256) {
            w = W_fc1[j*256 + o];
        } else {
            int hc = j - 256, h = hc >> 7, c = hc & 127;
            float s = 0.f;
            #pragma unroll
            for (int jp = 0; jp < 16; jp++)
                s += W_qkv_e[c*256 + 128 + h*16 + jp]*W_fc1[(256 + h*16 + jp)*256 + o];
            w = s;
        }
        g_W1[idx] = w;
    }
    if (blockIdx.x == 0) {
        for (int j = threadIdx.x; j < QS; j += blockDim.x) {
            float bv = 0.f;
            if (j < 256) bv = b_qkv[512 + j];
            else if (j < 264) { int h = j-256; for (int d=0; d<32; d++) bv += b_qkv[h*32+d]*w_attn[d]; }
            else if (j < 272) { int h = j-264; for (int d=0; d<32; d++) bv += b_qkv[256 + h*32+d]*w_attn[d]; }
            g_bcomb[j] = bv;
        }
    }
    if (blockIdx.x == 1) {
        __shared__ float swgt[128*8];
        __shared__ float sweff[128*8];
        for (int idx = threadIdx.x; idx < 128*8; idx += blockDim.x) {
            int c = idx >> 3, h = idx & 7; float s = 0.f;
            #pragma unroll
            for (int e = 0; e < 16; e++) s += W_qkv_e[c*256 + h*16 + e]*w_edge[e];
            sweff[idx] = s;
            float wt = tf32f(ln_e_g[c]*s);
            swgt[c*8 + h] = wt;
            g_wgT[c*8 + h] = wt;
        }
        __syncthreads();
        if (threadIdx.x < 8) {
            int h = threadIdx.x;
            float sw = 0.f, b2 = 0.f;
            for (int c = 0; c < 128; c++) {
                sw += swgt[c*8 + h];
                b2 += ln_e_b[c]*sweff[c*8 + h];
            }
            for (int e = 0; e < 16; e++) b2 += b_qkv_e[h*16 + e]*w_edge[e];
            g_swg[h] = sw; g_beff2[h] = b2;
        }
    }
    if (blockIdx.x == 2 && threadIdx.x < 256) {
        int o = threadIdx.x;
        float s = b_fc1[o];
        for (int j = 0; j < 128; j++)
            s += b_qkv_e[128 + j]*W_fc1[(256 + j)*256 + o];
        g_b1[o] = s;
    }
}

// ---------------- qkv GEMM: BM=32, 256 thr, A resident + fused LN/gate, 2-stage B ----------------
__global__ __launch_bounds__(256)
void gemm_qkv32(const float* __restrict__ X,
                const float* __restrict__ Bw,
                const float* __restrict__ bias,
                const float* __restrict__ Wg, const float* __restrict__ bg,
                const float* __restrict__ lng, const float* __restrict__ lnb,
                float* __restrict__ C)
{
    constexpr int K = 256, N = QS;
    constexpr int AS = 260, BS = 292;
    constexpr int ASZ = 32*AS, BSZ = 32*BS;
    constexpr int KT = K/32, WN = N/4, NT = WN/8, CT = N/32;   // WN=72, NT=9, CT=9
    extern __shared__ float smem[];
    float* sA = smem;                 // [32][260] resident
    float* sBst = smem + ASZ;         // 2 stages of [32][292]
    const int tid = threadIdx.x, lane = tid & 31, warp = tid >> 5;
    const int wr = warp >> 2, wc = warp & 3;   // 2 x 4
    const int gid = lane >> 2, tig = lane & 3;
    const int rowBase = blockIdx.x*32;

    auto issueB = [&](int kt) {
        float* dB = sBst + (kt & 1)*BSZ;
        #pragma unroll
        for (int jj = 0; jj < 9; jj++) {
            int idx = tid + 256*jj;
            int r = idx/72, c4 = idx - r*72;
            CP_ASYNC16(sptr(&dB[r*BS + c4*4]),
                       &Bw[(size_t)(kt*32 + r)*N + c4*4]);
        }
        CP_COMMIT();
    };

    // A load (group), then B stage 0
    {
        #pragma unroll
        for (int jj = 0; jj < 8; jj++) {
            int idx = tid + 256*jj;          // 2048 float4
            int r = idx >> 6, c4 = idx & 63;
            CP_ASYNC16(sptr(&sA[r*AS + c4*4]),
                       &X[(size_t)(rowBase + r)*K + c4*4]);
        }
        CP_COMMIT();
    }
    issueB(0);

    CP_WAIT1();            // A done (B0 may be pending)
    __syncthreads();

    // LN + gate on resident A: 8 warps x 4 rows
    #pragma unroll
    for (int rr = 0; rr < 4; rr++) {
        int row = warp*4 + rr;
        float v[8]; float s = 0.f, s2 = 0.f, gd = 0.f;
        #pragma unroll
        for (int j = 0; j < 8; j++) {
            int c = lane + 32*j;
            float t = sA[row*AS + c];
            v[j] = t; s += t; s2 += t*t; gd += t*Wg[c];
        }
        #pragma unroll
        for (int o = 16; o; o >>= 1) {
            s  += __shfl_xor_sync(0xffffffffu, s,  o);
            s2 += __shfl_xor_sync(0xffffffffu, s2, o);
            gd += __shfl_xor_sync(0xffffffffu, gd, o);
        }
        float mean = s*(1.f/256.f);
        float rstd = rsqrtf(s2*(1.f/256.f) - mean*mean + 1e-5f);
        #pragma unroll
        for (int j = 0; j < 8; j++) {
            int c = lane + 32*j;
            sA[row*AS + c] = (v[j]-mean)*rstd*lng[c] + lnb[c];
        }
        if (lane == 0) g_gate[rowBase + row] = 1.f/(1.f + __expf(-(gd + bg[0])));
    }
    __syncthreads();

    float acc[NT][4];
    #pragma unroll
    for (int t = 0; t < NT; t++) {
        int j0 = wc*WN + t*8 + tig*2;
        acc[t][0] = bias[j0];   acc[t][1] = bias[j0+1];
        acc[t][2] = bias[j0];   acc[t][3] = bias[j0+1];
    }

    for (int kt = 0; kt < KT; ++kt) {
        if (kt + 1 < KT) { issueB(kt + 1); CP_WAIT1(); } else { CP_WAIT0(); }
        __syncthreads();
        const float* sB = sBst + (kt & 1)*BSZ;
        #pragma unroll
        for (int kk = 0; kk < 4; kk++) {
            int kc = kt*32 + kk*8;
            uint32_t a0 = __float_as_uint(sA[(wr*16 + gid    )*AS + kc + tig    ]);
            uint32_t a1 = __float_as_uint(sA[(wr*16 + gid + 8)*AS + kc + tig    ]);
            uint32_t a2 = __float_as_uint(sA[(wr*16 + gid    )*AS + kc + tig + 4]);
            uint32_t a3 = __float_as_uint(sA[(wr*16 + gid + 8)*AS + kc + tig + 4]);
            #pragma unroll
            for (int t = 0; t < NT; t++) {
                int n0 = wc*WN + t*8;
                uint32_t b0 = __float_as_uint(sB[(kk*8 + tig    )*BS + n0 + gid]);
                uint32_t b1 = __float_as_uint(sB[(kk*8 + tig + 4)*BS + n0 + gid]);
                asm volatile(
                    "mma.sync.aligned.m16n8k8.row.col.f32.tf32.tf32.f32 "
                    "{%0,%1,%2,%3}, {%4,%5,%6,%7}, {%8,%9}, {%0,%1,%2,%3};"
                    : "+f"(acc[t][0]), "+f"(acc[t][1]), "+f"(acc[t][2]), "+f"(acc[t][3])
                    : "r"(a0), "r"(a1), "r"(a2), "r"(a3), "r"(b0), "r"(b1));
            }
        }
        __syncthreads();
    }

    // stage C through B-stage region [32][292]
    float* sC = sBst;
    #pragma unroll
    for (int t = 0; t < NT; t++) {
        int n0 = wc*WN + t*8 + tig*2;
        int r0 = wr*16 + gid;
        sC[ r0     *BS + n0    ] = acc[t][0];
        sC[ r0     *BS + n0 + 1] = acc[t][1];
        sC[(r0 + 8)*BS + n0    ] = acc[t][2];
        sC[(r0 + 8)*BS + n0 + 1] = acc[t][3];
    }
    __syncthreads();
    #pragma unroll
    for (int rr = 0; rr < 4; rr++) {
        int row = warp*4 + rr;
        int grow = rowBase + row;
        #pragma unroll
        for (int j = 0; j < CT; j++) {
            int col = lane + 32*j;
            C[(size_t)grow*N + col] = sC[row*BS + col];
        }
    }
}

// ---------------- fused fc1(gelu+LN)+fc2(+residual) (unchanged) ----------------
__global__ __launch_bounds__(512)
void gemm_fc12(const float* __restrict__ A,
               const float* __restrict__ W1,
               const float* __restrict__ b1,
               const float* __restrict__ W2,
               const float* __restrict__ b2,
               const float* __restrict__ token,
               const float* __restrict__ lnhg, const float* __restrict__ lnhb,
               float* __restrict__ out)
{
    constexpr int N = 256, K1 = HXS, K2 = 256;
    constexpr int KT1 = K1/32, KT2 = K2/32;
    constexpr int SA = 36, BS = N + 4;
    constexpr int ASZ = 64*SA, BSZ = 32*BS, STG1 = ASZ + BSZ;
    constexpr int SCSZ = 64*BS;
    constexpr int OFF2 = SCSZ;
    constexpr int NT = 8, CT = N/32;
    extern __shared__ float smem[];
    const int tid = threadIdx.x, lane = tid & 31, warp = tid >> 5;
    const int wr = warp >> 2, wc = warp & 3;
    const int gid = lane >> 2, tig = lane & 3;
    const int rowBase = blockIdx.x*64;
    const int ar = tid >> 3, ac4 = tid & 7;

    auto issueA = [&](int kt) {
        float* dA = smem + (kt % 3)*STG1;
        float* dB = dA + ASZ;
        CP_ASYNC16(sptr(&dA[ar*SA + ac4*4]),
                   &A[(size_t)(rowBase + ar)*K1 + kt*32 + ac4*4]);
        #pragma unroll
        for (int jj = 0; jj < 4; jj++) {
            int idx = tid + 512*jj;
            int r = idx >> 6, c4 = idx & 63;
            CP_ASYNC16(sptr(&dB[r*BS + c4*4]),
                       &W1[(size_t)(kt*32 + r)*N + c4*4]);
        }
        CP_COMMIT();
    };
    auto issueB = [&](int kt) {
        float* dB = smem + OFF2 + (kt % 3)*BSZ;
        #pragma unroll
        for (int jj = 0; jj < 4; jj++) {
            int idx = tid + 512*jj;
            int r = idx >> 6, c4 = idx & 63;
            CP_ASYNC16(sptr(&dB[r*BS + c4*4]),
                       &W2[(size_t)(kt*32 + r)*N + c4*4]);
        }
        CP_COMMIT();
    };

    issueA(0);
    issueA(1);

    float acc[NT][4];
    #pragma unroll
    for (int t = 0; t < NT; t++) {
        int j0 = wc*64 + t*8 + tig*2;
        acc[t][0] = b1[j0];   acc[t][1] = b1[j0+1];
        acc[t][2] = b1[j0];   acc[t][3] = b1[j0+1];
    }

    for (int kt = 0; kt < KT1; ++kt) {
        if (kt + 1 < KT1) CP_WAIT1(); else CP_WAIT0();
        __syncthreads();
        if (kt + 2 < KT1) issueA(kt + 2);
        const float* sA = smem + (kt % 3)*STG1;
        const float* sB = sA + ASZ;
        #pragma unroll
        for (int kk = 0; kk < 4; kk++) {
            uint32_t a0 = __float_as_uint(sA[(wr*16 + gid    )*SA + kk*8 + tig    ]);
            uint32_t a1 = __float_as_uint(sA[(wr*16 + gid + 8)*SA + kk*8 + tig    ]);
            uint32_t a2 = __float_as_uint(sA[(wr*16 + gid    )*SA + kk*8 + tig + 4]);
            uint32_t a3 = __float_as_uint(sA[(wr*16 + gid + 8)*SA + kk*8 + tig + 4]);
            #pragma unroll
            for (int t = 0; t < NT; t++) {
                int n0 = wc*64 + t*8;
                uint32_t b0 = __float_as_uint(sB[(kk*8 + tig    )*BS + n0 + gid]);
                uint32_t b1v = __float_as_uint(sB[(kk*8 + tig + 4)*BS + n0 + gid]);
                asm volatile(
                    "mma.sync.aligned.m16n8k8.row.col.f32.tf32.tf32.f32 "
                    "{%0,%1,%2,%3}, {%4,%5,%6,%7}, {%8,%9}, {%0,%1,%2,%3};"
                    : "+f"(acc[t][0]), "+f"(acc[t][1]), "+f"(acc[t][2]), "+f"(acc[t][3])
                    : "r"(a0), "r"(a1), "r"(a2), "r"(a3), "r"(b0), "r"(b1v));
            }
        }
    }

    __syncthreads();
    issueB(0);
    issueB(1);

    float* sC = smem;
    #pragma unroll
    for (int t = 0; t < NT; t++) {
        int n0 = wc*64 + t*8 + tig*2;
        int r0 = wr*16 + gid;
        sC[ r0     *BS + n0    ] = acc[t][0];
        sC[ r0     *BS + n0 + 1] = acc[t][1];
        sC[(r0 + 8)*BS + n0    ] = acc[t][2];
        sC[(r0 + 8)*BS + n0 + 1] = acc[t][3];
    }
    __syncthreads();
    #pragma unroll
    for (int rr = 0; rr < 4; rr++) {
        int row = warp*4 + rr;
        float v[CT]; float s = 0.f, s2 = 0.f;
        #pragma unroll
        for (int j = 0; j < CT; j++) {
            float x = sC[row*BS + lane + 32*j];
            x = 0.5f*x*(1.f + erff(x*0.70710678118654752f));
            v[j] = x; s += x; s2 += x*x;
        }
        #pragma unroll
        for (int o = 16; o; o >>= 1) {
            s  += __shfl_xor_sync(0xffffffffu, s,  o);
            s2 += __shfl_xor_sync(0xffffffffu, s2, o);
        }
        float mean = s*(1.f/256.f);
        float rstd = rsqrtf(s2*(1.f/256.f) - mean*mean + 1e-5f);
        #pragma unroll
        for (int j = 0; j < CT; j++) {
            int col = lane + 32*j;
            sC[row*BS + col] = (v[j]-mean)*rstd*lnhg[col] + lnhb[col];
        }
    }
    __syncthreads();

    float acc2[NT][4];
    #pragma unroll
    for (int t = 0; t < NT; t++) {
        int j0 = wc*64 + t*8 + tig*2;
        acc2[t][0] = b2[j0];   acc2[t][1] = b2[j0+1];
        acc2[t][2] = b2[j0];   acc2[t][3] = b2[j0+1];
    }
    for (int kt = 0; kt < KT2; ++kt) {
        if (kt + 1 < KT2) CP_WAIT1(); else CP_WAIT0();
        __syncthreads();
        if (kt + 2 < KT2) issueB(kt + 2);
        const float* sB = smem + OFF2 + (kt % 3)*BSZ;
        #pragma unroll
        for (int kk = 0; kk < 4; kk++) {
            int kc = kt*32 + kk*8;
            uint32_t a0 = __float_as_uint(sC[(wr*16 + gid    )*BS + kc + tig    ]);
            uint32_t a1 = __float_as_uint(sC[(wr*16 + gid + 8)*BS + kc + tig    ]);
            uint32_t a2 = __float_as_uint(sC[(wr*16 + gid    )*BS + kc + tig + 4]);
            uint32_t a3 = __float_as_uint(sC[(wr*16 + gid + 8)*BS + kc + tig + 4]);
            #pragma unroll
            for (int t = 0; t < NT; t++) {
                int n0 = wc*64 + t*8;
                uint32_t b0 = __float_as_uint(sB[(kk*8 + tig    )*BS + n0 + gid]);
                uint32_t b1v = __float_as_uint(sB[(kk*8 + tig + 4)*BS + n0 + gid]);
                asm volatile(
                    "mma.sync.aligned.m16n8k8.row.col.f32.tf32.tf32.f32 "
                    "{%0,%1,%2,%3}, {%4,%5,%6,%7}, {%8,%9}, {%0,%1,%2,%3};"
                    : "+f"(acc2[t][0]), "+f"(acc2[t][1]), "+f"(acc2[t][2]), "+f"(acc2[t][3])
                    : "r"(a0), "r"(a1), "r"(a2), "r"(a3), "r"(b0), "r"(b1v));
            }
        }
    }

    float* sO = smem + OFF2;
    __syncthreads();
    #pragma unroll
    for (int t = 0; t < NT; t++) {
        int n0 = wc*64 + t*8 + tig*2;
        int r0 = wr*16 + gid;
        sO[ r0     *BS + n0    ] = acc2[t][0];
        sO[ r0     *BS + n0 + 1] = acc2[t][1];
        sO[(r0 + 8)*BS + n0    ] = acc2[t][2];
        sO[(r0 + 8)*BS + n0 + 1] = acc2[t][3];
    }
    __syncthreads();
    #pragma unroll
    for (int rr = 0; rr < 4; rr++) {
        int row = warp*4 + rr;
        int grow = rowBase + row;
        #pragma unroll
        for (int j = 0; j < CT; j++) {
            int col = lane + 32*j;
            out[(size_t)grow*256 + col] = sO[row*BS + col] + token[(size_t)grow*256 + col];
        }
    }
}

// ---------------- fused per-token attention (unchanged from R12) ----------------
struct AttnGroup {
    float edge[32*ES];
    float logitP[2*32*LPS];
    float attnT[32*8];
    float arH[8*36];
    float mean[32];
    float rstd[32];
    float s1[8];
    float qd[8];
    int   nbr[32];
};
struct AttnSmem {
    float wgT[128*8];
    float swg[8];
    float beff2[8];
    float wfa[8];
    float lng[128];
    float lnb[128];
    AttnGroup grp[4];
};

#define GBAR(id) asm volatile("bar.sync %0, 128;" :: "r"(id) : "memory")

__global__ __launch_bounds__(512, 2)
void attn_kernel(const float* __restrict__ edge_feats,
                 const float* __restrict__ geo_feats,
                 const int*   __restrict__ nbr_idx,
                 const int*   __restrict__ masks,
                 const float* __restrict__ ln_e_g,
                 const float* __restrict__ ln_e_b,
                 const float* __restrict__ W_fa,
                 const float* __restrict__ b_fa,
                 float* __restrict__ out_geo)
{
    extern __shared__ char smraw[];
    AttnSmem& sm = *reinterpret_cast<AttnSmem*>(smraw);
    const int tid = threadIdx.x;

    for (int i = tid; i < 128*8; i += 512) sm.wgT[i] = g_wgT[i];
    if (tid < 128) { sm.lng[tid] = ln_e_g[tid]; sm.lnb[tid] = ln_e_b[tid]; }
    if (tid >= 128 && tid < 136) {
        int h = tid - 128;
        sm.swg[h] = g_swg[h]; sm.beff2[h] = g_beff2[h]; sm.wfa[h] = W_fa[h];
    }
    const float bfa = b_fa[0];
    __syncthreads();

    const int g     = tid >> 7;
    const int gtid  = tid & 127;
    const int glane = gtid & 31;
    const int gwarp = gtid >> 5;
    const int agid  = glane >> 2;
    const int atig  = glane & 3;
    const int bid   = 1 + g;
    AttnGroup& G = sm.grp[g];

    for (int tok = 0; tok < 2; ++tok) {
        const int n = blockIdx.x*8 + g*2 + tok;

        {
            const float4* ep4 = (const float4*)(edge_feats + (size_t)n*4096);
            #pragma unroll
            for (int jj = 0; jj < 8; jj++) {
                int idx = gtid + 128*jj;
                int m = gwarp + 4*jj;
                float4 v = ep4[idx];
                v.x = tf32f(v.x); v.y = tf32f(v.y); v.z = tf32f(v.z); v.w = tf32f(v.w);
                *(float4*)&G.edge[m*ES + glane*4] = v;
                float s  = v.x + v.y + v.z + v.w;
                float s2 = v.x*v.x + v.y*v.y + v.z*v.z + v.w*v.w;
                #pragma unroll
                for (int o = 16; o; o >>= 1) {
                    s  += __shfl_xor_sync(0xffffffffu, s,  o);
                    s2 += __shfl_xor_sync(0xffffffffu, s2, o);
                }
                if (glane == 0) {
                    float mean = s*(1.f/128.f);
                    float rstd = rsqrtf(s2*(1.f/128.f) - mean*mean + 1e-5f);
                    G.mean[m] = mean; G.rstd[m] = rstd;
                }
            }
            if (gtid < 32) G.nbr[gtid] = nbr_idx[n*32 + gtid];
            if (gtid >= 32 && gtid < 40) G.qd[gtid-32] = g_qkv[(size_t)n*QS + 256 + gtid-32];
        }
        GBAR(bid);

        {
            const int m0  = (gwarp & 1)*16;
            const int kc0 = (gwarp >> 1)*64;
            float d0 = 0.f, d1 = 0.f, d2 = 0.f, d3 = 0.f;
            #pragma unroll
            for (int kk = 0; kk < 8; kk++) {
                int kc = kc0 + kk*8;
                uint32_t a0 = __float_as_uint(G.edge[(m0 + agid    )*ES + kc + atig    ]);
                uint32_t a1 = __float_as_uint(G.edge[(m0 + agid + 8)*ES + kc + atig    ]);
                uint32_t a2 = __float_as_uint(G.edge[(m0 + agid    )*ES + kc + atig + 4]);
                uint32_t a3 = __float_as_uint(G.edge[(m0 + agid + 8)*ES + kc + atig + 4]);
                uint32_t b0 = __float_as_uint(sm.wgT[(kc + atig    )*8 + agid]);
                uint32_t b1 = __float_as_uint(sm.wgT[(kc + atig + 4)*8 + agid]);
                asm volatile(
                    "mma.sync.aligned.m16n8k8.row.col.f32.tf32.tf32.f32 "
                    "{%0,%1,%2,%3}, {%4,%5,%6,%7}, {%8,%9}, {%0,%1,%2,%3};"
                    : "+f"(d0), "+f"(d1), "+f"(d2), "+f"(d3)
                    : "r"(a0), "r"(a1), "r"(a2), "r"(a3), "r"(b0), "r"(b1));
            }
            float* lp = &G.logitP[(gwarp >> 1)*32*LPS];
            lp[(m0 + agid    )*LPS + 2*atig    ] = d0;
            lp[(m0 + agid    )*LPS + 2*atig + 1] = d1;
            lp[(m0 + agid + 8)*LPS + 2*atig    ] = d2;
            lp[(m0 + agid + 8)*LPS + 2*atig + 1] = d3;
        }
        GBAR(bid);

        {
            int m = glane;
            float rst = G.rstd[m], mn = G.mean[m];
            int nb = G.nbr[m];
            int mk = masks[n*32 + m];
            #pragma unroll
            for (int i = 0; i < 2; i++) {
                int h = gwarp + 4*i;
                float dot = G.logitP[m*LPS + h] + G.logitP[32*LPS + m*LPS + h];
                float kd = g_qkv[(size_t)nb*QS + 264 + h];
                float l = G.qd[h] + sm.beff2[h] + kd + rst*(dot - mn*sm.swg[h]);
                if (!mk) l = -1e9f;
                float mx = l;
                #pragma unroll
                for (int o = 16; o; o >>= 1) mx = fmaxf(mx, __shfl_xor_sync(0xffffffffu, mx, o));
                float e = __expf(l - mx);
                float ss = e;
                #pragma unroll
                for (int o = 16; o; o >>= 1) ss += __shfl_xor_sync(0xffffffffu, ss, o);
                float a = e/ss;
                float arr = __uint_as_float(f2tf32(a*rst));
                float s1p = arr*mn;
                #pragma unroll
                for (int o = 16; o; o >>= 1) s1p += __shfl_xor_sync(0xffffffffu, s1p, o);
                G.attnT[m*8 + h] = a;
                G.arH[h*36 + m]  = arr;
                if (glane == 0) G.s1[h] = s1p;
            }
        }
        GBAR(bid);

        {
            int c = 2*gtid;
            int h = c >> 5;
            float ax = 0.f, ay = 0.f;
            #pragma unroll
            for (int m = 0; m < 32; m++) {
                const float* vrow = &g_qkv[(size_t)G.nbr[m]*QS];
                float2 v = *(const float2*)&vrow[c];
                float a = G.attnT[m*8 + h];
                ax += a*v.x; ay += a*v.y;
            }
            *(float2*)&g_hx[(size_t)n*HXS + c] = make_float2(ax, ay);
        }
        {
            float d[4][2];
            float z0 = 0.f, z1 = 0.f;
            #pragma unroll
            for (int t = 0; t < 4; t++) { d[t][0] = 0.f; d[t][1] = 0.f; }
            #pragma unroll
            for (int kt = 0; kt < 4; kt++) {
                uint32_t a0 = __float_as_uint(G.arH[agid*36 + kt*8 + atig]);
                uint32_t a2 = __float_as_uint(G.arH[agid*36 + kt*8 + 4 + atig]);
                #pragma unroll
                for (int t = 0; t < 4; t++) {
                    int n0 = gwarp*32 + t*8;
                    uint32_t b0 = __float_as_uint(G.edge[(kt*8 + atig    )*ES + n0 + agid]);
                    uint32_t b1 = __float_as_uint(G.edge[(kt*8 + atig + 4)*ES + n0 + agid]);
                    asm volatile(
                        "mma.sync.aligned.m16n8k8.row.col.f32.tf32.tf32.f32 "
                        "{%0,%1,%2,%3}, {%4,%5,%6,%7}, {%8,%9}, {%0,%1,%2,%3};"
                        : "+f"(d[t][0]), "+f"(d[t][1]), "+f"(z0), "+f"(z1)
                        : "r"(a0), "r"(0u), "r"(a2), "r"(0u), "r"(b0), "r"(b1));
                }
            }
            float s1h = G.s1[agid];
            #pragma unroll
            for (int t = 0; t < 4; t++) {
                int c0 = gwarp*32 + t*8 + 2*atig;
                float e0 = sm.lng[c0    ]*(d[t][0] - s1h) + sm.lnb[c0    ];
                float e1 = sm.lng[c0 + 1]*(d[t][1] - s1h) + sm.lnb[c0 + 1];
                *(float2*)&g_hx[(size_t)n*HXS + 256 + agid*128 + c0] = make_float2(e0, e1);
            }
        }
        if (gwarp == 3) {
            int m = glane;
            float aw = 0.f;
            #pragma unroll
            for (int h = 0; h < 8; h++) aw += G.attnT[m*8 + h]*sm.wfa[h];
            int nb = G.nbr[m];
            float p0 = aw*g_proj[nb*3 + 0];
            float p1 = aw*g_proj[nb*3 + 1];
            float p2 = aw*g_proj[nb*3 + 2];
            #pragma unroll
            for (int o = 16; o; o >>= 1) {
                p0 += __shfl_xor_sync(0xffffffffu, p0, o);
                p1 += __shfl_xor_sync(0xffffffffu, p1, o);
                p2 += __shfl_xor_sync(0xffffffffu, p2, o);
            }
            if (glane == 0) {
                int b = n >> 9;
                float ps[3] = {p0, p1, p2};
                float sd[3];
                #pragma unroll
                for (int j = 0; j < 3; j++)
                    sd[j] = 0.5f*(siluf(ps[j] + bfa) - siluf(-ps[j] + bfa));
                float gt = g_gate[n];
                #pragma unroll
                for (int i = 0; i < 3; i++) {
                    float gc = g_center[b*3 + i]
                             + sd[0]*g_V[b*9 + i*3 + 0]
                             + sd[1]*g_V[b*9 + i*3 + 1]
                             + sd[2]*g_V[b*9 + i*3 + 2];
                    out_geo[n*3 + i] = gc*gt + geo_feats[n*3 + i]*(1.f - gt);
                }
            }
        }
        GBAR(bid);
    }
}

// ---------------- launcher ----------------
extern "C" void kernel_launch(void* const* d_in, const int* in_sizes, int n_in,
                              void* d_out, int out_size)
{
    const float* token    = (const float*)d_in[0];
    const float* geo      = (const float*)d_in[1];
    const float* edge     = (const float*)d_in[2];
    const int*   nbr      = (const int*)d_in[3];
    const int*   mask     = (const int*)d_in[5];
    const float* ln_qkv_g = (const float*)d_in[6];
    const float* ln_qkv_b = (const float*)d_in[7];
    const float* W_qkv    = (const float*)d_in[8];
    const float* b_qkv    = (const float*)d_in[9];
    const float* ln_e_g   = (const float*)d_in[10];
    const float* ln_e_b   = (const float*)d_in[11];
    const float* W_qkv_e  = (const float*)d_in[12];
    const float* b_qkv_e  = (const float*)d_in[13];
    const float* w_attn   = (const float*)d_in[14];
    const float* w_edge   = (const float*)d_in[15];
    const float* W_gate   = (const float*)d_in[16];
    const float* b_gate   = (const float*)d_in[17];
    const float* W_fc1    = (const float*)d_in[18];
    const float* b_fc1    = (const float*)d_in[19];
    const float* ln_h_g   = (const float*)d_in[20];
    const float* ln_h_b   = (const float*)d_in[21];
    const float* W_fc2    = (const float*)d_in[22];
    const float* b_fc2    = (const float*)d_in[23];
    const float* W_fa     = (const float*)d_in[24];
    const float* b_fa     = (const float*)d_in[25];
    float* out = (float*)d_out;

    void* p;
    cudaGetSymbolAddress(&p, g_qkv);   float* p_qkv   = (float*)p;
    cudaGetSymbolAddress(&p, g_hx);    float* p_hx    = (float*)p;
    cudaGetSymbolAddress(&p, g_Wcomb); float* p_Wcomb = (float*)p;
    cudaGetSymbolAddress(&p, g_bcomb); float* p_bcomb = (float*)p;
    cudaGetSymbolAddress(&p, g_W1);    float* p_W1    = (float*)p;
    cudaGetSymbolAddress(&p, g_b1);    float* p_b1    = (float*)p;

    prep_geom_kernel<<<80, 256>>>(W_qkv, b_qkv, w_attn, W_qkv_e, b_qkv_e, w_edge,
                                  W_fc1, b_fc1, ln_e_g, ln_e_b, geo);

    // qkv: token -> LN(+gate) -> @ Wcomb[256,288], BM=32, 2 CTAs/SM
    {
        constexpr int SM = (32*260 + 2*32*292)*sizeof(float);   // 105.5 KB
        cudaFuncSetAttribute((const void*)gemm_qkv32,
                             cudaFuncAttributeMaxDynamicSharedMemorySize, SM);
        gemm_qkv32<<<256, 256, SM>>>(token, p_Wcomb, p_bcomb,
                                     W_gate, b_gate, ln_qkv_g, ln_qkv_b, p_qkv);
    }

    cudaFuncSetAttribute(attn_kernel, cudaFuncAttributeMaxDynamicSharedMemorySize,
                         (int)sizeof(AttnSmem));
    attn_kernel<<<1024, 512, sizeof(AttnSmem)>>>(
        edge, geo, nbr, mask, ln_e_g, ln_e_b, W_fa, b_fa,
        out + (size_t)NTOK*256);

    {
        constexpr int SM = (64*260 + 3*32*260)*sizeof(float);
        cudaFuncSetAttribute((const void*)gemm_fc12,
                             cudaFuncAttributeMaxDynamicSharedMemorySize, SM);
        gemm_fc12<<<128, 512, SM>>>(p_hx, p_W1, p_b1, W_fc2, b_fc2,
                                    token, ln_h_g, ln_h_b, out);
    }
}